// round 1
// baseline (speedup 1.0000x reference)
#include <cuda_runtime.h>

#define TSEQ 4096
#define DM   768
#define NH   12
#define DKH  64
#define DFF  3072

// ---- scratch (static device arrays: allocation-free) ----
__device__ float g_q   [TSEQ * DM];
__device__ float g_k   [TSEQ * DM];
__device__ float g_v   [TSEQ * DM];
__device__ float g_attn[TSEQ * DM];
__device__ float g_y1  [TSEQ * DM];
__device__ float g_h   [TSEQ * DM];
__device__ float g_ff1 [TSEQ * DFF];
__device__ float g_y2  [TSEQ * DM];

// ============================================================
// SGEMM: C[M,N] = A[M,K] @ B[K,N] + bias (+relu) (+residual)
// 128x128 tile, BK=8, 256 threads, 8x8 frags (4+4 split)
// ============================================================
__global__ __launch_bounds__(256) void sgemm_kernel(
    const float* __restrict__ A, const float* __restrict__ B,
    const float* __restrict__ bias, const float* __restrict__ res,
    float* __restrict__ C, int M, int N, int K, int relu)
{
    __shared__ float As[8][128];
    __shared__ float Bs[8][128];

    const int tid  = threadIdx.x;
    const int brow = blockIdx.y * 128;
    const int bcol = blockIdx.x * 128;
    const int ty   = tid >> 4;      // 0..15
    const int tx   = tid & 15;      // 0..15

    const int arow = tid >> 1;          // 0..127
    const int acol = (tid & 1) * 4;     // 0 or 4
    const int blr  = tid >> 5;          // 0..7
    const int blc  = (tid & 31) * 4;    // 0..124

    const float* Aptr = A + (long)(brow + arow) * K + acol;
    const float* Bptr = B + (long)blr * N + bcol + blc;

    float acc[8][8];
    #pragma unroll
    for (int i = 0; i < 8; i++)
        #pragma unroll
        for (int j = 0; j < 8; j++) acc[i][j] = 0.f;

    for (int kt = 0; kt < K; kt += 8) {
        float4 av = *(const float4*)(Aptr + kt);
        As[acol + 0][arow] = av.x;
        As[acol + 1][arow] = av.y;
        As[acol + 2][arow] = av.z;
        As[acol + 3][arow] = av.w;
        *(float4*)&Bs[blr][blc] = *(const float4*)(Bptr + (long)kt * N);
        __syncthreads();

        #pragma unroll
        for (int k = 0; k < 8; k++) {
            float a[8], b[8];
            *(float4*)&a[0] = *(const float4*)&As[k][ty * 4];
            *(float4*)&a[4] = *(const float4*)&As[k][64 + ty * 4];
            *(float4*)&b[0] = *(const float4*)&Bs[k][tx * 4];
            *(float4*)&b[4] = *(const float4*)&Bs[k][64 + tx * 4];
            #pragma unroll
            for (int i = 0; i < 8; i++)
                #pragma unroll
                for (int j = 0; j < 8; j++)
                    acc[i][j] = fmaf(a[i], b[j], acc[i][j]);
        }
        __syncthreads();
    }

    #pragma unroll
    for (int i = 0; i < 8; i++) {
        int row = brow + ((i < 4) ? (ty * 4 + i) : (64 + ty * 4 + i - 4));
        #pragma unroll
        for (int jj = 0; jj < 2; jj++) {
            int col = bcol + ((jj == 0) ? (tx * 4) : (64 + tx * 4));
            float4 bv = *(const float4*)(bias + col);
            float4 o;
            o.x = acc[i][jj * 4 + 0] + bv.x;
            o.y = acc[i][jj * 4 + 1] + bv.y;
            o.z = acc[i][jj * 4 + 2] + bv.z;
            o.w = acc[i][jj * 4 + 3] + bv.w;
            if (relu) {
                o.x = fmaxf(o.x, 0.f); o.y = fmaxf(o.y, 0.f);
                o.z = fmaxf(o.z, 0.f); o.w = fmaxf(o.w, 0.f);
            }
            if (res) {
                float4 r = *(const float4*)(res + (long)row * N + col);
                o.x += r.x; o.y += r.y; o.z += r.z; o.w += r.w;
            }
            *(float4*)(C + (long)row * N + col) = o;
        }
    }
}

// ============================================================
// Flash attention (fp32 SIMT), causal.
// Grid: (T/64, NH). Block: 256. 64-query tile per CTA.
// smem: QsT(16K) + KPs(16K, K^T then P^T) + Vs(16K) = 48KB
// ============================================================
__global__ __launch_bounds__(256) void attn_kernel(
    const float* __restrict__ Q, const float* __restrict__ Km,
    const float* __restrict__ V, float* __restrict__ O)
{
    __shared__ float QsT[64 * 64];   // [d][q], pre-scaled
    __shared__ float KPs[64 * 64];   // [d][k] during S, [k][q] during PV
    __shared__ float Vs [64 * 64];   // [k][d]

    const int tid = threadIdx.x;
    const int qb  = (int)gridDim.x - 1 - (int)blockIdx.x;  // heavy tiles first
    const int h   = blockIdx.y;
    const int tr  = tid >> 4;    // 0..15  (q rows tr*4..+3)
    const int tc  = tid & 15;    // 0..15  (k/d cols tc*4..+3)

    const int lrow = tid >> 2;            // 0..63
    const int ldof = (tid & 3) * 16;      // 0,16,32,48

    // Load Q tile transposed, pre-scaled by 1/sqrt(dk)
    {
        const float* qp = Q + (long)(qb * 64 + lrow) * DM + h * DKH + ldof;
        #pragma unroll
        for (int v4 = 0; v4 < 4; v4++) {
            float4 q4 = *(const float4*)(qp + v4 * 4);
            int d = ldof + v4 * 4;
            QsT[(d + 0) * 64 + lrow] = q4.x * 0.125f;
            QsT[(d + 1) * 64 + lrow] = q4.y * 0.125f;
            QsT[(d + 2) * 64 + lrow] = q4.z * 0.125f;
            QsT[(d + 3) * 64 + lrow] = q4.w * 0.125f;
        }
    }

    float o[4][4];
    float m[4], l[4];
    #pragma unroll
    for (int i = 0; i < 4; i++) {
        m[i] = -1e30f; l[i] = 0.f;
        #pragma unroll
        for (int j = 0; j < 4; j++) o[i][j] = 0.f;
    }

    for (int kb = 0; kb <= qb; kb++) {
        // Load K transposed + V natural
        const float* kp = Km + (long)(kb * 64 + lrow) * DM + h * DKH + ldof;
        const float* vp = V  + (long)(kb * 64 + lrow) * DM + h * DKH + ldof;
        #pragma unroll
        for (int v4 = 0; v4 < 4; v4++) {
            float4 k4 = *(const float4*)(kp + v4 * 4);
            int d = ldof + v4 * 4;
            KPs[(d + 0) * 64 + lrow] = k4.x;
            KPs[(d + 1) * 64 + lrow] = k4.y;
            KPs[(d + 2) * 64 + lrow] = k4.z;
            KPs[(d + 3) * 64 + lrow] = k4.w;
            *(float4*)&Vs[lrow * 64 + d] = *(const float4*)(vp + v4 * 4);
        }
        __syncthreads();

        // S = Q @ K^T (rank-1 over d)
        float s[4][4];
        #pragma unroll
        for (int i = 0; i < 4; i++)
            #pragma unroll
            for (int j = 0; j < 4; j++) s[i][j] = 0.f;

        #pragma unroll 8
        for (int d = 0; d < 64; d++) {
            float4 a4 = *(const float4*)&QsT[d * 64 + tr * 4];
            float4 b4 = *(const float4*)&KPs[d * 64 + tc * 4];
            float a[4] = {a4.x, a4.y, a4.z, a4.w};
            float b[4] = {b4.x, b4.y, b4.z, b4.w};
            #pragma unroll
            for (int i = 0; i < 4; i++)
                #pragma unroll
                for (int j = 0; j < 4; j++)
                    s[i][j] = fmaf(a[i], b[j], s[i][j]);
        }

        // causal mask on the diagonal tile
        if (kb == qb) {
            #pragma unroll
            for (int i = 0; i < 4; i++)
                #pragma unroll
                for (int j = 0; j < 4; j++)
                    if (tc * 4 + j > tr * 4 + i) s[i][j] = -1e30f;
        }

        // online softmax
        #pragma unroll
        for (int i = 0; i < 4; i++) {
            float pm = fmaxf(fmaxf(s[i][0], s[i][1]), fmaxf(s[i][2], s[i][3]));
            #pragma unroll
            for (int off = 1; off < 16; off <<= 1)
                pm = fmaxf(pm, __shfl_xor_sync(0xffffffffu, pm, off));
            float mn    = fmaxf(m[i], pm);
            float alpha = __expf(m[i] - mn);
            float rs = 0.f;
            #pragma unroll
            for (int j = 0; j < 4; j++) {
                s[i][j] = __expf(s[i][j] - mn);
                rs += s[i][j];
            }
            #pragma unroll
            for (int off = 1; off < 16; off <<= 1)
                rs += __shfl_xor_sync(0xffffffffu, rs, off);
            l[i] = l[i] * alpha + rs;
            m[i] = mn;
            #pragma unroll
            for (int j = 0; j < 4; j++) o[i][j] *= alpha;
        }
        __syncthreads();   // all threads done reading K^T

        // write P transposed [k][q] over the K tile
        #pragma unroll
        for (int j = 0; j < 4; j++)
            #pragma unroll
            for (int i = 0; i < 4; i++)
                KPs[(tc * 4 + j) * 64 + tr * 4 + i] = s[i][j];
        __syncthreads();

        // O += P @ V (rank-1 over k)
        #pragma unroll 8
        for (int k = 0; k < 64; k++) {
            float4 a4 = *(const float4*)&KPs[k * 64 + tr * 4];
            float4 b4 = *(const float4*)&Vs [k * 64 + tc * 4];
            float a[4] = {a4.x, a4.y, a4.z, a4.w};
            float b[4] = {b4.x, b4.y, b4.z, b4.w};
            #pragma unroll
            for (int i = 0; i < 4; i++)
                #pragma unroll
                for (int j = 0; j < 4; j++)
                    o[i][j] = fmaf(a[i], b[j], o[i][j]);
        }
        __syncthreads();   // before next tile load
    }

    #pragma unroll
    for (int i = 0; i < 4; i++) {
        float inv = 1.0f / l[i];
        int row = qb * 64 + tr * 4 + i;
        float4 out4 = { o[i][0] * inv, o[i][1] * inv, o[i][2] * inv, o[i][3] * inv };
        *(float4*)(O + (long)row * DM + h * DKH + tc * 4) = out4;
    }
}

// ============================================================
// LayerNorm: one block (256 thr) per row, D=768
// ============================================================
__global__ __launch_bounds__(256) void ln_kernel(
    const float* __restrict__ X, const float* __restrict__ g,
    const float* __restrict__ b, float* __restrict__ Y)
{
    const int r   = blockIdx.x;
    const int tid = threadIdx.x;
    const float* x = X + (long)r * DM;

    float v[3];
    float s = 0.f, ss = 0.f;
    #pragma unroll
    for (int i = 0; i < 3; i++) {
        v[i] = x[tid + i * 256];
        s  += v[i];
        ss += v[i] * v[i];
    }
    #pragma unroll
    for (int off = 16; off > 0; off >>= 1) {
        s  += __shfl_xor_sync(0xffffffffu, s,  off);
        ss += __shfl_xor_sync(0xffffffffu, ss, off);
    }
    __shared__ float rs_[8], rss_[8];
    const int lane = tid & 31, wid = tid >> 5;
    if (lane == 0) { rs_[wid] = s; rss_[wid] = ss; }
    __syncthreads();
    float ts = 0.f, tss = 0.f;
    #pragma unroll
    for (int w = 0; w < 8; w++) { ts += rs_[w]; tss += rss_[w]; }

    const float mean = ts * (1.f / 768.f);
    const float var  = tss * (1.f / 768.f) - mean * mean;
    const float rstd = rsqrtf(var + 1e-5f);

    #pragma unroll
    for (int i = 0; i < 3; i++) {
        int c = tid + i * 256;
        Y[(long)r * DM + c] = (v[i] - mean) * rstd * g[c] + b[c];
    }
}

// ============================================================
extern "C" void kernel_launch(void* const* d_in, const int* in_sizes, int n_in,
                              void* d_out, int out_size)
{
    const float* x   = (const float*)d_in[0];
    const float* Wq  = (const float*)d_in[1];
    const float* bq  = (const float*)d_in[2];
    const float* Wk  = (const float*)d_in[3];
    const float* bk  = (const float*)d_in[4];
    const float* Wv  = (const float*)d_in[5];
    const float* bv  = (const float*)d_in[6];
    const float* Wo  = (const float*)d_in[7];
    const float* bo  = (const float*)d_in[8];
    const float* W1  = (const float*)d_in[9];
    const float* b1  = (const float*)d_in[10];
    const float* W2  = (const float*)d_in[11];
    const float* b2  = (const float*)d_in[12];
    const float* g1  = (const float*)d_in[13];
    const float* be1 = (const float*)d_in[14];
    const float* g2  = (const float*)d_in[15];
    const float* be2 = (const float*)d_in[16];
    float* out = (float*)d_out;

    float *q, *k, *v, *attn, *y1, *hbuf, *ff1, *y2;
    cudaGetSymbolAddress((void**)&q,    g_q);
    cudaGetSymbolAddress((void**)&k,    g_k);
    cudaGetSymbolAddress((void**)&v,    g_v);
    cudaGetSymbolAddress((void**)&attn, g_attn);
    cudaGetSymbolAddress((void**)&y1,   g_y1);
    cudaGetSymbolAddress((void**)&hbuf, g_h);
    cudaGetSymbolAddress((void**)&ff1,  g_ff1);
    cudaGetSymbolAddress((void**)&y2,   g_y2);

    dim3 blk(256);
    dim3 gProj(DM / 128, TSEQ / 128);    // (6,32)
    dim3 gFF1(DFF / 128, TSEQ / 128);    // (24,32)
    dim3 gAttn(TSEQ / 64, NH);           // (64,12)

    // QKV projections
    sgemm_kernel<<<gProj, blk>>>(x, Wq, bq, nullptr, q, TSEQ, DM, DM, 0);
    sgemm_kernel<<<gProj, blk>>>(x, Wk, bk, nullptr, k, TSEQ, DM, DM, 0);
    sgemm_kernel<<<gProj, blk>>>(x, Wv, bv, nullptr, v, TSEQ, DM, DM, 0);

    // causal attention
    attn_kernel<<<gAttn, blk>>>(q, k, v, attn);

    // output projection + residual(x)
    sgemm_kernel<<<gProj, blk>>>(attn, Wo, bo, x, y1, TSEQ, DM, DM, 0);

    // LN1
    ln_kernel<<<TSEQ, blk>>>(y1, g1, be1, hbuf);

    // FFN
    sgemm_kernel<<<gFF1, blk>>>(hbuf, W1, b1, nullptr, ff1, TSEQ, DFF, DM, 1);
    sgemm_kernel<<<gProj, blk>>>(ff1, W2, b2, hbuf, y2, TSEQ, DM, DFF, 0);

    // LN2 -> output
    ln_kernel<<<TSEQ, blk>>>(y2, g2, be2, out);
}

// round 3
// speedup vs baseline: 1.4710x; 1.4710x over previous
#include <cuda_runtime.h>
#include <cuda_bf16.h>

#define TSEQ 4096
#define DM   768
#define NH   12
#define DKH  64
#define DFF  3072

// ---- fp32 scratch ----
__device__ float g_q   [TSEQ * DM];
__device__ float g_k   [TSEQ * DM];
__device__ float g_v   [TSEQ * DM];
__device__ float g_attn[TSEQ * DM];
__device__ float g_y1  [TSEQ * DM];
__device__ float g_h   [TSEQ * DM];
__device__ float g_ff1 [TSEQ * DFF];
__device__ float g_y2  [TSEQ * DM];

// ---- bf16 hi/lo transposed weights [N, K] ----
__device__ __nv_bfloat16 g_wqh[DM * DM],  g_wql[DM * DM];
__device__ __nv_bfloat16 g_wkh[DM * DM],  g_wkl[DM * DM];
__device__ __nv_bfloat16 g_wvh[DM * DM],  g_wvl[DM * DM];
__device__ __nv_bfloat16 g_woh[DM * DM],  g_wol[DM * DM];
__device__ __nv_bfloat16 g_w1h[DM * DFF], g_w1l[DM * DFF];
__device__ __nv_bfloat16 g_w2h[DM * DFF], g_w2l[DM * DFF];

// ============================================================
// warp-mma helpers (sm_80+ baseline: valid on plain sm_103)
// ============================================================
__device__ __forceinline__ unsigned s2u(const void* p) {
    unsigned a;
    asm("{ .reg .u64 t; cvta.to.shared.u64 t, %1; cvt.u32.u64 %0, t; }"
        : "=r"(a) : "l"(p));
    return a;
}
__device__ __forceinline__ void ldm_x4(unsigned* r, unsigned addr) {
    asm volatile("ldmatrix.sync.aligned.m8n8.x4.shared.b16 {%0,%1,%2,%3}, [%4];"
                 : "=r"(r[0]), "=r"(r[1]), "=r"(r[2]), "=r"(r[3]) : "r"(addr));
}
__device__ __forceinline__ void ldm_x2(unsigned* r, unsigned addr) {
    asm volatile("ldmatrix.sync.aligned.m8n8.x2.shared.b16 {%0,%1}, [%2];"
                 : "=r"(r[0]), "=r"(r[1]) : "r"(addr));
}
__device__ __forceinline__ void mma_bf16(float* c, const unsigned* a, const unsigned* b) {
    asm volatile("mma.sync.aligned.m16n8k16.row.col.f32.bf16.bf16.f32 "
                 "{%0,%1,%2,%3}, {%4,%5,%6,%7}, {%8,%9}, {%0,%1,%2,%3};"
                 : "+f"(c[0]), "+f"(c[1]), "+f"(c[2]), "+f"(c[3])
                 : "r"(a[0]), "r"(a[1]), "r"(a[2]), "r"(a[3]), "r"(b[0]), "r"(b[1]));
}

// ============================================================
// Weight transpose + bf16 hi/lo split: W[K,N] -> Th/Tl[N,K]
// ============================================================
__global__ __launch_bounds__(256) void wsplit_t(
    const float* __restrict__ W, __nv_bfloat16* __restrict__ Th,
    __nv_bfloat16* __restrict__ Tl, int K, int N)
{
    __shared__ float t[32][33];
    const int tx = threadIdx.x, ty = threadIdx.y;
    const int n0 = blockIdx.x * 32, k0 = blockIdx.y * 32;
    #pragma unroll
    for (int i = 0; i < 4; i++)
        t[ty + i * 8][tx] = W[(long)(k0 + ty + i * 8) * N + n0 + tx];
    __syncthreads();
    #pragma unroll
    for (int i = 0; i < 4; i++) {
        int n = n0 + ty + i * 8;
        float v = t[tx][ty + i * 8];
        __nv_bfloat16 h = __float2bfloat16_rn(v);
        __nv_bfloat16 l = __float2bfloat16_rn(v - __bfloat162float(h));
        Th[(long)n * K + k0 + tx] = h;
        Tl[(long)n * K + k0 + tx] = l;
    }
}

// ============================================================
// bf16x3 tensor-core GEMM via mma.sync
// C[M,N] = A[M,K]@W[K,N] + bias (+relu) (+res)
// CTA 128x128, BK=32, 8 warps (2M x 4N), warp tile 64x32.
// smem per stage: Ah/Al/Bh/Bl, K-major, row stride 40 bf16.
// ============================================================
#define BKC    32
#define ASTR   40
#define SEG    10240               // 128*40*2 bytes
#define STAGE  (4 * SEG)           // 40960

__global__ __launch_bounds__(256, 2)
void gemm_bf16x3(const float* __restrict__ A,
                 const __nv_bfloat16* __restrict__ Bth,
                 const __nv_bfloat16* __restrict__ Btl,
                 const float* __restrict__ bias,
                 const float* __restrict__ res,
                 float* __restrict__ C,
                 int K, int N, int relu)
{
    extern __shared__ __align__(16) char smem[];

    const int tid   = threadIdx.x;
    const int wid   = tid >> 5;
    const int lane  = tid & 31;
    const int warpM = wid & 1;       // 0..1
    const int warpN = wid >> 1;      // 0..3
    const int brow  = blockIdx.y * 128;
    const int bcol  = blockIdx.x * 128;
    const unsigned smem_u = s2u(smem);

    float acc[4][4][4];
    #pragma unroll
    for (int mi = 0; mi < 4; mi++)
        #pragma unroll
        for (int ni = 0; ni < 4; ni++)
            #pragma unroll
            for (int r = 0; r < 4; r++) acc[mi][ni][r] = 0.f;

    const int nch = K / BKC;

    // global-load registers (prefetch)
    float4 aReg[4];
    uint4  bhReg[2], blReg[2];

    // prologue: load chunk 0
    {
        const float* Abase = A + (long)brow * K;
        #pragma unroll
        for (int it = 0; it < 4; it++) {
            int idx = tid + it * 256;            // 0..1023
            int r = idx >> 3, c4 = idx & 7;
            aReg[it] = *(const float4*)(Abase + (long)r * K + c4 * 4);
        }
        #pragma unroll
        for (int it = 0; it < 2; it++) {
            int idx = tid + it * 256;            // 0..511
            int n = idx >> 2, cc = idx & 3;
            bhReg[it] = *(const uint4*)((const char*)(Bth + (long)(bcol + n) * K) + cc * 16);
            blReg[it] = *(const uint4*)((const char*)(Btl + (long)(bcol + n) * K) + cc * 16);
        }
    }

    int s = 0;
    for (int c = 0; c < nch; ++c) {
        char* base = smem + s * STAGE;
        char* sAh = base;
        char* sAl = base + SEG;
        char* sBh = base + 2 * SEG;
        char* sBl = base + 3 * SEG;

        // store prefetched regs -> smem (with hi/lo split for A)
        #pragma unroll
        for (int it = 0; it < 4; it++) {
            int idx = tid + it * 256;
            int r = idx >> 3, c4 = idx & 7;
            float4 av = aReg[it];
            __nv_bfloat162 h01 = __floats2bfloat162_rn(av.x, av.y);
            __nv_bfloat162 h23 = __floats2bfloat162_rn(av.z, av.w);
            float2 f01 = __bfloat1622float2(h01);
            float2 f23 = __bfloat1622float2(h23);
            __nv_bfloat162 l01 = __floats2bfloat162_rn(av.x - f01.x, av.y - f01.y);
            __nv_bfloat162 l23 = __floats2bfloat162_rn(av.z - f23.x, av.w - f23.y);
            int off = (r * ASTR + c4 * 4) * 2;
            *(__nv_bfloat162*)(sAh + off)     = h01;
            *(__nv_bfloat162*)(sAh + off + 4) = h23;
            *(__nv_bfloat162*)(sAl + off)     = l01;
            *(__nv_bfloat162*)(sAl + off + 4) = l23;
        }
        #pragma unroll
        for (int it = 0; it < 2; it++) {
            int idx = tid + it * 256;
            int n = idx >> 2, cc = idx & 3;
            int off = n * (ASTR * 2) + cc * 16;
            *(uint4*)(sBh + off) = bhReg[it];
            *(uint4*)(sBl + off) = blReg[it];
        }
        __syncthreads();

        // prefetch next chunk
        if (c + 1 < nch) {
            const int kc = (c + 1) * BKC;
            const float* Abase = A + (long)brow * K + kc;
            #pragma unroll
            for (int it = 0; it < 4; it++) {
                int idx = tid + it * 256;
                int r = idx >> 3, c4 = idx & 7;
                aReg[it] = *(const float4*)(Abase + (long)r * K + c4 * 4);
            }
            #pragma unroll
            for (int it = 0; it < 2; it++) {
                int idx = tid + it * 256;
                int n = idx >> 2, cc = idx & 3;
                bhReg[it] = *(const uint4*)((const char*)(Bth + (long)(bcol + n) * K + kc) + cc * 16);
                blReg[it] = *(const uint4*)((const char*)(Btl + (long)(bcol + n) * K + kc) + cc * 16);
            }
        }

        // MMA phase
        const unsigned uAh = smem_u + s * STAGE;
        const unsigned uAl = uAh + SEG;
        const unsigned uBh = uAh + 2 * SEG;
        const unsigned uBl = uAh + 3 * SEG;

        #pragma unroll
        for (int kk = 0; kk < 2; kk++) {
            unsigned ah[4][4], al[4][4];
            #pragma unroll
            for (int mi = 0; mi < 4; mi++) {
                unsigned rowoff =
                    (unsigned)(((warpM * 64 + mi * 16 + (lane & 15)) * ASTR
                                + (lane >> 4) * 8 + kk * 16) * 2);
                ldm_x4(ah[mi], uAh + rowoff);
                ldm_x4(al[mi], uAl + rowoff);
            }
            #pragma unroll
            for (int ni = 0; ni < 4; ni++) {
                unsigned boff =
                    (unsigned)(((warpN * 32 + ni * 8 + (lane & 7)) * ASTR
                                + ((lane >> 3) & 1) * 8 + kk * 16) * 2);
                unsigned bh[2], bl[2];
                ldm_x2(bh, uBh + boff);
                ldm_x2(bl, uBl + boff);
                #pragma unroll
                for (int mi = 0; mi < 4; mi++) {
                    mma_bf16(acc[mi][ni], ah[mi], bh);
                    mma_bf16(acc[mi][ni], ah[mi], bl);
                    mma_bf16(acc[mi][ni], al[mi], bh);
                }
            }
        }
        s ^= 1;
    }

    // epilogue
    #pragma unroll
    for (int mi = 0; mi < 4; mi++) {
        #pragma unroll
        for (int half = 0; half < 2; half++) {
            int row = brow + warpM * 64 + mi * 16 + (lane >> 2) + half * 8;
            float* crow = C + (long)row * N;
            const float* rrow = res ? (res + (long)row * N) : (const float*)0;
            #pragma unroll
            for (int ni = 0; ni < 4; ni++) {
                int col = bcol + warpN * 32 + ni * 8 + (lane & 3) * 2;
                float2 o;
                o.x = acc[mi][ni][half * 2 + 0] + bias[col + 0];
                o.y = acc[mi][ni][half * 2 + 1] + bias[col + 1];
                if (relu) { o.x = fmaxf(o.x, 0.f); o.y = fmaxf(o.y, 0.f); }
                if (rrow) {
                    float2 r = *(const float2*)(rrow + col);
                    o.x += r.x; o.y += r.y;
                }
                *(float2*)(crow + col) = o;
            }
        }
    }
}

// ============================================================
// Flash attention (fp32 SIMT), causal — unchanged
// ============================================================
__global__ __launch_bounds__(256) void attn_kernel(
    const float* __restrict__ Q, const float* __restrict__ Km,
    const float* __restrict__ V, float* __restrict__ O)
{
    __shared__ float QsT[64 * 64];
    __shared__ float KPs[64 * 64];
    __shared__ float Vs [64 * 64];

    const int tid = threadIdx.x;
    const int qb  = (int)gridDim.x - 1 - (int)blockIdx.x;
    const int h   = blockIdx.y;
    const int tr  = tid >> 4;
    const int tc  = tid & 15;

    const int lrow = tid >> 2;
    const int ldof = (tid & 3) * 16;

    {
        const float* qp = Q + (long)(qb * 64 + lrow) * DM + h * DKH + ldof;
        #pragma unroll
        for (int v4 = 0; v4 < 4; v4++) {
            float4 q4 = *(const float4*)(qp + v4 * 4);
            int d = ldof + v4 * 4;
            QsT[(d + 0) * 64 + lrow] = q4.x * 0.125f;
            QsT[(d + 1) * 64 + lrow] = q4.y * 0.125f;
            QsT[(d + 2) * 64 + lrow] = q4.z * 0.125f;
            QsT[(d + 3) * 64 + lrow] = q4.w * 0.125f;
        }
    }

    float o[4][4];
    float m[4], l[4];
    #pragma unroll
    for (int i = 0; i < 4; i++) {
        m[i] = -1e30f; l[i] = 0.f;
        #pragma unroll
        for (int j = 0; j < 4; j++) o[i][j] = 0.f;
    }

    for (int kb = 0; kb <= qb; kb++) {
        const float* kp = Km + (long)(kb * 64 + lrow) * DM + h * DKH + ldof;
        const float* vp = V  + (long)(kb * 64 + lrow) * DM + h * DKH + ldof;
        #pragma unroll
        for (int v4 = 0; v4 < 4; v4++) {
            float4 k4 = *(const float4*)(kp + v4 * 4);
            int d = ldof + v4 * 4;
            KPs[(d + 0) * 64 + lrow] = k4.x;
            KPs[(d + 1) * 64 + lrow] = k4.y;
            KPs[(d + 2) * 64 + lrow] = k4.z;
            KPs[(d + 3) * 64 + lrow] = k4.w;
            *(float4*)&Vs[lrow * 64 + d] = *(const float4*)(vp + v4 * 4);
        }
        __syncthreads();

        float s[4][4];
        #pragma unroll
        for (int i = 0; i < 4; i++)
            #pragma unroll
            for (int j = 0; j < 4; j++) s[i][j] = 0.f;

        #pragma unroll 8
        for (int d = 0; d < 64; d++) {
            float4 a4 = *(const float4*)&QsT[d * 64 + tr * 4];
            float4 b4 = *(const float4*)&KPs[d * 64 + tc * 4];
            float a[4] = {a4.x, a4.y, a4.z, a4.w};
            float b[4] = {b4.x, b4.y, b4.z, b4.w};
            #pragma unroll
            for (int i = 0; i < 4; i++)
                #pragma unroll
                for (int j = 0; j < 4; j++)
                    s[i][j] = fmaf(a[i], b[j], s[i][j]);
        }

        if (kb == qb) {
            #pragma unroll
            for (int i = 0; i < 4; i++)
                #pragma unroll
                for (int j = 0; j < 4; j++)
                    if (tc * 4 + j > tr * 4 + i) s[i][j] = -1e30f;
        }

        #pragma unroll
        for (int i = 0; i < 4; i++) {
            float pm = fmaxf(fmaxf(s[i][0], s[i][1]), fmaxf(s[i][2], s[i][3]));
            #pragma unroll
            for (int off = 1; off < 16; off <<= 1)
                pm = fmaxf(pm, __shfl_xor_sync(0xffffffffu, pm, off));
            float mn    = fmaxf(m[i], pm);
            float alpha = __expf(m[i] - mn);
            float rs = 0.f;
            #pragma unroll
            for (int j = 0; j < 4; j++) {
                s[i][j] = __expf(s[i][j] - mn);
                rs += s[i][j];
            }
            #pragma unroll
            for (int off = 1; off < 16; off <<= 1)
                rs += __shfl_xor_sync(0xffffffffu, rs, off);
            l[i] = l[i] * alpha + rs;
            m[i] = mn;
            #pragma unroll
            for (int j = 0; j < 4; j++) o[i][j] *= alpha;
        }
        __syncthreads();

        #pragma unroll
        for (int j = 0; j < 4; j++)
            #pragma unroll
            for (int i = 0; i < 4; i++)
                KPs[(tc * 4 + j) * 64 + tr * 4 + i] = s[i][j];
        __syncthreads();

        #pragma unroll 8
        for (int k = 0; k < 64; k++) {
            float4 a4 = *(const float4*)&KPs[k * 64 + tr * 4];
            float4 b4 = *(const float4*)&Vs [k * 64 + tc * 4];
            float a[4] = {a4.x, a4.y, a4.z, a4.w};
            float b[4] = {b4.x, b4.y, b4.z, b4.w};
            #pragma unroll
            for (int i = 0; i < 4; i++)
                #pragma unroll
                for (int j = 0; j < 4; j++)
                    o[i][j] = fmaf(a[i], b[j], o[i][j]);
        }
        __syncthreads();
    }

    #pragma unroll
    for (int i = 0; i < 4; i++) {
        float inv = 1.0f / l[i];
        int row = qb * 64 + tr * 4 + i;
        float4 out4 = { o[i][0] * inv, o[i][1] * inv, o[i][2] * inv, o[i][3] * inv };
        *(float4*)(O + (long)row * DM + h * DKH + tc * 4) = out4;
    }
}

// ============================================================
// LayerNorm — unchanged
// ============================================================
__global__ __launch_bounds__(256) void ln_kernel(
    const float* __restrict__ X, const float* __restrict__ g,
    const float* __restrict__ b, float* __restrict__ Y)
{
    const int r   = blockIdx.x;
    const int tid = threadIdx.x;
    const float* x = X + (long)r * DM;

    float v[3];
    float s = 0.f, ss = 0.f;
    #pragma unroll
    for (int i = 0; i < 3; i++) {
        v[i] = x[tid + i * 256];
        s  += v[i];
        ss += v[i] * v[i];
    }
    #pragma unroll
    for (int off = 16; off > 0; off >>= 1) {
        s  += __shfl_xor_sync(0xffffffffu, s,  off);
        ss += __shfl_xor_sync(0xffffffffu, ss, off);
    }
    __shared__ float rs_[8], rss_[8];
    const int lane = tid & 31, wid = tid >> 5;
    if (lane == 0) { rs_[wid] = s; rss_[wid] = ss; }
    __syncthreads();
    float ts = 0.f, tss = 0.f;
    #pragma unroll
    for (int w = 0; w < 8; w++) { ts += rs_[w]; tss += rss_[w]; }

    const float mean = ts * (1.f / 768.f);
    const float var  = tss * (1.f / 768.f) - mean * mean;
    const float rstd = rsqrtf(var + 1e-5f);

    #pragma unroll
    for (int i = 0; i < 3; i++) {
        int c = tid + i * 256;
        Y[(long)r * DM + c] = (v[i] - mean) * rstd * g[c] + b[c];
    }
}

// ============================================================
extern "C" void kernel_launch(void* const* d_in, const int* in_sizes, int n_in,
                              void* d_out, int out_size)
{
    const float* x   = (const float*)d_in[0];
    const float* Wq  = (const float*)d_in[1];
    const float* bq  = (const float*)d_in[2];
    const float* Wk  = (const float*)d_in[3];
    const float* bk  = (const float*)d_in[4];
    const float* Wv  = (const float*)d_in[5];
    const float* bv  = (const float*)d_in[6];
    const float* Wo  = (const float*)d_in[7];
    const float* bo  = (const float*)d_in[8];
    const float* W1  = (const float*)d_in[9];
    const float* b1  = (const float*)d_in[10];
    const float* W2  = (const float*)d_in[11];
    const float* b2  = (const float*)d_in[12];
    const float* g1  = (const float*)d_in[13];
    const float* be1 = (const float*)d_in[14];
    const float* g2  = (const float*)d_in[15];
    const float* be2 = (const float*)d_in[16];
    float* out = (float*)d_out;

    float *q, *k, *v, *attn, *y1, *hbuf, *ff1, *y2;
    cudaGetSymbolAddress((void**)&q,    g_q);
    cudaGetSymbolAddress((void**)&k,    g_k);
    cudaGetSymbolAddress((void**)&v,    g_v);
    cudaGetSymbolAddress((void**)&attn, g_attn);
    cudaGetSymbolAddress((void**)&y1,   g_y1);
    cudaGetSymbolAddress((void**)&hbuf, g_h);
    cudaGetSymbolAddress((void**)&ff1,  g_ff1);
    cudaGetSymbolAddress((void**)&y2,   g_y2);

    __nv_bfloat16 *wqh, *wql, *wkh, *wkl, *wvh, *wvl, *woh, *wol, *w1h, *w1l, *w2h, *w2l;
    cudaGetSymbolAddress((void**)&wqh, g_wqh); cudaGetSymbolAddress((void**)&wql, g_wql);
    cudaGetSymbolAddress((void**)&wkh, g_wkh); cudaGetSymbolAddress((void**)&wkl, g_wkl);
    cudaGetSymbolAddress((void**)&wvh, g_wvh); cudaGetSymbolAddress((void**)&wvl, g_wvl);
    cudaGetSymbolAddress((void**)&woh, g_woh); cudaGetSymbolAddress((void**)&wol, g_wol);
    cudaGetSymbolAddress((void**)&w1h, g_w1h); cudaGetSymbolAddress((void**)&w1l, g_w1l);
    cudaGetSymbolAddress((void**)&w2h, g_w2h); cudaGetSymbolAddress((void**)&w2l, g_w2l);

    cudaFuncSetAttribute(gemm_bf16x3, cudaFuncAttributeMaxDynamicSharedMemorySize,
                         2 * STAGE);

    dim3 tblk(32, 8);
    wsplit_t<<<dim3(DM  / 32, DM  / 32), tblk>>>(Wq, wqh, wql, DM,  DM);
    wsplit_t<<<dim3(DM  / 32, DM  / 32), tblk>>>(Wk, wkh, wkl, DM,  DM);
    wsplit_t<<<dim3(DM  / 32, DM  / 32), tblk>>>(Wv, wvh, wvl, DM,  DM);
    wsplit_t<<<dim3(DM  / 32, DM  / 32), tblk>>>(Wo, woh, wol, DM,  DM);
    wsplit_t<<<dim3(DFF / 32, DM  / 32), tblk>>>(W1, w1h, w1l, DM,  DFF);
    wsplit_t<<<dim3(DM  / 32, DFF / 32), tblk>>>(W2, w2h, w2l, DFF, DM);

    dim3 blk(256);
    dim3 gProj(DM / 128, TSEQ / 128);    // (6, 32)
    dim3 gFF1(DFF / 128, TSEQ / 128);    // (24, 32)
    dim3 gAttn(TSEQ / 64, NH);
    const unsigned gsm = 2 * STAGE;

    gemm_bf16x3<<<gProj, blk, gsm>>>(x, wqh, wql, bq, nullptr, q, DM, DM, 0);
    gemm_bf16x3<<<gProj, blk, gsm>>>(x, wkh, wkl, bk, nullptr, k, DM, DM, 0);
    gemm_bf16x3<<<gProj, blk, gsm>>>(x, wvh, wvl, bv, nullptr, v, DM, DM, 0);

    attn_kernel<<<gAttn, blk>>>(q, k, v, attn);

    gemm_bf16x3<<<gProj, blk, gsm>>>(attn, woh, wol, bo, x, y1, DM, DM, 0);
    ln_kernel<<<TSEQ, blk>>>(y1, g1, be1, hbuf);

    gemm_bf16x3<<<gFF1, blk, gsm>>>(hbuf, w1h, w1l, b1, nullptr, ff1, DM, DFF, 1);
    gemm_bf16x3<<<gProj, blk, gsm>>>(ff1, w2h, w2l, b2, hbuf, y2, DFF, DM, 0);

    ln_kernel<<<TSEQ, blk>>>(y2, g2, be2, out);
}

// round 5
// speedup vs baseline: 2.5481x; 1.7322x over previous
#include <cuda_runtime.h>
#include <cuda_bf16.h>

#define TSEQ 4096
#define DM   768
#define NH   12
#define DKH  64
#define DFF  3072

// ---- fp32 scratch ----
__device__ float g_q   [TSEQ * DM];
__device__ float g_k   [TSEQ * DM];
__device__ float g_v   [TSEQ * DM];
__device__ float g_attn[TSEQ * DM];
__device__ float g_y1  [TSEQ * DM];
__device__ float g_h   [TSEQ * DM];
__device__ float g_ff1 [TSEQ * DFF];
__device__ float g_y2  [TSEQ * DM];

// ---- bf16 hi/lo transposed weights [N, K] ----
__device__ __nv_bfloat16 g_wqh[DM * DM],  g_wql[DM * DM];
__device__ __nv_bfloat16 g_wkh[DM * DM],  g_wkl[DM * DM];
__device__ __nv_bfloat16 g_wvh[DM * DM],  g_wvl[DM * DM];
__device__ __nv_bfloat16 g_woh[DM * DM],  g_wol[DM * DM];
__device__ __nv_bfloat16 g_w1h[DM * DFF], g_w1l[DM * DFF];
__device__ __nv_bfloat16 g_w2h[DM * DFF], g_w2l[DM * DFF];

// ---- bf16 hi/lo QKV, head-major [NH][TSEQ][64] ----
__device__ __nv_bfloat16 g_qbh[NH * TSEQ * DKH], g_qbl[NH * TSEQ * DKH];
__device__ __nv_bfloat16 g_kbh[NH * TSEQ * DKH], g_kbl[NH * TSEQ * DKH];
__device__ __nv_bfloat16 g_vbh[NH * TSEQ * DKH], g_vbl[NH * TSEQ * DKH];

// ============================================================
// helpers (sm_80+ baseline: valid on plain sm_103)
// ============================================================
__device__ __forceinline__ unsigned s2u(const void* p) {
    unsigned a;
    asm("{ .reg .u64 t; cvta.to.shared.u64 t, %1; cvt.u32.u64 %0, t; }"
        : "=r"(a) : "l"(p));
    return a;
}
__device__ __forceinline__ void ldm_x4(unsigned* r, unsigned addr) {
    asm volatile("ldmatrix.sync.aligned.m8n8.x4.shared.b16 {%0,%1,%2,%3}, [%4];"
                 : "=r"(r[0]), "=r"(r[1]), "=r"(r[2]), "=r"(r[3]) : "r"(addr));
}
__device__ __forceinline__ void ldm_x2(unsigned* r, unsigned addr) {
    asm volatile("ldmatrix.sync.aligned.m8n8.x2.shared.b16 {%0,%1}, [%2];"
                 : "=r"(r[0]), "=r"(r[1]) : "r"(addr));
}
__device__ __forceinline__ void ldm_x2t(unsigned* r, unsigned addr) {
    asm volatile("ldmatrix.sync.aligned.m8n8.x2.trans.shared.b16 {%0,%1}, [%2];"
                 : "=r"(r[0]), "=r"(r[1]) : "r"(addr));
}
__device__ __forceinline__ void mma_bf16(float* c, const unsigned* a, const unsigned* b) {
    asm volatile("mma.sync.aligned.m16n8k16.row.col.f32.bf16.bf16.f32 "
                 "{%0,%1,%2,%3}, {%4,%5,%6,%7}, {%8,%9}, {%0,%1,%2,%3};"
                 : "+f"(c[0]), "+f"(c[1]), "+f"(c[2]), "+f"(c[3])
                 : "r"(a[0]), "r"(a[1]), "r"(a[2]), "r"(a[3]), "r"(b[0]), "r"(b[1]));
}
__device__ __forceinline__ void cpa16(unsigned dst, const void* src) {
    asm volatile("cp.async.ca.shared.global [%0], [%1], 16;" :: "r"(dst), "l"(src));
}
__device__ __forceinline__ void cpa_commit() {
    asm volatile("cp.async.commit_group;" ::: "memory");
}
__device__ __forceinline__ void cpa_wait0() {
    asm volatile("cp.async.wait_group 0;" ::: "memory");
}

// ============================================================
// Weight transpose + bf16 hi/lo split: W[K,N] -> Th/Tl[N,K]
// ============================================================
__global__ __launch_bounds__(256) void wsplit_t(
    const float* __restrict__ W, __nv_bfloat16* __restrict__ Th,
    __nv_bfloat16* __restrict__ Tl, int K, int N)
{
    __shared__ float t[32][33];
    const int tx = threadIdx.x, ty = threadIdx.y;
    const int n0 = blockIdx.x * 32, k0 = blockIdx.y * 32;
    #pragma unroll
    for (int i = 0; i < 4; i++)
        t[ty + i * 8][tx] = W[(long)(k0 + ty + i * 8) * N + n0 + tx];
    __syncthreads();
    #pragma unroll
    for (int i = 0; i < 4; i++) {
        int n = n0 + ty + i * 8;
        float v = t[tx][ty + i * 8];
        __nv_bfloat16 h = __float2bfloat16_rn(v);
        __nv_bfloat16 l = __float2bfloat16_rn(v - __bfloat162float(h));
        Th[(long)n * K + k0 + tx] = h;
        Tl[(long)n * K + k0 + tx] = l;
    }
}

// ============================================================
// fp32 [T][768] -> bf16 hi/lo head-major [NH][T][64] (optional scale)
// ============================================================
__global__ __launch_bounds__(256) void qkv2bf16(
    const float* __restrict__ X, __nv_bfloat16* __restrict__ H,
    __nv_bfloat16* __restrict__ L, float scale)
{
    int idx = (blockIdx.x * 256 + threadIdx.x) * 4;   // over TSEQ*DM floats
    int t = idx / DM, c = idx % DM;
    int h = c >> 6, d = c & 63;
    float4 v = *(const float4*)(X + (long)t * DM + c);
    v.x *= scale; v.y *= scale; v.z *= scale; v.w *= scale;
    __nv_bfloat162 h01 = __floats2bfloat162_rn(v.x, v.y);
    __nv_bfloat162 h23 = __floats2bfloat162_rn(v.z, v.w);
    float2 f01 = __bfloat1622float2(h01);
    float2 f23 = __bfloat1622float2(h23);
    __nv_bfloat162 l01 = __floats2bfloat162_rn(v.x - f01.x, v.y - f01.y);
    __nv_bfloat162 l23 = __floats2bfloat162_rn(v.z - f23.x, v.w - f23.y);
    long off = ((long)h * TSEQ + t) * DKH + d;
    *(__nv_bfloat162*)(H + off)     = h01;
    *(__nv_bfloat162*)(H + off + 2) = h23;
    *(__nv_bfloat162*)(L + off)     = l01;
    *(__nv_bfloat162*)(L + off + 2) = l23;
}

// ============================================================
// bf16x3 tensor-core GEMM via mma.sync (unchanged from R3)
// ============================================================
#define BKC    32
#define ASTR   40
#define SEG    10240
#define STAGE  (4 * SEG)

__global__ __launch_bounds__(256, 2)
void gemm_bf16x3(const float* __restrict__ A,
                 const __nv_bfloat16* __restrict__ Bth,
                 const __nv_bfloat16* __restrict__ Btl,
                 const float* __restrict__ bias,
                 const float* __restrict__ res,
                 float* __restrict__ C,
                 int K, int N, int relu)
{
    extern __shared__ __align__(16) char smem[];

    const int tid   = threadIdx.x;
    const int wid   = tid >> 5;
    const int lane  = tid & 31;
    const int warpM = wid & 1;
    const int warpN = wid >> 1;
    const int brow  = blockIdx.y * 128;
    const int bcol  = blockIdx.x * 128;
    const unsigned smem_u = s2u(smem);

    float acc[4][4][4];
    #pragma unroll
    for (int mi = 0; mi < 4; mi++)
        #pragma unroll
        for (int ni = 0; ni < 4; ni++)
            #pragma unroll
            for (int r = 0; r < 4; r++) acc[mi][ni][r] = 0.f;

    const int nch = K / BKC;

    float4 aReg[4];
    uint4  bhReg[2], blReg[2];

    {
        const float* Abase = A + (long)brow * K;
        #pragma unroll
        for (int it = 0; it < 4; it++) {
            int idx = tid + it * 256;
            int r = idx >> 3, c4 = idx & 7;
            aReg[it] = *(const float4*)(Abase + (long)r * K + c4 * 4);
        }
        #pragma unroll
        for (int it = 0; it < 2; it++) {
            int idx = tid + it * 256;
            int n = idx >> 2, cc = idx & 3;
            bhReg[it] = *(const uint4*)((const char*)(Bth + (long)(bcol + n) * K) + cc * 16);
            blReg[it] = *(const uint4*)((const char*)(Btl + (long)(bcol + n) * K) + cc * 16);
        }
    }

    int s = 0;
    for (int c = 0; c < nch; ++c) {
        char* base = smem + s * STAGE;
        char* sAh = base;
        char* sAl = base + SEG;
        char* sBh = base + 2 * SEG;
        char* sBl = base + 3 * SEG;

        #pragma unroll
        for (int it = 0; it < 4; it++) {
            int idx = tid + it * 256;
            int r = idx >> 3, c4 = idx & 7;
            float4 av = aReg[it];
            __nv_bfloat162 h01 = __floats2bfloat162_rn(av.x, av.y);
            __nv_bfloat162 h23 = __floats2bfloat162_rn(av.z, av.w);
            float2 f01 = __bfloat1622float2(h01);
            float2 f23 = __bfloat1622float2(h23);
            __nv_bfloat162 l01 = __floats2bfloat162_rn(av.x - f01.x, av.y - f01.y);
            __nv_bfloat162 l23 = __floats2bfloat162_rn(av.z - f23.x, av.w - f23.y);
            int off = (r * ASTR + c4 * 4) * 2;
            *(__nv_bfloat162*)(sAh + off)     = h01;
            *(__nv_bfloat162*)(sAh + off + 4) = h23;
            *(__nv_bfloat162*)(sAl + off)     = l01;
            *(__nv_bfloat162*)(sAl + off + 4) = l23;
        }
        #pragma unroll
        for (int it = 0; it < 2; it++) {
            int idx = tid + it * 256;
            int n = idx >> 2, cc = idx & 3;
            int off = n * (ASTR * 2) + cc * 16;
            *(uint4*)(sBh + off) = bhReg[it];
            *(uint4*)(sBl + off) = blReg[it];
        }
        __syncthreads();

        if (c + 1 < nch) {
            const int kc = (c + 1) * BKC;
            const float* Abase = A + (long)brow * K + kc;
            #pragma unroll
            for (int it = 0; it < 4; it++) {
                int idx = tid + it * 256;
                int r = idx >> 3, c4 = idx & 7;
                aReg[it] = *(const float4*)(Abase + (long)r * K + c4 * 4);
            }
            #pragma unroll
            for (int it = 0; it < 2; it++) {
                int idx = tid + it * 256;
                int n = idx >> 2, cc = idx & 3;
                bhReg[it] = *(const uint4*)((const char*)(Bth + (long)(bcol + n) * K + kc) + cc * 16);
                blReg[it] = *(const uint4*)((const char*)(Btl + (long)(bcol + n) * K + kc) + cc * 16);
            }
        }

        const unsigned uAh = smem_u + s * STAGE;
        const unsigned uAl = uAh + SEG;
        const unsigned uBh = uAh + 2 * SEG;
        const unsigned uBl = uAh + 3 * SEG;

        #pragma unroll
        for (int kk = 0; kk < 2; kk++) {
            unsigned ah[4][4], al[4][4];
            #pragma unroll
            for (int mi = 0; mi < 4; mi++) {
                unsigned rowoff =
                    (unsigned)(((warpM * 64 + mi * 16 + (lane & 15)) * ASTR
                                + (lane >> 4) * 8 + kk * 16) * 2);
                ldm_x4(ah[mi], uAh + rowoff);
                ldm_x4(al[mi], uAl + rowoff);
            }
            #pragma unroll
            for (int ni = 0; ni < 4; ni++) {
                unsigned boff =
                    (unsigned)(((warpN * 32 + ni * 8 + (lane & 7)) * ASTR
                                + ((lane >> 3) & 1) * 8 + kk * 16) * 2);
                unsigned bh[2], bl[2];
                ldm_x2(bh, uBh + boff);
                ldm_x2(bl, uBl + boff);
                #pragma unroll
                for (int mi = 0; mi < 4; mi++) {
                    mma_bf16(acc[mi][ni], ah[mi], bh);
                    mma_bf16(acc[mi][ni], ah[mi], bl);
                    mma_bf16(acc[mi][ni], al[mi], bh);
                }
            }
        }
        s ^= 1;
    }

    #pragma unroll
    for (int mi = 0; mi < 4; mi++) {
        #pragma unroll
        for (int half = 0; half < 2; half++) {
            int row = brow + warpM * 64 + mi * 16 + (lane >> 2) + half * 8;
            float* crow = C + (long)row * N;
            const float* rrow = res ? (res + (long)row * N) : (const float*)0;
            #pragma unroll
            for (int ni = 0; ni < 4; ni++) {
                int col = bcol + warpN * 32 + ni * 8 + (lane & 3) * 2;
                float2 o;
                o.x = acc[mi][ni][half * 2 + 0] + bias[col + 0];
                o.y = acc[mi][ni][half * 2 + 1] + bias[col + 1];
                if (relu) { o.x = fmaxf(o.x, 0.f); o.y = fmaxf(o.y, 0.f); }
                if (rrow) {
                    float2 r = *(const float2*)(rrow + col);
                    o.x += r.x; o.y += r.y;
                }
                *(float2*)(crow + col) = o;
            }
        }
    }
}

// ============================================================
// Tensor-core flash attention, causal, bf16 hi/lo (x3 passes)
// CTA = (head, 128-q tile), 8 warps x 16 q-rows, key blocks of 64.
// cp.async double-buffered K/V. Q frags resident in registers.
// ============================================================
#define AT_STR  72                    // bf16 row stride (144 B)
#define Q_BYTES (128 * 144)           // 18432 per Q array
#define KV_ARR  (64 * 144)            // 9216 per KV array
#define KV_STG  (4 * KV_ARR)          // 36864 per stage
#define SM_KV   (2 * Q_BYTES)         // 36864
#define AT_SMEM (SM_KV + 2 * KV_STG)  // 110592

__global__ __launch_bounds__(256)
void attn_tc(const __nv_bfloat16* __restrict__ Qh, const __nv_bfloat16* __restrict__ Ql,
             const __nv_bfloat16* __restrict__ Kh, const __nv_bfloat16* __restrict__ Kl,
             const __nv_bfloat16* __restrict__ Vh, const __nv_bfloat16* __restrict__ Vl,
             float* __restrict__ O)
{
    extern __shared__ __align__(16) char sm[];
    const unsigned smu = s2u(sm);
    const int tid  = threadIdx.x;
    const int lane = tid & 31;
    const int wq   = tid >> 5;                       // warp -> q rows wq*16..+15
    const int qb   = (int)gridDim.x - 1 - (int)blockIdx.x;
    const int h    = blockIdx.y;
    const long hb  = (long)h * TSEQ * DKH;

    // ---- load Q hi/lo (128x64) ----
    {
        const char* sh = (const char*)(Qh + hb + (long)qb * 128 * DKH);
        const char* sl = (const char*)(Ql + hb + (long)qb * 128 * DKH);
        #pragma unroll
        for (int it = 0; it < 4; it++) {
            int idx = tid + it * 256;                // 0..1023
            int row = idx >> 3, ch = idx & 7;
            cpa16(smu + row * 144 + ch * 16,          sh + row * 128 + ch * 16);
            cpa16(smu + Q_BYTES + row * 144 + ch * 16, sl + row * 128 + ch * 16);
        }
    }
    // ---- load KV block 0 into stage 0 ----
    const char* kvsrc[4] = { (const char*)(Kh + hb), (const char*)(Kl + hb),
                             (const char*)(Vh + hb), (const char*)(Vl + hb) };
    {
        #pragma unroll
        for (int it = 0; it < 8; it++) {
            int idx = tid + it * 256;                // 0..2047
            int arr = idx >> 9, rem = idx & 511;
            int row = rem >> 3, ch = rem & 7;
            cpa16(smu + SM_KV + arr * KV_ARR + row * 144 + ch * 16,
                  kvsrc[arr] + (long)row * 128 + ch * 16);
        }
    }
    cpa_commit();
    cpa_wait0();
    __syncthreads();

    // ---- Q fragments to registers (4 k-steps of d) ----
    unsigned qfh[4][4], qfl[4][4];
    #pragma unroll
    for (int kt = 0; kt < 4; kt++) {
        unsigned a = smu + (wq * 16 + (lane & 15)) * 144
                   + ((lane >> 4) * 8 + kt * 16) * 2;
        ldm_x4(qfh[kt], a);
        ldm_x4(qfl[kt], a + Q_BYTES);
    }

    float o_[8][4];
    #pragma unroll
    for (int i = 0; i < 8; i++)
        #pragma unroll
        for (int j = 0; j < 4; j++) o_[i][j] = 0.f;
    float m0 = -1e30f, m1 = -1e30f, l0 = 0.f, l1 = 0.f;

    const int nkb    = (qb + 1) * 2;
    const int diagKb = (qb * 128 + wq * 16) >> 6;
    const int r0g    = qb * 128 + wq * 16 + (lane >> 2);

    for (int kb = 0; kb < nkb; kb++) {
        const int s = kb & 1;

        // prefetch next KV block into other stage
        if (kb + 1 < nkb) {
            const long kb0 = (long)(kb + 1) * 64;
            #pragma unroll
            for (int it = 0; it < 8; it++) {
                int idx = tid + it * 256;
                int arr = idx >> 9, rem = idx & 511;
                int row = rem >> 3, ch = rem & 7;
                cpa16(smu + SM_KV + (s ^ 1) * KV_STG + arr * KV_ARR + row * 144 + ch * 16,
                      kvsrc[arr] + (kb0 + row) * 128 + ch * 16);
            }
        }
        cpa_commit();

        // ---- S = Q K^T (hi/lo x3) ----
        float sc[8][4];
        #pragma unroll
        for (int i = 0; i < 8; i++)
            #pragma unroll
            for (int j = 0; j < 4; j++) sc[i][j] = 0.f;

        const unsigned kbase = smu + SM_KV + s * KV_STG;
        #pragma unroll
        for (int kt = 0; kt < 4; kt++) {
            #pragma unroll
            for (int nt = 0; nt < 8; nt++) {
                unsigned ka = kbase + (nt * 8 + (lane & 7)) * 144
                            + (((lane >> 3) & 1) * 8 + kt * 16) * 2;
                unsigned bh[2], bl[2];
                ldm_x2(bh, ka);
                ldm_x2(bl, ka + KV_ARR);
                mma_bf16(sc[nt], qfh[kt], bh);
                mma_bf16(sc[nt], qfh[kt], bl);
                mma_bf16(sc[nt], qfl[kt], bh);
            }
        }

        // ---- causal mask ----
        if (kb >= diagKb) {
            #pragma unroll
            for (int nt = 0; nt < 8; nt++) {
                int keyb = kb * 64 + nt * 8 + (lane & 3) * 2;
                #pragma unroll
                for (int c = 0; c < 4; c++) {
                    int key = keyb + (c & 1);
                    int row = r0g + (c >> 1) * 8;
                    if (key > row) sc[nt][c] = -1e30f;
                }
            }
        }

        // ---- online softmax (rows r0g and r0g+8) ----
        float pm0 = -1e30f, pm1 = -1e30f;
        #pragma unroll
        for (int nt = 0; nt < 8; nt++) {
            pm0 = fmaxf(pm0, fmaxf(sc[nt][0], sc[nt][1]));
            pm1 = fmaxf(pm1, fmaxf(sc[nt][2], sc[nt][3]));
        }
        pm0 = fmaxf(pm0, __shfl_xor_sync(0xffffffffu, pm0, 1));
        pm0 = fmaxf(pm0, __shfl_xor_sync(0xffffffffu, pm0, 2));
        pm1 = fmaxf(pm1, __shfl_xor_sync(0xffffffffu, pm1, 1));
        pm1 = fmaxf(pm1, __shfl_xor_sync(0xffffffffu, pm1, 2));

        float mn0 = fmaxf(m0, pm0), mn1 = fmaxf(m1, pm1);
        float a0 = __expf(m0 - mn0), a1 = __expf(m1 - mn1);
        m0 = mn0; m1 = mn1;

        float rs0 = 0.f, rs1 = 0.f;
        #pragma unroll
        for (int nt = 0; nt < 8; nt++) {
            sc[nt][0] = __expf(sc[nt][0] - mn0);
            sc[nt][1] = __expf(sc[nt][1] - mn0);
            sc[nt][2] = __expf(sc[nt][2] - mn1);
            sc[nt][3] = __expf(sc[nt][3] - mn1);
            rs0 += sc[nt][0] + sc[nt][1];
            rs1 += sc[nt][2] + sc[nt][3];
        }
        rs0 += __shfl_xor_sync(0xffffffffu, rs0, 1);
        rs0 += __shfl_xor_sync(0xffffffffu, rs0, 2);
        rs1 += __shfl_xor_sync(0xffffffffu, rs1, 1);
        rs1 += __shfl_xor_sync(0xffffffffu, rs1, 2);
        l0 = l0 * a0 + rs0;
        l1 = l1 * a1 + rs1;

        #pragma unroll
        for (int dt = 0; dt < 8; dt++) {
            o_[dt][0] *= a0; o_[dt][1] *= a0;
            o_[dt][2] *= a1; o_[dt][3] *= a1;
        }

        // ---- pack P -> A fragments (hi/lo) ----
        // Accumulator regs {c0,c1}=(row r), {c2,c3}=(row r+8); A frag regs:
        // a0=(r,k0..1), a1=(r+8,k0..1), a2=(r,k8..9), a3=(r+8,k8..9).
        // sc[2kt] covers keys kt*16+0..7, sc[2kt+1] covers kt*16+8..15, so
        // pf[kt] = { sc[2kt].rowr, sc[2kt].rowr8, sc[2kt+1].rowr, sc[2kt+1].rowr8 }
        // matches {a0,a1,a2,a3} directly — NO reordering needed.
        unsigned pfh[4][4], pfl[4][4];
        #pragma unroll
        for (int kt = 0; kt < 4; kt++) {
            #pragma unroll
            for (int half = 0; half < 2; half++) {   // key +0 / +8 within k16
                const float* v0 = sc[kt * 2 + half];
                __nv_bfloat162 h01 = __floats2bfloat162_rn(v0[0], v0[1]);
                __nv_bfloat162 h23 = __floats2bfloat162_rn(v0[2], v0[3]);
                float2 f01 = __bfloat1622float2(h01);
                float2 f23 = __bfloat1622float2(h23);
                __nv_bfloat162 l01 = __floats2bfloat162_rn(v0[0] - f01.x, v0[1] - f01.y);
                __nv_bfloat162 l23 = __floats2bfloat162_rn(v0[2] - f23.x, v0[3] - f23.y);
                pfh[kt][half * 2 + 0] = *(unsigned*)&h01;
                pfh[kt][half * 2 + 1] = *(unsigned*)&h23;
                pfl[kt][half * 2 + 0] = *(unsigned*)&l01;
                pfl[kt][half * 2 + 1] = *(unsigned*)&l23;
            }
        }

        // ---- O += P V (hi/lo x3) ----
        const unsigned vbase = kbase + 2 * KV_ARR;
        #pragma unroll
        for (int kt = 0; kt < 4; kt++) {
            #pragma unroll
            for (int nt = 0; nt < 8; nt++) {
                unsigned va = vbase + (kt * 16 + (lane & 15)) * 144 + nt * 16;
                unsigned bh[2], bl[2];
                ldm_x2t(bh, va);
                ldm_x2t(bl, va + KV_ARR);
                mma_bf16(o_[nt], pfh[kt], bh);
                mma_bf16(o_[nt], pfh[kt], bl);
                mma_bf16(o_[nt], pfl[kt], bh);
            }
        }

        cpa_wait0();
        __syncthreads();
    }

    // ---- write O ----
    const float i0 = 1.f / l0, i1 = 1.f / l1;
    #pragma unroll
    for (int nt = 0; nt < 8; nt++) {
        int col = h * DKH + nt * 8 + (lane & 3) * 2;
        float2 w0 = { o_[nt][0] * i0, o_[nt][1] * i0 };
        float2 w1 = { o_[nt][2] * i1, o_[nt][3] * i1 };
        *(float2*)(O + (long)r0g * DM + col)       = w0;
        *(float2*)(O + (long)(r0g + 8) * DM + col) = w1;
    }
}

// ============================================================
// LayerNorm — unchanged
// ============================================================
__global__ __launch_bounds__(256) void ln_kernel(
    const float* __restrict__ X, const float* __restrict__ g,
    const float* __restrict__ b, float* __restrict__ Y)
{
    const int r   = blockIdx.x;
    const int tid = threadIdx.x;
    const float* x = X + (long)r * DM;

    float v[3];
    float s = 0.f, ss = 0.f;
    #pragma unroll
    for (int i = 0; i < 3; i++) {
        v[i] = x[tid + i * 256];
        s  += v[i];
        ss += v[i] * v[i];
    }
    #pragma unroll
    for (int off = 16; off > 0; off >>= 1) {
        s  += __shfl_xor_sync(0xffffffffu, s,  off);
        ss += __shfl_xor_sync(0xffffffffu, ss, off);
    }
    __shared__ float rs_[8], rss_[8];
    const int lane = tid & 31, wid = tid >> 5;
    if (lane == 0) { rs_[wid] = s; rss_[wid] = ss; }
    __syncthreads();
    float ts = 0.f, tss = 0.f;
    #pragma unroll
    for (int w = 0; w < 8; w++) { ts += rs_[w]; tss += rss_[w]; }

    const float mean = ts * (1.f / 768.f);
    const float var  = tss * (1.f / 768.f) - mean * mean;
    const float rstd = rsqrtf(var + 1e-5f);

    #pragma unroll
    for (int i = 0; i < 3; i++) {
        int c = tid + i * 256;
        Y[(long)r * DM + c] = (v[i] - mean) * rstd * g[c] + b[c];
    }
}

// ============================================================
extern "C" void kernel_launch(void* const* d_in, const int* in_sizes, int n_in,
                              void* d_out, int out_size)
{
    const float* x   = (const float*)d_in[0];
    const float* Wq  = (const float*)d_in[1];
    const float* bq  = (const float*)d_in[2];
    const float* Wk  = (const float*)d_in[3];
    const float* bk  = (const float*)d_in[4];
    const float* Wv  = (const float*)d_in[5];
    const float* bv  = (const float*)d_in[6];
    const float* Wo  = (const float*)d_in[7];
    const float* bo  = (const float*)d_in[8];
    const float* W1  = (const float*)d_in[9];
    const float* b1  = (const float*)d_in[10];
    const float* W2  = (const float*)d_in[11];
    const float* b2  = (const float*)d_in[12];
    const float* g1  = (const float*)d_in[13];
    const float* be1 = (const float*)d_in[14];
    const float* g2  = (const float*)d_in[15];
    const float* be2 = (const float*)d_in[16];
    float* out = (float*)d_out;

    float *q, *k, *v, *attn, *y1, *hbuf, *ff1, *y2;
    cudaGetSymbolAddress((void**)&q,    g_q);
    cudaGetSymbolAddress((void**)&k,    g_k);
    cudaGetSymbolAddress((void**)&v,    g_v);
    cudaGetSymbolAddress((void**)&attn, g_attn);
    cudaGetSymbolAddress((void**)&y1,   g_y1);
    cudaGetSymbolAddress((void**)&hbuf, g_h);
    cudaGetSymbolAddress((void**)&ff1,  g_ff1);
    cudaGetSymbolAddress((void**)&y2,   g_y2);

    __nv_bfloat16 *wqh, *wql, *wkh, *wkl, *wvh, *wvl, *woh, *wol, *w1h, *w1l, *w2h, *w2l;
    cudaGetSymbolAddress((void**)&wqh, g_wqh); cudaGetSymbolAddress((void**)&wql, g_wql);
    cudaGetSymbolAddress((void**)&wkh, g_wkh); cudaGetSymbolAddress((void**)&wkl, g_wkl);
    cudaGetSymbolAddress((void**)&wvh, g_wvh); cudaGetSymbolAddress((void**)&wvl, g_wvl);
    cudaGetSymbolAddress((void**)&woh, g_woh); cudaGetSymbolAddress((void**)&wol, g_wol);
    cudaGetSymbolAddress((void**)&w1h, g_w1h); cudaGetSymbolAddress((void**)&w1l, g_w1l);
    cudaGetSymbolAddress((void**)&w2h, g_w2h); cudaGetSymbolAddress((void**)&w2l, g_w2l);

    __nv_bfloat16 *qbh, *qbl, *kbh, *kbl, *vbh, *vbl;
    cudaGetSymbolAddress((void**)&qbh, g_qbh); cudaGetSymbolAddress((void**)&qbl, g_qbl);
    cudaGetSymbolAddress((void**)&kbh, g_kbh); cudaGetSymbolAddress((void**)&kbl, g_kbl);
    cudaGetSymbolAddress((void**)&vbh, g_vbh); cudaGetSymbolAddress((void**)&vbl, g_vbl);

    cudaFuncSetAttribute(gemm_bf16x3, cudaFuncAttributeMaxDynamicSharedMemorySize,
                         2 * STAGE);
    cudaFuncSetAttribute(attn_tc, cudaFuncAttributeMaxDynamicSharedMemorySize,
                         AT_SMEM);

    dim3 tblk(32, 8);
    wsplit_t<<<dim3(DM  / 32, DM  / 32), tblk>>>(Wq, wqh, wql, DM,  DM);
    wsplit_t<<<dim3(DM  / 32, DM  / 32), tblk>>>(Wk, wkh, wkl, DM,  DM);
    wsplit_t<<<dim3(DM  / 32, DM  / 32), tblk>>>(Wv, wvh, wvl, DM,  DM);
    wsplit_t<<<dim3(DM  / 32, DM  / 32), tblk>>>(Wo, woh, wol, DM,  DM);
    wsplit_t<<<dim3(DFF / 32, DM  / 32), tblk>>>(W1, w1h, w1l, DM,  DFF);
    wsplit_t<<<dim3(DM  / 32, DFF / 32), tblk>>>(W2, w2h, w2l, DFF, DM);

    dim3 blk(256);
    dim3 gProj(DM / 128, TSEQ / 128);
    dim3 gFF1(DFF / 128, TSEQ / 128);
    const unsigned gsm = 2 * STAGE;

    gemm_bf16x3<<<gProj, blk, gsm>>>(x, wqh, wql, bq, nullptr, q, DM, DM, 0);
    gemm_bf16x3<<<gProj, blk, gsm>>>(x, wkh, wkl, bk, nullptr, k, DM, DM, 0);
    gemm_bf16x3<<<gProj, blk, gsm>>>(x, wvh, wvl, bv, nullptr, v, DM, DM, 0);

    const int cvB = (TSEQ * DM / 4) / 256;     // 3072
    qkv2bf16<<<cvB, blk>>>(q, qbh, qbl, 0.125f);
    qkv2bf16<<<cvB, blk>>>(k, kbh, kbl, 1.0f);
    qkv2bf16<<<cvB, blk>>>(v, vbh, vbl, 1.0f);

    attn_tc<<<dim3(TSEQ / 128, NH), blk, AT_SMEM>>>(qbh, qbl, kbh, kbl, vbh, vbl, attn);

    gemm_bf16x3<<<gProj, blk, gsm>>>(attn, woh, wol, bo, x, y1, DM, DM, 0);
    ln_kernel<<<TSEQ, blk>>>(y1, g1, be1, hbuf);

    gemm_bf16x3<<<gFF1, blk, gsm>>>(hbuf, w1h, w1l, b1, nullptr, ff1, DM, DFF, 1);
    gemm_bf16x3<<<gProj, blk, gsm>>>(ff1, w2h, w2l, b2, hbuf, y2, DFF, DM, 0);

    ln_kernel<<<TSEQ, blk>>>(y2, g2, be2, out);
}

// round 6
// speedup vs baseline: 3.0099x; 1.1812x over previous
#include <cuda_runtime.h>
#include <cuda_bf16.h>

#define TSEQ 4096
#define DM   768
#define NH   12
#define DKH  64
#define DFF  3072

// ---- fp32 scratch ----
__device__ float g_y1  [TSEQ * DM];
__device__ float g_h   [TSEQ * DM];
__device__ float g_y2  [TSEQ * DM];
__device__ float g_bqkv[3 * DM];

// ---- bf16 hi/lo pre-split activations ----
__device__ __nv_bfloat16 g_xh [TSEQ * DM],  g_xl [TSEQ * DM];
__device__ __nv_bfloat16 g_abh[TSEQ * DM],  g_abl[TSEQ * DM];
__device__ __nv_bfloat16 g_hh [TSEQ * DM],  g_hl [TSEQ * DM];
__device__ __nv_bfloat16 g_f1h[TSEQ * DFF], g_f1l[TSEQ * DFF];

// ---- bf16 hi/lo transposed weights [N, K] ----
__device__ __nv_bfloat16 g_wqkvh[3 * DM * DM], g_wqkvl[3 * DM * DM];
__device__ __nv_bfloat16 g_woh[DM * DM],  g_wol[DM * DM];
__device__ __nv_bfloat16 g_w1h[DM * DFF], g_w1l[DM * DFF];
__device__ __nv_bfloat16 g_w2h[DM * DFF], g_w2l[DM * DFF];

// ---- bf16 hi/lo QKV, head-major [NH][TSEQ][64] ----
__device__ __nv_bfloat16 g_qbh[NH * TSEQ * DKH], g_qbl[NH * TSEQ * DKH];
__device__ __nv_bfloat16 g_kbh[NH * TSEQ * DKH], g_kbl[NH * TSEQ * DKH];
__device__ __nv_bfloat16 g_vbh[NH * TSEQ * DKH], g_vbl[NH * TSEQ * DKH];

// ============================================================
// helpers (sm_80+ baseline: valid on plain sm_103)
// ============================================================
__device__ __forceinline__ unsigned s2u(const void* p) {
    unsigned a;
    asm("{ .reg .u64 t; cvta.to.shared.u64 t, %1; cvt.u32.u64 %0, t; }"
        : "=r"(a) : "l"(p));
    return a;
}
__device__ __forceinline__ void ldm_x4(unsigned* r, unsigned addr) {
    asm volatile("ldmatrix.sync.aligned.m8n8.x4.shared.b16 {%0,%1,%2,%3}, [%4];"
                 : "=r"(r[0]), "=r"(r[1]), "=r"(r[2]), "=r"(r[3]) : "r"(addr));
}
__device__ __forceinline__ void ldm_x2(unsigned* r, unsigned addr) {
    asm volatile("ldmatrix.sync.aligned.m8n8.x2.shared.b16 {%0,%1}, [%2];"
                 : "=r"(r[0]), "=r"(r[1]) : "r"(addr));
}
__device__ __forceinline__ void ldm_x2t(unsigned* r, unsigned addr) {
    asm volatile("ldmatrix.sync.aligned.m8n8.x2.trans.shared.b16 {%0,%1}, [%2];"
                 : "=r"(r[0]), "=r"(r[1]) : "r"(addr));
}
__device__ __forceinline__ void mma_bf16(float* c, const unsigned* a, const unsigned* b) {
    asm volatile("mma.sync.aligned.m16n8k16.row.col.f32.bf16.bf16.f32 "
                 "{%0,%1,%2,%3}, {%4,%5,%6,%7}, {%8,%9}, {%0,%1,%2,%3};"
                 : "+f"(c[0]), "+f"(c[1]), "+f"(c[2]), "+f"(c[3])
                 : "r"(a[0]), "r"(a[1]), "r"(a[2]), "r"(a[3]), "r"(b[0]), "r"(b[1]));
}
__device__ __forceinline__ void cpa16(unsigned dst, const void* src) {
    asm volatile("cp.async.cg.shared.global [%0], [%1], 16;" :: "r"(dst), "l"(src));
}
__device__ __forceinline__ void cpa16ca(unsigned dst, const void* src) {
    asm volatile("cp.async.ca.shared.global [%0], [%1], 16;" :: "r"(dst), "l"(src));
}
__device__ __forceinline__ void cpa_commit() {
    asm volatile("cp.async.commit_group;" ::: "memory");
}
template<int N> __device__ __forceinline__ void cpa_wait() {
    asm volatile("cp.async.wait_group %0;" :: "n"(N) : "memory");
}
// fp32x2 -> bf16 hi/lo pair
__device__ __forceinline__ void split2(float x, float y,
                                       __nv_bfloat162& h, __nv_bfloat162& l) {
    h = __floats2bfloat162_rn(x, y);
    float2 f = __bfloat1622float2(h);
    l = __floats2bfloat162_rn(x - f.x, y - f.y);
}

// ============================================================
// Weight transpose + bf16 hi/lo split: W[K,N] -> Th/Tl[N,K]
// ============================================================
__device__ __forceinline__ void wsplit_body(
    const float* __restrict__ W, __nv_bfloat16* __restrict__ Th,
    __nv_bfloat16* __restrict__ Tl, int K, int N,
    int n0, int k0, float t[32][33])
{
    const int tx = threadIdx.x, ty = threadIdx.y;
    #pragma unroll
    for (int i = 0; i < 4; i++)
        t[ty + i * 8][tx] = W[(long)(k0 + ty + i * 8) * N + n0 + tx];
    __syncthreads();
    #pragma unroll
    for (int i = 0; i < 4; i++) {
        int n = n0 + ty + i * 8;
        float v = t[tx][ty + i * 8];
        __nv_bfloat16 h = __float2bfloat16_rn(v);
        __nv_bfloat16 l = __float2bfloat16_rn(v - __bfloat162float(h));
        Th[(long)n * K + k0 + tx] = h;
        Tl[(long)n * K + k0 + tx] = l;
    }
}
__global__ __launch_bounds__(256) void wsplit_t(
    const float* __restrict__ W, __nv_bfloat16* __restrict__ Th,
    __nv_bfloat16* __restrict__ Tl, int K, int N)
{
    __shared__ float t[32][33];
    wsplit_body(W, Th, Tl, K, N, blockIdx.x * 32, blockIdx.y * 32, t);
}
// 4 square weights (Wq,Wk,Wv -> combined buffer; Wo separate) in one launch
__global__ __launch_bounds__(256) void wsplit4(
    const float* __restrict__ W0, const float* __restrict__ W1,
    const float* __restrict__ W2, const float* __restrict__ W3,
    __nv_bfloat16* __restrict__ qkvh, __nv_bfloat16* __restrict__ qkvl,
    __nv_bfloat16* __restrict__ oh,   __nv_bfloat16* __restrict__ ol)
{
    __shared__ float t[32][33];
    const int z = blockIdx.z;
    const float* W = (z == 0) ? W0 : (z == 1) ? W1 : (z == 2) ? W2 : W3;
    __nv_bfloat16* Th = (z < 3) ? (qkvh + (long)z * DM * DM) : oh;
    __nv_bfloat16* Tl = (z < 3) ? (qkvl + (long)z * DM * DM) : ol;
    wsplit_body(W, Th, Tl, DM, DM, blockIdx.x * 32, blockIdx.y * 32, t);
}

// ============================================================
// fp32 -> bf16 hi/lo elementwise (row-major, no reorder)
// ============================================================
__global__ __launch_bounds__(256) void fsplit(
    const float* __restrict__ X, __nv_bfloat16* __restrict__ H,
    __nv_bfloat16* __restrict__ L)
{
    long idx = ((long)blockIdx.x * 256 + threadIdx.x) * 4;
    float4 v = *(const float4*)(X + idx);
    __nv_bfloat162 h01, l01, h23, l23;
    split2(v.x, v.y, h01, l01);
    split2(v.z, v.w, h23, l23);
    *(__nv_bfloat162*)(H + idx)     = h01;
    *(__nv_bfloat162*)(H + idx + 2) = h23;
    *(__nv_bfloat162*)(L + idx)     = l01;
    *(__nv_bfloat162*)(L + idx + 2) = l23;
}

// ============================================================
// bf16x3 GEMM, pre-split A and B, cp.async double-buffered.
// C[M,N] = A[M,K] @ B^T[N,K]  (+bias)
// MODE 0: fp32 out (+res).  MODE 1: bf16 hi/lo out (+relu).
// MODE 2: QKV head-major bf16 hi/lo out (Q scaled).
// ============================================================
#define BKC   32
#define ASTR  40
#define SEG   10240                 // 128 rows * 80 B
#define STGB  (4 * SEG)             // 40960 per stage
#define GSMEM (2 * STGB)            // 81920

template<int MODE, bool RELU, bool HASRES>
__global__ __launch_bounds__(256, 2)
void gemm_bfp(const __nv_bfloat16* __restrict__ Ah, const __nv_bfloat16* __restrict__ Al,
              const __nv_bfloat16* __restrict__ Bh, const __nv_bfloat16* __restrict__ Bl,
              const float* __restrict__ bias, const float* __restrict__ res,
              float* __restrict__ Cf, __nv_bfloat16* __restrict__ Ch,
              __nv_bfloat16* __restrict__ Cl, int K, int N)
{
    extern __shared__ __align__(128) char smem[];
    const int tid   = threadIdx.x;
    const int wid   = tid >> 5;
    const int lane  = tid & 31;
    const int warpM = wid & 1;
    const int warpN = wid >> 1;
    const int brow  = blockIdx.y * 128;
    const int bcol  = blockIdx.x * 128;
    const unsigned smu = s2u(smem);

    const char* src[4] = { (const char*)Ah, (const char*)Al,
                           (const char*)Bh, (const char*)Bl };

    float acc[4][4][4];
    #pragma unroll
    for (int mi = 0; mi < 4; mi++)
        #pragma unroll
        for (int ni = 0; ni < 4; ni++)
            #pragma unroll
            for (int r = 0; r < 4; r++) acc[mi][ni][r] = 0.f;

    const int nch = K / BKC;

    // stage loader: 2048 cp.async16 over 256 threads = 8 each
    auto load_stage = [&](int s, int kc) {
        #pragma unroll
        for (int it = 0; it < 8; it++) {
            int idx = tid + it * 256;
            int arr = idx >> 9, rem = idx & 511;
            int row = rem >> 2, ch = rem & 3;
            int base_row = (arr < 2) ? (brow + row) : (bcol + row);
            cpa16(smu + s * STGB + arr * SEG + row * 80 + ch * 16,
                  src[arr] + ((long)base_row * K + kc) * 2 + ch * 16);
        }
    };

    load_stage(0, 0);
    cpa_commit();

    for (int c = 0; c < nch; ++c) {
        const int s = c & 1;
        if (c + 1 < nch) {
            load_stage(s ^ 1, (c + 1) * BKC);
            cpa_commit();
            cpa_wait<1>();
        } else {
            cpa_wait<0>();
        }
        __syncthreads();

        const unsigned uAh = smu + s * STGB;
        const unsigned uAl = uAh + SEG;
        const unsigned uBh = uAh + 2 * SEG;
        const unsigned uBl = uAh + 3 * SEG;

        #pragma unroll
        for (int kk = 0; kk < 2; kk++) {
            unsigned ah[4][4], al[4][4];
            #pragma unroll
            for (int mi = 0; mi < 4; mi++) {
                unsigned rowoff =
                    (unsigned)(((warpM * 64 + mi * 16 + (lane & 15)) * ASTR
                                + (lane >> 4) * 8 + kk * 16) * 2);
                ldm_x4(ah[mi], uAh + rowoff);
                ldm_x4(al[mi], uAl + rowoff);
            }
            #pragma unroll
            for (int ni = 0; ni < 4; ni++) {
                unsigned boff =
                    (unsigned)(((warpN * 32 + ni * 8 + (lane & 7)) * ASTR
                                + (((lane >> 3) & 1)) * 8 + kk * 16) * 2);
                unsigned bh[2], bl[2];
                ldm_x2(bh, uBh + boff);
                ldm_x2(bl, uBl + boff);
                #pragma unroll
                for (int mi = 0; mi < 4; mi++) {
                    mma_bf16(acc[mi][ni], ah[mi], bh);
                    mma_bf16(acc[mi][ni], ah[mi], bl);
                    mma_bf16(acc[mi][ni], al[mi], bh);
                }
            }
        }
        __syncthreads();
    }

    // epilogue
    #pragma unroll
    for (int mi = 0; mi < 4; mi++) {
        #pragma unroll
        for (int half = 0; half < 2; half++) {
            const int row = brow + warpM * 64 + mi * 16 + (lane >> 2) + half * 8;
            #pragma unroll
            for (int ni = 0; ni < 4; ni++) {
                const int col = bcol + warpN * 32 + ni * 8 + (lane & 3) * 2;
                float2 o;
                o.x = acc[mi][ni][half * 2 + 0] + bias[col + 0];
                o.y = acc[mi][ni][half * 2 + 1] + bias[col + 1];
                if (RELU) { o.x = fmaxf(o.x, 0.f); o.y = fmaxf(o.y, 0.f); }
                if (HASRES) {
                    float2 r = *(const float2*)(res + (long)row * N + col);
                    o.x += r.x; o.y += r.y;
                }
                if (MODE == 0) {
                    *(float2*)(Cf + (long)row * N + col) = o;
                } else if (MODE == 1) {
                    __nv_bfloat162 h2, l2;
                    split2(o.x, o.y, h2, l2);
                    *(__nv_bfloat162*)(Ch + (long)row * N + col) = h2;
                    *(__nv_bfloat162*)(Cl + (long)row * N + col) = l2;
                } else {  // MODE 2: QKV head-major
                    int kind = (col >= 2 * DM) ? 2 : ((col >= DM) ? 1 : 0);
                    int cm   = col - kind * DM;
                    if (kind == 0) { o.x *= 0.125f; o.y *= 0.125f; }
                    int hh = cm >> 6, dd = cm & 63;
                    long off = ((long)hh * TSEQ + row) * DKH + dd;
                    __nv_bfloat162 h2, l2;
                    split2(o.x, o.y, h2, l2);
                    if (kind == 0) {
                        *(__nv_bfloat162*)(g_qbh + off) = h2;
                        *(__nv_bfloat162*)(g_qbl + off) = l2;
                    } else if (kind == 1) {
                        *(__nv_bfloat162*)(g_kbh + off) = h2;
                        *(__nv_bfloat162*)(g_kbl + off) = l2;
                    } else {
                        *(__nv_bfloat162*)(g_vbh + off) = h2;
                        *(__nv_bfloat162*)(g_vbl + off) = l2;
                    }
                }
            }
        }
    }
}

// ============================================================
// Tensor-core flash attention, causal, bf16 hi/lo (x3 passes)
// Outputs bf16 hi/lo row-major [T][768].
// ============================================================
#define Q_BYTES (128 * 144)
#define KV_ARR  (64 * 144)
#define KV_STG  (4 * KV_ARR)
#define SM_KV   (2 * Q_BYTES)
#define AT_SMEM (SM_KV + 2 * KV_STG)

__global__ __launch_bounds__(256)
void attn_tc(const __nv_bfloat16* __restrict__ Qh, const __nv_bfloat16* __restrict__ Ql,
             const __nv_bfloat16* __restrict__ Kh, const __nv_bfloat16* __restrict__ Kl,
             const __nv_bfloat16* __restrict__ Vh, const __nv_bfloat16* __restrict__ Vl,
             __nv_bfloat16* __restrict__ Oh, __nv_bfloat16* __restrict__ Ol)
{
    extern __shared__ __align__(16) char sm[];
    const unsigned smu = s2u(sm);
    const int tid  = threadIdx.x;
    const int lane = tid & 31;
    const int wq   = tid >> 5;
    const int qb   = (int)gridDim.x - 1 - (int)blockIdx.x;
    const int h    = blockIdx.y;
    const long hb  = (long)h * TSEQ * DKH;

    {
        const char* sh = (const char*)(Qh + hb + (long)qb * 128 * DKH);
        const char* sl = (const char*)(Ql + hb + (long)qb * 128 * DKH);
        #pragma unroll
        for (int it = 0; it < 4; it++) {
            int idx = tid + it * 256;
            int row = idx >> 3, ch = idx & 7;
            cpa16ca(smu + row * 144 + ch * 16,           sh + row * 128 + ch * 16);
            cpa16ca(smu + Q_BYTES + row * 144 + ch * 16, sl + row * 128 + ch * 16);
        }
    }
    const char* kvsrc[4] = { (const char*)(Kh + hb), (const char*)(Kl + hb),
                             (const char*)(Vh + hb), (const char*)(Vl + hb) };
    {
        #pragma unroll
        for (int it = 0; it < 8; it++) {
            int idx = tid + it * 256;
            int arr = idx >> 9, rem = idx & 511;
            int row = rem >> 3, ch = rem & 7;
            cpa16ca(smu + SM_KV + arr * KV_ARR + row * 144 + ch * 16,
                    kvsrc[arr] + (long)row * 128 + ch * 16);
        }
    }
    cpa_commit();
    cpa_wait<0>();
    __syncthreads();

    unsigned qfh[4][4], qfl[4][4];
    #pragma unroll
    for (int kt = 0; kt < 4; kt++) {
        unsigned a = smu + (wq * 16 + (lane & 15)) * 144
                   + ((lane >> 4) * 8 + kt * 16) * 2;
        ldm_x4(qfh[kt], a);
        ldm_x4(qfl[kt], a + Q_BYTES);
    }

    float o_[8][4];
    #pragma unroll
    for (int i = 0; i < 8; i++)
        #pragma unroll
        for (int j = 0; j < 4; j++) o_[i][j] = 0.f;
    float m0 = -1e30f, m1 = -1e30f, l0 = 0.f, l1 = 0.f;

    const int nkb    = (qb + 1) * 2;
    const int diagKb = (qb * 128 + wq * 16) >> 6;
    const int r0g    = qb * 128 + wq * 16 + (lane >> 2);

    for (int kb = 0; kb < nkb; kb++) {
        const int s = kb & 1;

        if (kb + 1 < nkb) {
            const long kb0 = (long)(kb + 1) * 64;
            #pragma unroll
            for (int it = 0; it < 8; it++) {
                int idx = tid + it * 256;
                int arr = idx >> 9, rem = idx & 511;
                int row = rem >> 3, ch = rem & 7;
                cpa16ca(smu + SM_KV + (s ^ 1) * KV_STG + arr * KV_ARR + row * 144 + ch * 16,
                        kvsrc[arr] + (kb0 + row) * 128 + ch * 16);
            }
        }
        cpa_commit();

        float sc[8][4];
        #pragma unroll
        for (int i = 0; i < 8; i++)
            #pragma unroll
            for (int j = 0; j < 4; j++) sc[i][j] = 0.f;

        const unsigned kbase = smu + SM_KV + s * KV_STG;
        #pragma unroll
        for (int kt = 0; kt < 4; kt++) {
            #pragma unroll
            for (int nt = 0; nt < 8; nt++) {
                unsigned ka = kbase + (nt * 8 + (lane & 7)) * 144
                            + (((lane >> 3) & 1) * 8 + kt * 16) * 2;
                unsigned bh[2], bl[2];
                ldm_x2(bh, ka);
                ldm_x2(bl, ka + KV_ARR);
                mma_bf16(sc[nt], qfh[kt], bh);
                mma_bf16(sc[nt], qfh[kt], bl);
                mma_bf16(sc[nt], qfl[kt], bh);
            }
        }

        if (kb >= diagKb) {
            #pragma unroll
            for (int nt = 0; nt < 8; nt++) {
                int keyb = kb * 64 + nt * 8 + (lane & 3) * 2;
                #pragma unroll
                for (int c = 0; c < 4; c++) {
                    int key = keyb + (c & 1);
                    int row = r0g + (c >> 1) * 8;
                    if (key > row) sc[nt][c] = -1e30f;
                }
            }
        }

        float pm0 = -1e30f, pm1 = -1e30f;
        #pragma unroll
        for (int nt = 0; nt < 8; nt++) {
            pm0 = fmaxf(pm0, fmaxf(sc[nt][0], sc[nt][1]));
            pm1 = fmaxf(pm1, fmaxf(sc[nt][2], sc[nt][3]));
        }
        pm0 = fmaxf(pm0, __shfl_xor_sync(0xffffffffu, pm0, 1));
        pm0 = fmaxf(pm0, __shfl_xor_sync(0xffffffffu, pm0, 2));
        pm1 = fmaxf(pm1, __shfl_xor_sync(0xffffffffu, pm1, 1));
        pm1 = fmaxf(pm1, __shfl_xor_sync(0xffffffffu, pm1, 2));

        float mn0 = fmaxf(m0, pm0), mn1 = fmaxf(m1, pm1);
        float a0 = __expf(m0 - mn0), a1 = __expf(m1 - mn1);
        m0 = mn0; m1 = mn1;

        float rs0 = 0.f, rs1 = 0.f;
        #pragma unroll
        for (int nt = 0; nt < 8; nt++) {
            sc[nt][0] = __expf(sc[nt][0] - mn0);
            sc[nt][1] = __expf(sc[nt][1] - mn0);
            sc[nt][2] = __expf(sc[nt][2] - mn1);
            sc[nt][3] = __expf(sc[nt][3] - mn1);
            rs0 += sc[nt][0] + sc[nt][1];
            rs1 += sc[nt][2] + sc[nt][3];
        }
        rs0 += __shfl_xor_sync(0xffffffffu, rs0, 1);
        rs0 += __shfl_xor_sync(0xffffffffu, rs0, 2);
        rs1 += __shfl_xor_sync(0xffffffffu, rs1, 1);
        rs1 += __shfl_xor_sync(0xffffffffu, rs1, 2);
        l0 = l0 * a0 + rs0;
        l1 = l1 * a1 + rs1;

        #pragma unroll
        for (int dt = 0; dt < 8; dt++) {
            o_[dt][0] *= a0; o_[dt][1] *= a0;
            o_[dt][2] *= a1; o_[dt][3] *= a1;
        }

        unsigned pfh[4][4], pfl[4][4];
        #pragma unroll
        for (int kt = 0; kt < 4; kt++) {
            #pragma unroll
            for (int half = 0; half < 2; half++) {
                const float* v0 = sc[kt * 2 + half];
                __nv_bfloat162 h01, l01, h23, l23;
                split2(v0[0], v0[1], h01, l01);
                split2(v0[2], v0[3], h23, l23);
                pfh[kt][half * 2 + 0] = *(unsigned*)&h01;
                pfh[kt][half * 2 + 1] = *(unsigned*)&h23;
                pfl[kt][half * 2 + 0] = *(unsigned*)&l01;
                pfl[kt][half * 2 + 1] = *(unsigned*)&l23;
            }
        }

        const unsigned vbase = kbase + 2 * KV_ARR;
        #pragma unroll
        for (int kt = 0; kt < 4; kt++) {
            #pragma unroll
            for (int nt = 0; nt < 8; nt++) {
                unsigned va = vbase + (kt * 16 + (lane & 15)) * 144 + nt * 16;
                unsigned bh[2], bl[2];
                ldm_x2t(bh, va);
                ldm_x2t(bl, va + KV_ARR);
                mma_bf16(o_[nt], pfh[kt], bh);
                mma_bf16(o_[nt], pfh[kt], bl);
                mma_bf16(o_[nt], pfl[kt], bh);
            }
        }

        cpa_wait<0>();
        __syncthreads();
    }

    // write bf16 hi/lo O
    const float i0 = 1.f / l0, i1 = 1.f / l1;
    #pragma unroll
    for (int nt = 0; nt < 8; nt++) {
        int col = h * DKH + nt * 8 + (lane & 3) * 2;
        __nv_bfloat162 h2, l2;
        split2(o_[nt][0] * i0, o_[nt][1] * i0, h2, l2);
        *(__nv_bfloat162*)(Oh + (long)r0g * DM + col) = h2;
        *(__nv_bfloat162*)(Ol + (long)r0g * DM + col) = l2;
        split2(o_[nt][2] * i1, o_[nt][3] * i1, h2, l2);
        *(__nv_bfloat162*)(Oh + (long)(r0g + 8) * DM + col) = h2;
        *(__nv_bfloat162*)(Ol + (long)(r0g + 8) * DM + col) = l2;
    }
}

// ============================================================
// LayerNorm; optional bf16 hi/lo side outputs
// ============================================================
__global__ __launch_bounds__(256) void ln_kernel(
    const float* __restrict__ X, const float* __restrict__ g,
    const float* __restrict__ b, float* __restrict__ Y,
    __nv_bfloat16* __restrict__ Yh, __nv_bfloat16* __restrict__ Yl)
{
    const int r   = blockIdx.x;
    const int tid = threadIdx.x;
    const float* x = X + (long)r * DM;

    float v[3];
    float s = 0.f, ss = 0.f;
    #pragma unroll
    for (int i = 0; i < 3; i++) {
        v[i] = x[tid + i * 256];
        s  += v[i];
        ss += v[i] * v[i];
    }
    #pragma unroll
    for (int off = 16; off > 0; off >>= 1) {
        s  += __shfl_xor_sync(0xffffffffu, s,  off);
        ss += __shfl_xor_sync(0xffffffffu, ss, off);
    }
    __shared__ float rs_[8], rss_[8];
    const int lane = tid & 31, wid = tid >> 5;
    if (lane == 0) { rs_[wid] = s; rss_[wid] = ss; }
    __syncthreads();
    float ts = 0.f, tss = 0.f;
    #pragma unroll
    for (int w = 0; w < 8; w++) { ts += rs_[w]; tss += rss_[w]; }

    const float mean = ts * (1.f / 768.f);
    const float var  = tss * (1.f / 768.f) - mean * mean;
    const float rstd = rsqrtf(var + 1e-5f);

    #pragma unroll
    for (int i = 0; i < 3; i++) {
        int c = tid + i * 256;
        float yv = (v[i] - mean) * rstd * g[c] + b[c];
        Y[(long)r * DM + c] = yv;
        if (Yh) {
            __nv_bfloat16 hh = __float2bfloat16_rn(yv);
            __nv_bfloat16 ll = __float2bfloat16_rn(yv - __bfloat162float(hh));
            Yh[(long)r * DM + c] = hh;
            Yl[(long)r * DM + c] = ll;
        }
    }
}

// ============================================================
extern "C" void kernel_launch(void* const* d_in, const int* in_sizes, int n_in,
                              void* d_out, int out_size)
{
    const float* x   = (const float*)d_in[0];
    const float* Wq  = (const float*)d_in[1];
    const float* bq  = (const float*)d_in[2];
    const float* Wk  = (const float*)d_in[3];
    const float* bk  = (const float*)d_in[4];
    const float* Wv  = (const float*)d_in[5];
    const float* bv  = (const float*)d_in[6];
    const float* Wo  = (const float*)d_in[7];
    const float* bo  = (const float*)d_in[8];
    const float* W1  = (const float*)d_in[9];
    const float* b1  = (const float*)d_in[10];
    const float* W2  = (const float*)d_in[11];
    const float* b2  = (const float*)d_in[12];
    const float* g1  = (const float*)d_in[13];
    const float* be1 = (const float*)d_in[14];
    const float* g2  = (const float*)d_in[15];
    const float* be2 = (const float*)d_in[16];
    float* out = (float*)d_out;

    float *y1, *hbuf, *y2, *bqkv;
    cudaGetSymbolAddress((void**)&y1,   g_y1);
    cudaGetSymbolAddress((void**)&hbuf, g_h);
    cudaGetSymbolAddress((void**)&y2,   g_y2);
    cudaGetSymbolAddress((void**)&bqkv, g_bqkv);

    __nv_bfloat16 *xh, *xl, *abh, *abl, *hh, *hl, *f1h, *f1l;
    cudaGetSymbolAddress((void**)&xh,  g_xh);  cudaGetSymbolAddress((void**)&xl,  g_xl);
    cudaGetSymbolAddress((void**)&abh, g_abh); cudaGetSymbolAddress((void**)&abl, g_abl);
    cudaGetSymbolAddress((void**)&hh,  g_hh);  cudaGetSymbolAddress((void**)&hl,  g_hl);
    cudaGetSymbolAddress((void**)&f1h, g_f1h); cudaGetSymbolAddress((void**)&f1l, g_f1l);

    __nv_bfloat16 *wqkvh, *wqkvl, *woh, *wol, *w1h, *w1l, *w2h, *w2l;
    cudaGetSymbolAddress((void**)&wqkvh, g_wqkvh); cudaGetSymbolAddress((void**)&wqkvl, g_wqkvl);
    cudaGetSymbolAddress((void**)&woh, g_woh); cudaGetSymbolAddress((void**)&wol, g_wol);
    cudaGetSymbolAddress((void**)&w1h, g_w1h); cudaGetSymbolAddress((void**)&w1l, g_w1l);
    cudaGetSymbolAddress((void**)&w2h, g_w2h); cudaGetSymbolAddress((void**)&w2l, g_w2l);

    __nv_bfloat16 *qbh, *qbl, *kbh, *kbl, *vbh, *vbl;
    cudaGetSymbolAddress((void**)&qbh, g_qbh); cudaGetSymbolAddress((void**)&qbl, g_qbl);
    cudaGetSymbolAddress((void**)&kbh, g_kbh); cudaGetSymbolAddress((void**)&kbl, g_kbl);
    cudaGetSymbolAddress((void**)&vbh, g_vbh); cudaGetSymbolAddress((void**)&vbl, g_vbl);

    cudaFuncSetAttribute(gemm_bfp<2, false, false>,
                         cudaFuncAttributeMaxDynamicSharedMemorySize, GSMEM);
    cudaFuncSetAttribute(gemm_bfp<0, false, true>,
                         cudaFuncAttributeMaxDynamicSharedMemorySize, GSMEM);
    cudaFuncSetAttribute(gemm_bfp<1, true, false>,
                         cudaFuncAttributeMaxDynamicSharedMemorySize, GSMEM);
    cudaFuncSetAttribute(attn_tc, cudaFuncAttributeMaxDynamicSharedMemorySize, AT_SMEM);

    dim3 tblk(32, 8);
    dim3 blk(256);

    // weight prep
    wsplit4<<<dim3(24, 24, 4), tblk>>>(Wq, Wk, Wv, Wo, wqkvh, wqkvl, woh, wol);
    wsplit_t<<<dim3(DFF / 32, DM  / 32), tblk>>>(W1, w1h, w1l, DM,  DFF);
    wsplit_t<<<dim3(DM  / 32, DFF / 32), tblk>>>(W2, w2h, w2l, DFF, DM);
    cudaMemcpyAsync(bqkv,            bq, DM * 4, cudaMemcpyDeviceToDevice);
    cudaMemcpyAsync(bqkv + DM,       bk, DM * 4, cudaMemcpyDeviceToDevice);
    cudaMemcpyAsync(bqkv + 2 * DM,   bv, DM * 4, cudaMemcpyDeviceToDevice);

    // x -> bf16 hi/lo
    fsplit<<<TSEQ * DM / 1024, blk>>>(x, xh, xl);

    // fused QKV projection -> head-major bf16 hi/lo (Q pre-scaled)
    gemm_bfp<2, false, false><<<dim3(18, 32), blk, GSMEM>>>(
        xh, xl, wqkvh, wqkvl, bqkv, nullptr, nullptr, nullptr, nullptr, DM, 3 * DM);

    // attention -> bf16 hi/lo
    attn_tc<<<dim3(TSEQ / 128, NH), blk, AT_SMEM>>>(qbh, qbl, kbh, kbl, vbh, vbl, abh, abl);

    // output projection + residual(x)
    gemm_bfp<0, false, true><<<dim3(6, 32), blk, GSMEM>>>(
        abh, abl, woh, wol, bo, x, y1, nullptr, nullptr, DM, DM);

    ln_kernel<<<TSEQ, blk>>>(y1, g1, be1, hbuf, hh, hl);

    // FFN
    gemm_bfp<1, true, false><<<dim3(24, 32), blk, GSMEM>>>(
        hh, hl, w1h, w1l, b1, nullptr, nullptr, f1h, f1l, DM, DFF);
    gemm_bfp<0, false, true><<<dim3(6, 32), blk, GSMEM>>>(
        f1h, f1l, w2h, w2l, b2, hbuf, y2, nullptr, nullptr, DFF, DM);

    ln_kernel<<<TSEQ, blk>>>(y2, g2, be2, out, nullptr, nullptr);
}

// round 7
// speedup vs baseline: 3.8883x; 1.2918x over previous
#include <cuda_runtime.h>
#include <cuda_fp16.h>

#define TSEQ 4096
#define DM   768
#define NH   12
#define DKH  64
#define DFF  3072

// ---- fp32 scratch ----
__device__ float g_y1  [TSEQ * DM];
__device__ float g_h   [TSEQ * DM];
__device__ float g_y2  [TSEQ * DM];
__device__ float g_bqkv[3 * DM];

// ---- fp16 hi/lo pre-split activations ----
__device__ __half g_xh [TSEQ * DM],  g_xl [TSEQ * DM];
__device__ __half g_abh[TSEQ * DM],  g_abl[TSEQ * DM];
__device__ __half g_hh [TSEQ * DM],  g_hl [TSEQ * DM];
__device__ __half g_f1h[TSEQ * DFF], g_f1l[TSEQ * DFF];

// ---- fp16 transposed weights [N, K] (single precision copy) ----
__device__ __half g_wqkv[3 * DM * DM];
__device__ __half g_wo  [DM * DM];
__device__ __half g_w1  [DM * DFF];
__device__ __half g_w2  [DM * DFF];

// ---- fp16 QKV, head-major [NH][TSEQ][64] ----
__device__ __half g_qs [NH * TSEQ * DKH];                      // Q single (scaled)
__device__ __half g_kbh[NH * TSEQ * DKH], g_kbl[NH * TSEQ * DKH];
__device__ __half g_vbh[NH * TSEQ * DKH], g_vbl[NH * TSEQ * DKH];

// ============================================================
// helpers (sm_80+ baseline: valid on plain sm_103)
// ============================================================
__device__ __forceinline__ unsigned s2u(const void* p) {
    unsigned a;
    asm("{ .reg .u64 t; cvta.to.shared.u64 t, %1; cvt.u32.u64 %0, t; }"
        : "=r"(a) : "l"(p));
    return a;
}
__device__ __forceinline__ void ldm_x4(unsigned* r, unsigned addr) {
    asm volatile("ldmatrix.sync.aligned.m8n8.x4.shared.b16 {%0,%1,%2,%3}, [%4];"
                 : "=r"(r[0]), "=r"(r[1]), "=r"(r[2]), "=r"(r[3]) : "r"(addr));
}
__device__ __forceinline__ void ldm_x2(unsigned* r, unsigned addr) {
    asm volatile("ldmatrix.sync.aligned.m8n8.x2.shared.b16 {%0,%1}, [%2];"
                 : "=r"(r[0]), "=r"(r[1]) : "r"(addr));
}
__device__ __forceinline__ void ldm_x2t(unsigned* r, unsigned addr) {
    asm volatile("ldmatrix.sync.aligned.m8n8.x2.trans.shared.b16 {%0,%1}, [%2];"
                 : "=r"(r[0]), "=r"(r[1]) : "r"(addr));
}
__device__ __forceinline__ void mma_f16(float* c, const unsigned* a, const unsigned* b) {
    asm volatile("mma.sync.aligned.m16n8k16.row.col.f32.f16.f16.f32 "
                 "{%0,%1,%2,%3}, {%4,%5,%6,%7}, {%8,%9}, {%0,%1,%2,%3};"
                 : "+f"(c[0]), "+f"(c[1]), "+f"(c[2]), "+f"(c[3])
                 : "r"(a[0]), "r"(a[1]), "r"(a[2]), "r"(a[3]), "r"(b[0]), "r"(b[1]));
}
__device__ __forceinline__ void cpa16(unsigned dst, const void* src) {
    asm volatile("cp.async.cg.shared.global [%0], [%1], 16;" :: "r"(dst), "l"(src));
}
__device__ __forceinline__ void cpa16ca(unsigned dst, const void* src) {
    asm volatile("cp.async.ca.shared.global [%0], [%1], 16;" :: "r"(dst), "l"(src));
}
__device__ __forceinline__ void cpa_commit() {
    asm volatile("cp.async.commit_group;" ::: "memory");
}
template<int N> __device__ __forceinline__ void cpa_wait() {
    asm volatile("cp.async.wait_group %0;" :: "n"(N) : "memory");
}
// fp32x2 -> fp16 hi/lo pair
__device__ __forceinline__ void splitH2(float x, float y, __half2& h, __half2& l) {
    h = __floats2half2_rn(x, y);
    float2 f = __half22float2(h);
    l = __floats2half2_rn(x - f.x, y - f.y);
}

// ============================================================
// Weight transpose + fp16 convert: W[K,N] -> T[N,K]
// ============================================================
__device__ __forceinline__ void wconv_body(
    const float* __restrict__ W, __half* __restrict__ T,
    int K, int N, int n0, int k0, float t[32][33])
{
    const int tx = threadIdx.x, ty = threadIdx.y;
    #pragma unroll
    for (int i = 0; i < 4; i++)
        t[ty + i * 8][tx] = W[(long)(k0 + ty + i * 8) * N + n0 + tx];
    __syncthreads();
    #pragma unroll
    for (int i = 0; i < 4; i++) {
        int n = n0 + ty + i * 8;
        T[(long)n * K + k0 + tx] = __float2half_rn(t[tx][ty + i * 8]);
    }
}
__global__ __launch_bounds__(256) void wconv_t(
    const float* __restrict__ W, __half* __restrict__ T, int K, int N)
{
    __shared__ float t[32][33];
    wconv_body(W, T, K, N, blockIdx.x * 32, blockIdx.y * 32, t);
}
__global__ __launch_bounds__(256) void wconv4(
    const float* __restrict__ W0, const float* __restrict__ W1,
    const float* __restrict__ W2, const float* __restrict__ W3,
    __half* __restrict__ qkv, __half* __restrict__ wo)
{
    __shared__ float t[32][33];
    const int z = blockIdx.z;
    const float* W = (z == 0) ? W0 : (z == 1) ? W1 : (z == 2) ? W2 : W3;
    __half* T = (z < 3) ? (qkv + (long)z * DM * DM) : wo;
    wconv_body(W, T, DM, DM, blockIdx.x * 32, blockIdx.y * 32, t);
}

// ============================================================
// fp32 -> fp16 hi/lo elementwise
// ============================================================
__global__ __launch_bounds__(256) void fsplit(
    const float* __restrict__ X, __half* __restrict__ H, __half* __restrict__ L)
{
    long idx = ((long)blockIdx.x * 256 + threadIdx.x) * 4;
    float4 v = *(const float4*)(X + idx);
    __half2 h01, l01, h23, l23;
    splitH2(v.x, v.y, h01, l01);
    splitH2(v.z, v.w, h23, l23);
    *(__half2*)(H + idx)     = h01;
    *(__half2*)(H + idx + 2) = h23;
    *(__half2*)(L + idx)     = l01;
    *(__half2*)(L + idx + 2) = l23;
}

// ============================================================
// fp16 x2 GEMM: C[M,N] = (Ah+Al)[M,K] @ B^T[N,K] (+bias)
// A hi/lo fp16, B single fp16. cp.async double-buffered.
// MODE 0: fp32 out (+res). MODE 1: fp16 hi/lo out (+relu).
// MODE 2: QKV out (Q single scaled, K/V hi/lo, head-major).
// ============================================================
#define BKC   32
#define ASTR  40
#define SEG   10240                 // 128 rows * 80 B
#define STGB  (3 * SEG)             // 30720 per stage
#define GSMEM (2 * STGB)            // 61440

template<int MODE, bool RELU, bool HASRES>
__global__ __launch_bounds__(256, 2)
void gemm_h2(const __half* __restrict__ Ah, const __half* __restrict__ Al,
             const __half* __restrict__ B,
             const float* __restrict__ bias, const float* __restrict__ res,
             float* __restrict__ Cf, __half* __restrict__ Ch,
             __half* __restrict__ Cl, int K, int N)
{
    extern __shared__ __align__(128) char smem[];
    const int tid   = threadIdx.x;
    const int wid   = tid >> 5;
    const int lane  = tid & 31;
    const int warpM = wid & 1;
    const int warpN = wid >> 1;
    const int brow  = blockIdx.y * 128;
    const int bcol  = blockIdx.x * 128;
    const unsigned smu = s2u(smem);

    const char* src[3] = { (const char*)Ah, (const char*)Al, (const char*)B };

    float acc[4][4][4];
    #pragma unroll
    for (int mi = 0; mi < 4; mi++)
        #pragma unroll
        for (int ni = 0; ni < 4; ni++)
            #pragma unroll
            for (int r = 0; r < 4; r++) acc[mi][ni][r] = 0.f;

    const int nch = K / BKC;

    // stage loader: 1536 cp.async16 over 256 threads = 6 each
    auto load_stage = [&](int s, int kc) {
        #pragma unroll
        for (int it = 0; it < 6; it++) {
            int idx = tid + it * 256;
            int arr = idx >> 9, rem = idx & 511;
            int row = rem >> 2, ch = rem & 3;
            int base_row = (arr < 2) ? (brow + row) : (bcol + row);
            cpa16(smu + s * STGB + arr * SEG + row * 80 + ch * 16,
                  src[arr] + ((long)base_row * K + kc) * 2 + ch * 16);
        }
    };

    load_stage(0, 0);
    cpa_commit();

    for (int c = 0; c < nch; ++c) {
        const int s = c & 1;
        if (c + 1 < nch) {
            load_stage(s ^ 1, (c + 1) * BKC);
            cpa_commit();
            cpa_wait<1>();
        } else {
            cpa_wait<0>();
        }
        __syncthreads();

        const unsigned uAh = smu + s * STGB;
        const unsigned uAl = uAh + SEG;
        const unsigned uB  = uAh + 2 * SEG;

        #pragma unroll
        for (int kk = 0; kk < 2; kk++) {
            unsigned ah[4][4], al[4][4];
            #pragma unroll
            for (int mi = 0; mi < 4; mi++) {
                unsigned rowoff =
                    (unsigned)(((warpM * 64 + mi * 16 + (lane & 15)) * ASTR
                                + (lane >> 4) * 8 + kk * 16) * 2);
                ldm_x4(ah[mi], uAh + rowoff);
                ldm_x4(al[mi], uAl + rowoff);
            }
            #pragma unroll
            for (int ni = 0; ni < 4; ni++) {
                unsigned boff =
                    (unsigned)(((warpN * 32 + ni * 8 + (lane & 7)) * ASTR
                                + (((lane >> 3) & 1)) * 8 + kk * 16) * 2);
                unsigned b[2];
                ldm_x2(b, uB + boff);
                #pragma unroll
                for (int mi = 0; mi < 4; mi++) {
                    mma_f16(acc[mi][ni], ah[mi], b);
                    mma_f16(acc[mi][ni], al[mi], b);
                }
            }
        }
        __syncthreads();
    }

    // epilogue
    #pragma unroll
    for (int mi = 0; mi < 4; mi++) {
        #pragma unroll
        for (int half = 0; half < 2; half++) {
            const int row = brow + warpM * 64 + mi * 16 + (lane >> 2) + half * 8;
            #pragma unroll
            for (int ni = 0; ni < 4; ni++) {
                const int col = bcol + warpN * 32 + ni * 8 + (lane & 3) * 2;
                float2 o;
                o.x = acc[mi][ni][half * 2 + 0] + bias[col + 0];
                o.y = acc[mi][ni][half * 2 + 1] + bias[col + 1];
                if (RELU) { o.x = fmaxf(o.x, 0.f); o.y = fmaxf(o.y, 0.f); }
                if (HASRES) {
                    float2 r = *(const float2*)(res + (long)row * N + col);
                    o.x += r.x; o.y += r.y;
                }
                if (MODE == 0) {
                    *(float2*)(Cf + (long)row * N + col) = o;
                } else if (MODE == 1) {
                    __half2 h2, l2;
                    splitH2(o.x, o.y, h2, l2);
                    *(__half2*)(Ch + (long)row * N + col) = h2;
                    *(__half2*)(Cl + (long)row * N + col) = l2;
                } else {  // MODE 2: QKV head-major
                    int kind = (col >= 2 * DM) ? 2 : ((col >= DM) ? 1 : 0);
                    int cm   = col - kind * DM;
                    int hh = cm >> 6, dd = cm & 63;
                    long off = ((long)hh * TSEQ + row) * DKH + dd;
                    if (kind == 0) {
                        *(__half2*)(g_qs + off) =
                            __floats2half2_rn(o.x * 0.125f, o.y * 0.125f);
                    } else {
                        __half2 h2, l2;
                        splitH2(o.x, o.y, h2, l2);
                        if (kind == 1) {
                            *(__half2*)(g_kbh + off) = h2;
                            *(__half2*)(g_kbl + off) = l2;
                        } else {
                            *(__half2*)(g_vbh + off) = h2;
                            *(__half2*)(g_vbl + off) = l2;
                        }
                    }
                }
            }
        }
    }
}

// ============================================================
// Tensor-core flash attention, causal, fp16 x2 passes.
// Q single (scaled), K hi/lo, V hi/lo. Out fp16 hi/lo.
// ============================================================
#define SM_Q    (128 * 144)            // 18432
#define KV_ARR  (64 * 144)             // 9216
#define KV_STG  (4 * KV_ARR)           // 36864
#define AT_SMEM (SM_Q + 2 * KV_STG)    // 92160

__global__ __launch_bounds__(256)
void attn_tc(const __half* __restrict__ Qs,
             const __half* __restrict__ Kh, const __half* __restrict__ Kl,
             const __half* __restrict__ Vh, const __half* __restrict__ Vl,
             __half* __restrict__ Oh, __half* __restrict__ Ol)
{
    extern __shared__ __align__(16) char sm[];
    const unsigned smu = s2u(sm);
    const int tid  = threadIdx.x;
    const int lane = tid & 31;
    const int wq   = tid >> 5;
    const int qb   = (int)gridDim.x - 1 - (int)blockIdx.x;
    const int h    = blockIdx.y;
    const long hb  = (long)h * TSEQ * DKH;

    // Q single: 128 rows x 128 B
    {
        const char* sq = (const char*)(Qs + hb + (long)qb * 128 * DKH);
        #pragma unroll
        for (int it = 0; it < 4; it++) {
            int idx = tid + it * 256;
            int row = idx >> 3, ch = idx & 7;
            cpa16ca(smu + row * 144 + ch * 16, sq + row * 128 + ch * 16);
        }
    }
    const char* kvsrc[4] = { (const char*)(Kh + hb), (const char*)(Kl + hb),
                             (const char*)(Vh + hb), (const char*)(Vl + hb) };
    {
        #pragma unroll
        for (int it = 0; it < 8; it++) {
            int idx = tid + it * 256;
            int arr = idx >> 9, rem = idx & 511;
            int row = rem >> 3, ch = rem & 7;
            cpa16ca(smu + SM_Q + arr * KV_ARR + row * 144 + ch * 16,
                    kvsrc[arr] + (long)row * 128 + ch * 16);
        }
    }
    cpa_commit();
    cpa_wait<0>();
    __syncthreads();

    unsigned qf[4][4];
    #pragma unroll
    for (int kt = 0; kt < 4; kt++) {
        unsigned a = smu + (wq * 16 + (lane & 15)) * 144
                   + ((lane >> 4) * 8 + kt * 16) * 2;
        ldm_x4(qf[kt], a);
    }

    float o_[8][4];
    #pragma unroll
    for (int i = 0; i < 8; i++)
        #pragma unroll
        for (int j = 0; j < 4; j++) o_[i][j] = 0.f;
    float m0 = -1e30f, m1 = -1e30f, l0 = 0.f, l1 = 0.f;

    const int nkb    = (qb + 1) * 2;
    const int diagKb = (qb * 128 + wq * 16) >> 6;
    const int r0g    = qb * 128 + wq * 16 + (lane >> 2);

    for (int kb = 0; kb < nkb; kb++) {
        const int s = kb & 1;

        if (kb + 1 < nkb) {
            const long kb0 = (long)(kb + 1) * 64;
            #pragma unroll
            for (int it = 0; it < 8; it++) {
                int idx = tid + it * 256;
                int arr = idx >> 9, rem = idx & 511;
                int row = rem >> 3, ch = rem & 7;
                cpa16ca(smu + SM_Q + (s ^ 1) * KV_STG + arr * KV_ARR + row * 144 + ch * 16,
                        kvsrc[arr] + (kb0 + row) * 128 + ch * 16);
            }
        }
        cpa_commit();

        float sc[8][4];
        #pragma unroll
        for (int i = 0; i < 8; i++)
            #pragma unroll
            for (int j = 0; j < 4; j++) sc[i][j] = 0.f;

        const unsigned kbase = smu + SM_Q + s * KV_STG;
        #pragma unroll
        for (int kt = 0; kt < 4; kt++) {
            #pragma unroll
            for (int nt = 0; nt < 8; nt++) {
                unsigned ka = kbase + (nt * 8 + (lane & 7)) * 144
                            + (((lane >> 3) & 1) * 8 + kt * 16) * 2;
                unsigned bh[2], bl[2];
                ldm_x2(bh, ka);
                ldm_x2(bl, ka + KV_ARR);
                mma_f16(sc[nt], qf[kt], bh);
                mma_f16(sc[nt], qf[kt], bl);
            }
        }

        if (kb >= diagKb) {
            #pragma unroll
            for (int nt = 0; nt < 8; nt++) {
                int keyb = kb * 64 + nt * 8 + (lane & 3) * 2;
                #pragma unroll
                for (int c = 0; c < 4; c++) {
                    int key = keyb + (c & 1);
                    int row = r0g + (c >> 1) * 8;
                    if (key > row) sc[nt][c] = -1e30f;
                }
            }
        }

        float pm0 = -1e30f, pm1 = -1e30f;
        #pragma unroll
        for (int nt = 0; nt < 8; nt++) {
            pm0 = fmaxf(pm0, fmaxf(sc[nt][0], sc[nt][1]));
            pm1 = fmaxf(pm1, fmaxf(sc[nt][2], sc[nt][3]));
        }
        pm0 = fmaxf(pm0, __shfl_xor_sync(0xffffffffu, pm0, 1));
        pm0 = fmaxf(pm0, __shfl_xor_sync(0xffffffffu, pm0, 2));
        pm1 = fmaxf(pm1, __shfl_xor_sync(0xffffffffu, pm1, 1));
        pm1 = fmaxf(pm1, __shfl_xor_sync(0xffffffffu, pm1, 2));

        float mn0 = fmaxf(m0, pm0), mn1 = fmaxf(m1, pm1);
        float a0 = __expf(m0 - mn0), a1 = __expf(m1 - mn1);
        m0 = mn0; m1 = mn1;

        float rs0 = 0.f, rs1 = 0.f;
        #pragma unroll
        for (int nt = 0; nt < 8; nt++) {
            sc[nt][0] = __expf(sc[nt][0] - mn0);
            sc[nt][1] = __expf(sc[nt][1] - mn0);
            sc[nt][2] = __expf(sc[nt][2] - mn1);
            sc[nt][3] = __expf(sc[nt][3] - mn1);
            rs0 += sc[nt][0] + sc[nt][1];
            rs1 += sc[nt][2] + sc[nt][3];
        }
        rs0 += __shfl_xor_sync(0xffffffffu, rs0, 1);
        rs0 += __shfl_xor_sync(0xffffffffu, rs0, 2);
        rs1 += __shfl_xor_sync(0xffffffffu, rs1, 1);
        rs1 += __shfl_xor_sync(0xffffffffu, rs1, 2);
        l0 = l0 * a0 + rs0;
        l1 = l1 * a1 + rs1;

        #pragma unroll
        for (int dt = 0; dt < 8; dt++) {
            o_[dt][0] *= a0; o_[dt][1] *= a0;
            o_[dt][2] *= a1; o_[dt][3] *= a1;
        }

        // pack P (single fp16): acc layout == A-frag layout
        unsigned pf[4][4];
        #pragma unroll
        for (int kt = 0; kt < 4; kt++) {
            #pragma unroll
            for (int half = 0; half < 2; half++) {
                const float* v0 = sc[kt * 2 + half];
                __half2 p01 = __floats2half2_rn(v0[0], v0[1]);
                __half2 p23 = __floats2half2_rn(v0[2], v0[3]);
                pf[kt][half * 2 + 0] = *(unsigned*)&p01;
                pf[kt][half * 2 + 1] = *(unsigned*)&p23;
            }
        }

        const unsigned vbase = kbase + 2 * KV_ARR;
        #pragma unroll
        for (int kt = 0; kt < 4; kt++) {
            #pragma unroll
            for (int nt = 0; nt < 8; nt++) {
                unsigned va = vbase + (kt * 16 + (lane & 15)) * 144 + nt * 16;
                unsigned bh[2], bl[2];
                ldm_x2t(bh, va);
                ldm_x2t(bl, va + KV_ARR);
                mma_f16(o_[nt], pf[kt], bh);
                mma_f16(o_[nt], pf[kt], bl);
            }
        }

        cpa_wait<0>();
        __syncthreads();
    }

    const float i0 = 1.f / l0, i1 = 1.f / l1;
    #pragma unroll
    for (int nt = 0; nt < 8; nt++) {
        int col = h * DKH + nt * 8 + (lane & 3) * 2;
        __half2 h2, l2;
        splitH2(o_[nt][0] * i0, o_[nt][1] * i0, h2, l2);
        *(__half2*)(Oh + (long)r0g * DM + col) = h2;
        *(__half2*)(Ol + (long)r0g * DM + col) = l2;
        splitH2(o_[nt][2] * i1, o_[nt][3] * i1, h2, l2);
        *(__half2*)(Oh + (long)(r0g + 8) * DM + col) = h2;
        *(__half2*)(Ol + (long)(r0g + 8) * DM + col) = l2;
    }
}

// ============================================================
// LayerNorm; optional fp16 hi/lo side outputs
// ============================================================
__global__ __launch_bounds__(256) void ln_kernel(
    const float* __restrict__ X, const float* __restrict__ g,
    const float* __restrict__ b, float* __restrict__ Y,
    __half* __restrict__ Yh, __half* __restrict__ Yl)
{
    const int r   = blockIdx.x;
    const int tid = threadIdx.x;
    const float* x = X + (long)r * DM;

    float v[3];
    float s = 0.f, ss = 0.f;
    #pragma unroll
    for (int i = 0; i < 3; i++) {
        v[i] = x[tid + i * 256];
        s  += v[i];
        ss += v[i] * v[i];
    }
    #pragma unroll
    for (int off = 16; off > 0; off >>= 1) {
        s  += __shfl_xor_sync(0xffffffffu, s,  off);
        ss += __shfl_xor_sync(0xffffffffu, ss, off);
    }
    __shared__ float rs_[8], rss_[8];
    const int lane = tid & 31, wid = tid >> 5;
    if (lane == 0) { rs_[wid] = s; rss_[wid] = ss; }
    __syncthreads();
    float ts = 0.f, tss = 0.f;
    #pragma unroll
    for (int w = 0; w < 8; w++) { ts += rs_[w]; tss += rss_[w]; }

    const float mean = ts * (1.f / 768.f);
    const float var  = tss * (1.f / 768.f) - mean * mean;
    const float rstd = rsqrtf(var + 1e-5f);

    #pragma unroll
    for (int i = 0; i < 3; i++) {
        int c = tid + i * 256;
        float yv = (v[i] - mean) * rstd * g[c] + b[c];
        Y[(long)r * DM + c] = yv;
        if (Yh) {
            __half hh = __float2half_rn(yv);
            Yh[(long)r * DM + c] = hh;
            Yl[(long)r * DM + c] = __float2half_rn(yv - __half2float(hh));
        }
    }
}

// ============================================================
extern "C" void kernel_launch(void* const* d_in, const int* in_sizes, int n_in,
                              void* d_out, int out_size)
{
    const float* x   = (const float*)d_in[0];
    const float* Wq  = (const float*)d_in[1];
    const float* bq  = (const float*)d_in[2];
    const float* Wk  = (const float*)d_in[3];
    const float* bk  = (const float*)d_in[4];
    const float* Wv  = (const float*)d_in[5];
    const float* bv  = (const float*)d_in[6];
    const float* Wo  = (const float*)d_in[7];
    const float* bo  = (const float*)d_in[8];
    const float* W1  = (const float*)d_in[9];
    const float* b1  = (const float*)d_in[10];
    const float* W2  = (const float*)d_in[11];
    const float* b2  = (const float*)d_in[12];
    const float* g1  = (const float*)d_in[13];
    const float* be1 = (const float*)d_in[14];
    const float* g2  = (const float*)d_in[15];
    const float* be2 = (const float*)d_in[16];
    float* out = (float*)d_out;

    float *y1, *hbuf, *y2, *bqkv;
    cudaGetSymbolAddress((void**)&y1,   g_y1);
    cudaGetSymbolAddress((void**)&hbuf, g_h);
    cudaGetSymbolAddress((void**)&y2,   g_y2);
    cudaGetSymbolAddress((void**)&bqkv, g_bqkv);

    __half *xh, *xl, *abh, *abl, *hh, *hl, *f1h, *f1l;
    cudaGetSymbolAddress((void**)&xh,  g_xh);  cudaGetSymbolAddress((void**)&xl,  g_xl);
    cudaGetSymbolAddress((void**)&abh, g_abh); cudaGetSymbolAddress((void**)&abl, g_abl);
    cudaGetSymbolAddress((void**)&hh,  g_hh);  cudaGetSymbolAddress((void**)&hl,  g_hl);
    cudaGetSymbolAddress((void**)&f1h, g_f1h); cudaGetSymbolAddress((void**)&f1l, g_f1l);

    __half *wqkv, *wo, *w1, *w2;
    cudaGetSymbolAddress((void**)&wqkv, g_wqkv);
    cudaGetSymbolAddress((void**)&wo, g_wo);
    cudaGetSymbolAddress((void**)&w1, g_w1);
    cudaGetSymbolAddress((void**)&w2, g_w2);

    __half *qs, *kbh, *kbl, *vbh, *vbl;
    cudaGetSymbolAddress((void**)&qs,  g_qs);
    cudaGetSymbolAddress((void**)&kbh, g_kbh); cudaGetSymbolAddress((void**)&kbl, g_kbl);
    cudaGetSymbolAddress((void**)&vbh, g_vbh); cudaGetSymbolAddress((void**)&vbl, g_vbl);

    cudaFuncSetAttribute(gemm_h2<2, false, false>,
                         cudaFuncAttributeMaxDynamicSharedMemorySize, GSMEM);
    cudaFuncSetAttribute(gemm_h2<0, false, true>,
                         cudaFuncAttributeMaxDynamicSharedMemorySize, GSMEM);
    cudaFuncSetAttribute(gemm_h2<1, true, false>,
                         cudaFuncAttributeMaxDynamicSharedMemorySize, GSMEM);
    cudaFuncSetAttribute(attn_tc, cudaFuncAttributeMaxDynamicSharedMemorySize, AT_SMEM);

    dim3 tblk(32, 8);
    dim3 blk(256);

    // weight prep (fp16 single) + bias concat
    wconv4<<<dim3(24, 24, 4), tblk>>>(Wq, Wk, Wv, Wo, wqkv, wo);
    wconv_t<<<dim3(DFF / 32, DM  / 32), tblk>>>(W1, w1, DM,  DFF);
    wconv_t<<<dim3(DM  / 32, DFF / 32), tblk>>>(W2, w2, DFF, DM);
    cudaMemcpyAsync(bqkv,          bq, DM * 4, cudaMemcpyDeviceToDevice);
    cudaMemcpyAsync(bqkv + DM,     bk, DM * 4, cudaMemcpyDeviceToDevice);
    cudaMemcpyAsync(bqkv + 2 * DM, bv, DM * 4, cudaMemcpyDeviceToDevice);

    // x -> fp16 hi/lo
    fsplit<<<TSEQ * DM / 1024, blk>>>(x, xh, xl);

    // fused QKV projection -> head-major fp16 (Q scaled single, K/V hi/lo)
    gemm_h2<2, false, false><<<dim3(18, 32), blk, GSMEM>>>(
        xh, xl, wqkv, bqkv, nullptr, nullptr, nullptr, nullptr, DM, 3 * DM);

    // attention -> fp16 hi/lo
    attn_tc<<<dim3(TSEQ / 128, NH), blk, AT_SMEM>>>(qs, kbh, kbl, vbh, vbl, abh, abl);

    // output projection + residual(x)
    gemm_h2<0, false, true><<<dim3(6, 32), blk, GSMEM>>>(
        abh, abl, wo, bo, x, y1, nullptr, nullptr, DM, DM);

    ln_kernel<<<TSEQ, blk>>>(y1, g1, be1, hbuf, hh, hl);

    // FFN
    gemm_h2<1, true, false><<<dim3(24, 32), blk, GSMEM>>>(
        hh, hl, w1, b1, nullptr, nullptr, f1h, f1l, DM, DFF);
    gemm_h2<0, false, true><<<dim3(6, 32), blk, GSMEM>>>(
        f1h, f1l, w2, b2, hbuf, y2, nullptr, nullptr, DFF, DM);

    ln_kernel<<<TSEQ, blk>>>(y2, g2, be2, out, nullptr, nullptr);
}

// round 8
// speedup vs baseline: 6.4197x; 1.6510x over previous
#include <cuda_runtime.h>
#include <cuda_fp16.h>

#define TSEQ 4096
#define DM   768
#define NH   12
#define DKH  64
#define DFF  3072

// ---- fp32 scratch ----
__device__ float g_y1  [TSEQ * DM];
__device__ float g_h   [TSEQ * DM];
__device__ float g_y2  [TSEQ * DM];
__device__ float g_bqkv[3 * DM];

// ---- fp16 activations (single precision) ----
__device__ __half g_x16[TSEQ * DM];
__device__ __half g_ab [TSEQ * DM];
__device__ __half g_h16[TSEQ * DM];
__device__ __half g_f1 [TSEQ * DFF];

// ---- fp16 transposed weights [N, K] ----
__device__ __half g_wqkv[3 * DM * DM];
__device__ __half g_wo  [DM * DM];
__device__ __half g_w1  [DM * DFF];
__device__ __half g_w2  [DM * DFF];

// ---- fp16 QKV, head-major [NH][TSEQ][64] ----
__device__ __half g_qs[NH * TSEQ * DKH];    // Q (scaled)
__device__ __half g_ks[NH * TSEQ * DKH];
__device__ __half g_vs[NH * TSEQ * DKH];

// ============================================================
// helpers (sm_80+ baseline: valid on plain sm_103)
// ============================================================
__device__ __forceinline__ unsigned s2u(const void* p) {
    unsigned a;
    asm("{ .reg .u64 t; cvta.to.shared.u64 t, %1; cvt.u32.u64 %0, t; }"
        : "=r"(a) : "l"(p));
    return a;
}
__device__ __forceinline__ void ldm_x4(unsigned* r, unsigned addr) {
    asm volatile("ldmatrix.sync.aligned.m8n8.x4.shared.b16 {%0,%1,%2,%3}, [%4];"
                 : "=r"(r[0]), "=r"(r[1]), "=r"(r[2]), "=r"(r[3]) : "r"(addr));
}
__device__ __forceinline__ void ldm_x2(unsigned* r, unsigned addr) {
    asm volatile("ldmatrix.sync.aligned.m8n8.x2.shared.b16 {%0,%1}, [%2];"
                 : "=r"(r[0]), "=r"(r[1]) : "r"(addr));
}
__device__ __forceinline__ void ldm_x2t(unsigned* r, unsigned addr) {
    asm volatile("ldmatrix.sync.aligned.m8n8.x2.trans.shared.b16 {%0,%1}, [%2];"
                 : "=r"(r[0]), "=r"(r[1]) : "r"(addr));
}
__device__ __forceinline__ void mma_f16(float* c, const unsigned* a, const unsigned* b) {
    asm volatile("mma.sync.aligned.m16n8k16.row.col.f32.f16.f16.f32 "
                 "{%0,%1,%2,%3}, {%4,%5,%6,%7}, {%8,%9}, {%0,%1,%2,%3};"
                 : "+f"(c[0]), "+f"(c[1]), "+f"(c[2]), "+f"(c[3])
                 : "r"(a[0]), "r"(a[1]), "r"(a[2]), "r"(a[3]), "r"(b[0]), "r"(b[1]));
}
__device__ __forceinline__ void cpa16(unsigned dst, const void* src) {
    asm volatile("cp.async.cg.shared.global [%0], [%1], 16;" :: "r"(dst), "l"(src));
}
__device__ __forceinline__ void cpa16ca(unsigned dst, const void* src) {
    asm volatile("cp.async.ca.shared.global [%0], [%1], 16;" :: "r"(dst), "l"(src));
}
__device__ __forceinline__ void cpa_commit() {
    asm volatile("cp.async.commit_group;" ::: "memory");
}
template<int N> __device__ __forceinline__ void cpa_wait() {
    asm volatile("cp.async.wait_group %0;" :: "n"(N) : "memory");
}

// ============================================================
// Weight transpose + fp16 convert: W[K,N] -> T[N,K]
// ============================================================
__device__ __forceinline__ void wconv_body(
    const float* __restrict__ W, __half* __restrict__ T,
    int K, int N, int n0, int k0, float t[32][33])
{
    const int tx = threadIdx.x, ty = threadIdx.y;
    #pragma unroll
    for (int i = 0; i < 4; i++)
        t[ty + i * 8][tx] = W[(long)(k0 + ty + i * 8) * N + n0 + tx];
    __syncthreads();
    #pragma unroll
    for (int i = 0; i < 4; i++) {
        int n = n0 + ty + i * 8;
        T[(long)n * K + k0 + tx] = __float2half_rn(t[tx][ty + i * 8]);
    }
}
__global__ __launch_bounds__(256) void wconv_t(
    const float* __restrict__ W, __half* __restrict__ T, int K, int N)
{
    __shared__ float t[32][33];
    wconv_body(W, T, K, N, blockIdx.x * 32, blockIdx.y * 32, t);
}
__global__ __launch_bounds__(256) void wconv4(
    const float* __restrict__ W0, const float* __restrict__ W1,
    const float* __restrict__ W2, const float* __restrict__ W3,
    __half* __restrict__ qkv, __half* __restrict__ wo)
{
    __shared__ float t[32][33];
    const int z = blockIdx.z;
    const float* W = (z == 0) ? W0 : (z == 1) ? W1 : (z == 2) ? W2 : W3;
    __half* T = (z < 3) ? (qkv + (long)z * DM * DM) : wo;
    wconv_body(W, T, DM, DM, blockIdx.x * 32, blockIdx.y * 32, t);
}

// ============================================================
// fp32 -> fp16 elementwise
// ============================================================
__global__ __launch_bounds__(256) void fconv(
    const float* __restrict__ X, __half* __restrict__ H)
{
    long idx = ((long)blockIdx.x * 256 + threadIdx.x) * 4;
    float4 v = *(const float4*)(X + idx);
    *(__half2*)(H + idx)     = __floats2half2_rn(v.x, v.y);
    *(__half2*)(H + idx + 2) = __floats2half2_rn(v.z, v.w);
}

// ============================================================
// fp16 single-pass GEMM: C[M,N] = A[M,K] @ B^T[N,K] (+bias)
// cp.async double-buffered.
// MODE 0: fp32 out (+res). MODE 1: fp16 out (+relu).
// MODE 2: QKV head-major fp16 out (Q scaled).
// ============================================================
#define BKC   32
#define ASTR  40
#define SEG   10240                 // 128 rows * 80 B
#define STGB  (2 * SEG)             // 20480 per stage
#define GSMEM (2 * STGB)            // 40960

template<int MODE, bool RELU, bool HASRES>
__global__ __launch_bounds__(256, 2)
void gemm_h1(const __half* __restrict__ A, const __half* __restrict__ B,
             const float* __restrict__ bias, const float* __restrict__ res,
             float* __restrict__ Cf, __half* __restrict__ Ch, int K, int N)
{
    extern __shared__ __align__(128) char smem[];
    const int tid   = threadIdx.x;
    const int wid   = tid >> 5;
    const int lane  = tid & 31;
    const int warpM = wid & 1;
    const int warpN = wid >> 1;
    const int brow  = blockIdx.y * 128;
    const int bcol  = blockIdx.x * 128;
    const unsigned smu = s2u(smem);

    const char* src[2] = { (const char*)A, (const char*)B };

    float acc[4][4][4];
    #pragma unroll
    for (int mi = 0; mi < 4; mi++)
        #pragma unroll
        for (int ni = 0; ni < 4; ni++)
            #pragma unroll
            for (int r = 0; r < 4; r++) acc[mi][ni][r] = 0.f;

    const int nch = K / BKC;

    // stage loader: 1024 cp.async16 over 256 threads = 4 each
    auto load_stage = [&](int s, int kc) {
        #pragma unroll
        for (int it = 0; it < 4; it++) {
            int idx = tid + it * 256;
            int arr = idx >> 9, rem = idx & 511;
            int row = rem >> 2, ch = rem & 3;
            int base_row = (arr == 0) ? (brow + row) : (bcol + row);
            cpa16(smu + s * STGB + arr * SEG + row * 80 + ch * 16,
                  src[arr] + ((long)base_row * K + kc) * 2 + ch * 16);
        }
    };

    load_stage(0, 0);
    cpa_commit();

    for (int c = 0; c < nch; ++c) {
        const int s = c & 1;
        if (c + 1 < nch) {
            load_stage(s ^ 1, (c + 1) * BKC);
            cpa_commit();
            cpa_wait<1>();
        } else {
            cpa_wait<0>();
        }
        __syncthreads();

        const unsigned uA = smu + s * STGB;
        const unsigned uB = uA + SEG;

        #pragma unroll
        for (int kk = 0; kk < 2; kk++) {
            unsigned a[4][4];
            #pragma unroll
            for (int mi = 0; mi < 4; mi++) {
                unsigned rowoff =
                    (unsigned)(((warpM * 64 + mi * 16 + (lane & 15)) * ASTR
                                + (lane >> 4) * 8 + kk * 16) * 2);
                ldm_x4(a[mi], uA + rowoff);
            }
            #pragma unroll
            for (int ni = 0; ni < 4; ni++) {
                unsigned boff =
                    (unsigned)(((warpN * 32 + ni * 8 + (lane & 7)) * ASTR
                                + (((lane >> 3) & 1)) * 8 + kk * 16) * 2);
                unsigned b[2];
                ldm_x2(b, uB + boff);
                #pragma unroll
                for (int mi = 0; mi < 4; mi++)
                    mma_f16(acc[mi][ni], a[mi], b);
            }
        }
        __syncthreads();
    }

    // epilogue
    #pragma unroll
    for (int mi = 0; mi < 4; mi++) {
        #pragma unroll
        for (int half = 0; half < 2; half++) {
            const int row = brow + warpM * 64 + mi * 16 + (lane >> 2) + half * 8;
            #pragma unroll
            for (int ni = 0; ni < 4; ni++) {
                const int col = bcol + warpN * 32 + ni * 8 + (lane & 3) * 2;
                float2 o;
                o.x = acc[mi][ni][half * 2 + 0] + bias[col + 0];
                o.y = acc[mi][ni][half * 2 + 1] + bias[col + 1];
                if (RELU) { o.x = fmaxf(o.x, 0.f); o.y = fmaxf(o.y, 0.f); }
                if (HASRES) {
                    float2 r = *(const float2*)(res + (long)row * N + col);
                    o.x += r.x; o.y += r.y;
                }
                if (MODE == 0) {
                    *(float2*)(Cf + (long)row * N + col) = o;
                } else if (MODE == 1) {
                    *(__half2*)(Ch + (long)row * N + col) = __floats2half2_rn(o.x, o.y);
                } else {  // MODE 2: QKV head-major
                    int kind = (col >= 2 * DM) ? 2 : ((col >= DM) ? 1 : 0);
                    int cm   = col - kind * DM;
                    if (kind == 0) { o.x *= 0.125f; o.y *= 0.125f; }
                    int hh = cm >> 6, dd = cm & 63;
                    long off = ((long)hh * TSEQ + row) * DKH + dd;
                    __half2 v = __floats2half2_rn(o.x, o.y);
                    if (kind == 0)      *(__half2*)(g_qs + off) = v;
                    else if (kind == 1) *(__half2*)(g_ks + off) = v;
                    else                *(__half2*)(g_vs + off) = v;
                }
            }
        }
    }
}

// ============================================================
// Tensor-core flash attention, causal, single-pass fp16.
// Q scaled; out fp16.
// ============================================================
#define SM_Q    (128 * 144)            // 18432
#define KV_ARR  (64 * 144)             // 9216
#define KV_STG  (2 * KV_ARR)           // 18432
#define AT_SMEM (SM_Q + 2 * KV_STG)    // 55296

__global__ __launch_bounds__(256)
void attn_tc(const __half* __restrict__ Qs, const __half* __restrict__ Ks,
             const __half* __restrict__ Vs, __half* __restrict__ O)
{
    extern __shared__ __align__(16) char sm[];
    const unsigned smu = s2u(sm);
    const int tid  = threadIdx.x;
    const int lane = tid & 31;
    const int wq   = tid >> 5;
    const int qb   = (int)gridDim.x - 1 - (int)blockIdx.x;
    const int h    = blockIdx.y;
    const long hb  = (long)h * TSEQ * DKH;

    // Q: 128 rows x 128 B
    {
        const char* sq = (const char*)(Qs + hb + (long)qb * 128 * DKH);
        #pragma unroll
        for (int it = 0; it < 4; it++) {
            int idx = tid + it * 256;
            int row = idx >> 3, ch = idx & 7;
            cpa16ca(smu + row * 144 + ch * 16, sq + row * 128 + ch * 16);
        }
    }
    const char* kvsrc[2] = { (const char*)(Ks + hb), (const char*)(Vs + hb) };
    {
        #pragma unroll
        for (int it = 0; it < 4; it++) {
            int idx = tid + it * 256;
            int arr = idx >> 9, rem = idx & 511;
            int row = rem >> 3, ch = rem & 7;
            cpa16ca(smu + SM_Q + arr * KV_ARR + row * 144 + ch * 16,
                    kvsrc[arr] + (long)row * 128 + ch * 16);
        }
    }
    cpa_commit();
    cpa_wait<0>();
    __syncthreads();

    unsigned qf[4][4];
    #pragma unroll
    for (int kt = 0; kt < 4; kt++) {
        unsigned a = smu + (wq * 16 + (lane & 15)) * 144
                   + ((lane >> 4) * 8 + kt * 16) * 2;
        ldm_x4(qf[kt], a);
    }

    float o_[8][4];
    #pragma unroll
    for (int i = 0; i < 8; i++)
        #pragma unroll
        for (int j = 0; j < 4; j++) o_[i][j] = 0.f;
    float m0 = -1e30f, m1 = -1e30f, l0 = 0.f, l1 = 0.f;

    const int nkb    = (qb + 1) * 2;
    const int diagKb = (qb * 128 + wq * 16) >> 6;
    const int r0g    = qb * 128 + wq * 16 + (lane >> 2);

    for (int kb = 0; kb < nkb; kb++) {
        const int s = kb & 1;

        if (kb + 1 < nkb) {
            const long kb0 = (long)(kb + 1) * 64;
            #pragma unroll
            for (int it = 0; it < 4; it++) {
                int idx = tid + it * 256;
                int arr = idx >> 9, rem = idx & 511;
                int row = rem >> 3, ch = rem & 7;
                cpa16ca(smu + SM_Q + (s ^ 1) * KV_STG + arr * KV_ARR + row * 144 + ch * 16,
                        kvsrc[arr] + (kb0 + row) * 128 + ch * 16);
            }
        }
        cpa_commit();

        float sc[8][4];
        #pragma unroll
        for (int i = 0; i < 8; i++)
            #pragma unroll
            for (int j = 0; j < 4; j++) sc[i][j] = 0.f;

        const unsigned kbase = smu + SM_Q + s * KV_STG;
        #pragma unroll
        for (int kt = 0; kt < 4; kt++) {
            #pragma unroll
            for (int nt = 0; nt < 8; nt++) {
                unsigned ka = kbase + (nt * 8 + (lane & 7)) * 144
                            + (((lane >> 3) & 1) * 8 + kt * 16) * 2;
                unsigned b[2];
                ldm_x2(b, ka);
                mma_f16(sc[nt], qf[kt], b);
            }
        }

        if (kb >= diagKb) {
            #pragma unroll
            for (int nt = 0; nt < 8; nt++) {
                int keyb = kb * 64 + nt * 8 + (lane & 3) * 2;
                #pragma unroll
                for (int c = 0; c < 4; c++) {
                    int key = keyb + (c & 1);
                    int row = r0g + (c >> 1) * 8;
                    if (key > row) sc[nt][c] = -1e30f;
                }
            }
        }

        float pm0 = -1e30f, pm1 = -1e30f;
        #pragma unroll
        for (int nt = 0; nt < 8; nt++) {
            pm0 = fmaxf(pm0, fmaxf(sc[nt][0], sc[nt][1]));
            pm1 = fmaxf(pm1, fmaxf(sc[nt][2], sc[nt][3]));
        }
        pm0 = fmaxf(pm0, __shfl_xor_sync(0xffffffffu, pm0, 1));
        pm0 = fmaxf(pm0, __shfl_xor_sync(0xffffffffu, pm0, 2));
        pm1 = fmaxf(pm1, __shfl_xor_sync(0xffffffffu, pm1, 1));
        pm1 = fmaxf(pm1, __shfl_xor_sync(0xffffffffu, pm1, 2));

        float mn0 = fmaxf(m0, pm0), mn1 = fmaxf(m1, pm1);
        float a0 = __expf(m0 - mn0), a1 = __expf(m1 - mn1);
        m0 = mn0; m1 = mn1;

        float rs0 = 0.f, rs1 = 0.f;
        #pragma unroll
        for (int nt = 0; nt < 8; nt++) {
            sc[nt][0] = __expf(sc[nt][0] - mn0);
            sc[nt][1] = __expf(sc[nt][1] - mn0);
            sc[nt][2] = __expf(sc[nt][2] - mn1);
            sc[nt][3] = __expf(sc[nt][3] - mn1);
            rs0 += sc[nt][0] + sc[nt][1];
            rs1 += sc[nt][2] + sc[nt][3];
        }
        rs0 += __shfl_xor_sync(0xffffffffu, rs0, 1);
        rs0 += __shfl_xor_sync(0xffffffffu, rs0, 2);
        rs1 += __shfl_xor_sync(0xffffffffu, rs1, 1);
        rs1 += __shfl_xor_sync(0xffffffffu, rs1, 2);
        l0 = l0 * a0 + rs0;
        l1 = l1 * a1 + rs1;

        #pragma unroll
        for (int dt = 0; dt < 8; dt++) {
            o_[dt][0] *= a0; o_[dt][1] *= a0;
            o_[dt][2] *= a1; o_[dt][3] *= a1;
        }

        // pack P: acc layout == A-frag layout
        unsigned pf[4][4];
        #pragma unroll
        for (int kt = 0; kt < 4; kt++) {
            #pragma unroll
            for (int half = 0; half < 2; half++) {
                const float* v0 = sc[kt * 2 + half];
                __half2 p01 = __floats2half2_rn(v0[0], v0[1]);
                __half2 p23 = __floats2half2_rn(v0[2], v0[3]);
                pf[kt][half * 2 + 0] = *(unsigned*)&p01;
                pf[kt][half * 2 + 1] = *(unsigned*)&p23;
            }
        }

        const unsigned vbase = kbase + KV_ARR;
        #pragma unroll
        for (int kt = 0; kt < 4; kt++) {
            #pragma unroll
            for (int nt = 0; nt < 8; nt++) {
                unsigned va = vbase + (kt * 16 + (lane & 15)) * 144 + nt * 16;
                unsigned b[2];
                ldm_x2t(b, va);
                mma_f16(o_[nt], pf[kt], b);
            }
        }

        cpa_wait<0>();
        __syncthreads();
    }

    const float i0 = 1.f / l0, i1 = 1.f / l1;
    #pragma unroll
    for (int nt = 0; nt < 8; nt++) {
        int col = h * DKH + nt * 8 + (lane & 3) * 2;
        *(__half2*)(O + (long)r0g * DM + col) =
            __floats2half2_rn(o_[nt][0] * i0, o_[nt][1] * i0);
        *(__half2*)(O + (long)(r0g + 8) * DM + col) =
            __floats2half2_rn(o_[nt][2] * i1, o_[nt][3] * i1);
    }
}

// ============================================================
// LayerNorm; optional fp16 side output
// ============================================================
__global__ __launch_bounds__(256) void ln_kernel(
    const float* __restrict__ X, const float* __restrict__ g,
    const float* __restrict__ b, float* __restrict__ Y,
    __half* __restrict__ Yh)
{
    const int r   = blockIdx.x;
    const int tid = threadIdx.x;
    const float* x = X + (long)r * DM;

    float v[3];
    float s = 0.f, ss = 0.f;
    #pragma unroll
    for (int i = 0; i < 3; i++) {
        v[i] = x[tid + i * 256];
        s  += v[i];
        ss += v[i] * v[i];
    }
    #pragma unroll
    for (int off = 16; off > 0; off >>= 1) {
        s  += __shfl_xor_sync(0xffffffffu, s,  off);
        ss += __shfl_xor_sync(0xffffffffu, ss, off);
    }
    __shared__ float rs_[8], rss_[8];
    const int lane = tid & 31, wid = tid >> 5;
    if (lane == 0) { rs_[wid] = s; rss_[wid] = ss; }
    __syncthreads();
    float ts = 0.f, tss = 0.f;
    #pragma unroll
    for (int w = 0; w < 8; w++) { ts += rs_[w]; tss += rss_[w]; }

    const float mean = ts * (1.f / 768.f);
    const float var  = tss * (1.f / 768.f) - mean * mean;
    const float rstd = rsqrtf(var + 1e-5f);

    #pragma unroll
    for (int i = 0; i < 3; i++) {
        int c = tid + i * 256;
        float yv = (v[i] - mean) * rstd * g[c] + b[c];
        Y[(long)r * DM + c] = yv;
        if (Yh) Yh[(long)r * DM + c] = __float2half_rn(yv);
    }
}

// ============================================================
extern "C" void kernel_launch(void* const* d_in, const int* in_sizes, int n_in,
                              void* d_out, int out_size)
{
    const float* x   = (const float*)d_in[0];
    const float* Wq  = (const float*)d_in[1];
    const float* bq  = (const float*)d_in[2];
    const float* Wk  = (const float*)d_in[3];
    const float* bk  = (const float*)d_in[4];
    const float* Wv  = (const float*)d_in[5];
    const float* bv  = (const float*)d_in[6];
    const float* Wo  = (const float*)d_in[7];
    const float* bo  = (const float*)d_in[8];
    const float* W1  = (const float*)d_in[9];
    const float* b1  = (const float*)d_in[10];
    const float* W2  = (const float*)d_in[11];
    const float* b2  = (const float*)d_in[12];
    const float* g1  = (const float*)d_in[13];
    const float* be1 = (const float*)d_in[14];
    const float* g2  = (const float*)d_in[15];
    const float* be2 = (const float*)d_in[16];
    float* out = (float*)d_out;

    float *y1, *hbuf, *y2, *bqkv;
    cudaGetSymbolAddress((void**)&y1,   g_y1);
    cudaGetSymbolAddress((void**)&hbuf, g_h);
    cudaGetSymbolAddress((void**)&y2,   g_y2);
    cudaGetSymbolAddress((void**)&bqkv, g_bqkv);

    __half *x16, *ab, *h16, *f1;
    cudaGetSymbolAddress((void**)&x16, g_x16);
    cudaGetSymbolAddress((void**)&ab,  g_ab);
    cudaGetSymbolAddress((void**)&h16, g_h16);
    cudaGetSymbolAddress((void**)&f1,  g_f1);

    __half *wqkv, *wo, *w1, *w2;
    cudaGetSymbolAddress((void**)&wqkv, g_wqkv);
    cudaGetSymbolAddress((void**)&wo, g_wo);
    cudaGetSymbolAddress((void**)&w1, g_w1);
    cudaGetSymbolAddress((void**)&w2, g_w2);

    __half *qs, *ks, *vs;
    cudaGetSymbolAddress((void**)&qs, g_qs);
    cudaGetSymbolAddress((void**)&ks, g_ks);
    cudaGetSymbolAddress((void**)&vs, g_vs);

    cudaFuncSetAttribute(gemm_h1<2, false, false>,
                         cudaFuncAttributeMaxDynamicSharedMemorySize, GSMEM);
    cudaFuncSetAttribute(gemm_h1<0, false, true>,
                         cudaFuncAttributeMaxDynamicSharedMemorySize, GSMEM);
    cudaFuncSetAttribute(gemm_h1<1, true, false>,
                         cudaFuncAttributeMaxDynamicSharedMemorySize, GSMEM);
    cudaFuncSetAttribute(attn_tc, cudaFuncAttributeMaxDynamicSharedMemorySize, AT_SMEM);

    dim3 tblk(32, 8);
    dim3 blk(256);

    // weight prep (fp16) + bias concat
    wconv4<<<dim3(24, 24, 4), tblk>>>(Wq, Wk, Wv, Wo, wqkv, wo);
    wconv_t<<<dim3(DFF / 32, DM  / 32), tblk>>>(W1, w1, DM,  DFF);
    wconv_t<<<dim3(DM  / 32, DFF / 32), tblk>>>(W2, w2, DFF, DM);
    cudaMemcpyAsync(bqkv,          bq, DM * 4, cudaMemcpyDeviceToDevice);
    cudaMemcpyAsync(bqkv + DM,     bk, DM * 4, cudaMemcpyDeviceToDevice);
    cudaMemcpyAsync(bqkv + 2 * DM, bv, DM * 4, cudaMemcpyDeviceToDevice);

    // x -> fp16
    fconv<<<TSEQ * DM / 1024, blk>>>(x, x16);

    // fused QKV projection -> head-major fp16 (Q scaled)
    gemm_h1<2, false, false><<<dim3(18, 32), blk, GSMEM>>>(
        x16, wqkv, bqkv, nullptr, nullptr, nullptr, DM, 3 * DM);

    // attention -> fp16
    attn_tc<<<dim3(TSEQ / 128, NH), blk, AT_SMEM>>>(qs, ks, vs, ab);

    // output projection + residual(x)
    gemm_h1<0, false, true><<<dim3(6, 32), blk, GSMEM>>>(
        ab, wo, bo, x, y1, nullptr, DM, DM);

    ln_kernel<<<TSEQ, blk>>>(y1, g1, be1, hbuf, h16);

    // FFN
    gemm_h1<1, true, false><<<dim3(24, 32), blk, GSMEM>>>(
        h16, w1, b1, nullptr, nullptr, f1, DM, DFF);
    gemm_h1<0, false, true><<<dim3(6, 32), blk, GSMEM>>>(
        f1, w2, b2, hbuf, y2, nullptr, DFF, DM);

    ln_kernel<<<TSEQ, blk>>>(y2, g2, be2, out, nullptr);
}

// round 9
// speedup vs baseline: 6.8304x; 1.0640x over previous
#include <cuda_runtime.h>
#include <cuda_fp16.h>

#define TSEQ 4096
#define DM   768
#define NH   12
#define DKH  64
#define DFF  3072

// ---- fp32 scratch ----
__device__ float g_y1  [TSEQ * DM];
__device__ float g_h   [TSEQ * DM];
__device__ float g_y2  [TSEQ * DM];
__device__ float g_bqkv[3 * DM];

// ---- fp16 activations ----
__device__ __half g_x16[TSEQ * DM];
__device__ __half g_ab [TSEQ * DM];
__device__ __half g_h16[TSEQ * DM];
__device__ __half g_f1 [TSEQ * DFF];

// ---- fp16 transposed weights [N, K] ----
__device__ __half g_wqkv[3 * DM * DM];
__device__ __half g_wo  [DM * DM];
__device__ __half g_w1  [DM * DFF];
__device__ __half g_w2  [DM * DFF];

// ---- fp16 QKV, head-major [NH][TSEQ][64] ----
__device__ __half g_qs[NH * TSEQ * DKH];
__device__ __half g_ks[NH * TSEQ * DKH];
__device__ __half g_vs[NH * TSEQ * DKH];

// ============================================================
// helpers
// ============================================================
__device__ __forceinline__ unsigned s2u(const void* p) {
    unsigned a;
    asm("{ .reg .u64 t; cvta.to.shared.u64 t, %1; cvt.u32.u64 %0, t; }"
        : "=r"(a) : "l"(p));
    return a;
}
__device__ __forceinline__ void ldm_x4(unsigned* r, unsigned addr) {
    asm volatile("ldmatrix.sync.aligned.m8n8.x4.shared.b16 {%0,%1,%2,%3}, [%4];"
                 : "=r"(r[0]), "=r"(r[1]), "=r"(r[2]), "=r"(r[3]) : "r"(addr));
}
__device__ __forceinline__ void ldm_x4t(unsigned* r, unsigned addr) {
    asm volatile("ldmatrix.sync.aligned.m8n8.x4.trans.shared.b16 {%0,%1,%2,%3}, [%4];"
                 : "=r"(r[0]), "=r"(r[1]), "=r"(r[2]), "=r"(r[3]) : "r"(addr));
}
__device__ __forceinline__ void mma_f16(float* c, const unsigned* a, const unsigned* b) {
    asm volatile("mma.sync.aligned.m16n8k16.row.col.f32.f16.f16.f32 "
                 "{%0,%1,%2,%3}, {%4,%5,%6,%7}, {%8,%9}, {%0,%1,%2,%3};"
                 : "+f"(c[0]), "+f"(c[1]), "+f"(c[2]), "+f"(c[3])
                 : "r"(a[0]), "r"(a[1]), "r"(a[2]), "r"(a[3]), "r"(b[0]), "r"(b[1]));
}
__device__ __forceinline__ void cpa16(unsigned dst, const void* src) {
    asm volatile("cp.async.cg.shared.global [%0], [%1], 16;" :: "r"(dst), "l"(src));
}
__device__ __forceinline__ void cpa16ca(unsigned dst, const void* src) {
    asm volatile("cp.async.ca.shared.global [%0], [%1], 16;" :: "r"(dst), "l"(src));
}
__device__ __forceinline__ void cpa_commit() {
    asm volatile("cp.async.commit_group;" ::: "memory");
}
template<int N> __device__ __forceinline__ void cpa_wait() {
    asm volatile("cp.async.wait_group %0;" :: "n"(N) : "memory");
}

// ============================================================
// Weight transpose + fp16 convert: W[K,N] -> T[N,K]
// ============================================================
__device__ __forceinline__ void wconv_body(
    const float* __restrict__ W, __half* __restrict__ T,
    int K, int N, int n0, int k0, float t[32][33])
{
    const int tx = threadIdx.x, ty = threadIdx.y;
    #pragma unroll
    for (int i = 0; i < 4; i++)
        t[ty + i * 8][tx] = W[(long)(k0 + ty + i * 8) * N + n0 + tx];
    __syncthreads();
    #pragma unroll
    for (int i = 0; i < 4; i++) {
        int n = n0 + ty + i * 8;
        T[(long)n * K + k0 + tx] = __float2half_rn(t[tx][ty + i * 8]);
    }
}
__global__ __launch_bounds__(256) void wconv_t(
    const float* __restrict__ W, __half* __restrict__ T, int K, int N)
{
    __shared__ float t[32][33];
    wconv_body(W, T, K, N, blockIdx.x * 32, blockIdx.y * 32, t);
}
__global__ __launch_bounds__(256) void wconv4(
    const float* __restrict__ W0, const float* __restrict__ W1,
    const float* __restrict__ W2, const float* __restrict__ W3,
    __half* __restrict__ qkv, __half* __restrict__ wo)
{
    __shared__ float t[32][33];
    const int z = blockIdx.z;
    const float* W = (z == 0) ? W0 : (z == 1) ? W1 : (z == 2) ? W2 : W3;
    __half* T = (z < 3) ? (qkv + (long)z * DM * DM) : wo;
    wconv_body(W, T, DM, DM, blockIdx.x * 32, blockIdx.y * 32, t);
}

// bias concat (replaces 3 memcpy nodes)
__global__ __launch_bounds__(256) void bcat(
    const float* __restrict__ bq, const float* __restrict__ bk,
    const float* __restrict__ bv, float* __restrict__ dst)
{
    int i = blockIdx.x * 256 + threadIdx.x;     // 0..2303
    float v = (i < DM) ? bq[i] : (i < 2 * DM) ? bk[i - DM] : bv[i - 2 * DM];
    dst[i] = v;
}

// fp32 -> fp16 elementwise
__global__ __launch_bounds__(256) void fconv(
    const float* __restrict__ X, __half* __restrict__ H)
{
    long idx = ((long)blockIdx.x * 256 + threadIdx.x) * 4;
    float4 v = *(const float4*)(X + idx);
    *(__half2*)(H + idx)     = __floats2half2_rn(v.x, v.y);
    *(__half2*)(H + idx + 2) = __floats2half2_rn(v.z, v.w);
}

// ============================================================
// fp16 GEMM: C[M,N] = A[M,K] @ B^T[N,K] (+bias)
// 3-stage cp.async pipeline, ldmatrix.x4 B-loads.
// MODE 0: fp32 out (+res). MODE 1: fp16 out (+relu).
// MODE 2: QKV head-major fp16 out (Q scaled).
// ============================================================
#define BKC   32
#define ASTR  40
#define SEG   10240                 // 128 rows * 80 B
#define STGB  (2 * SEG)             // 20480 per stage
#define GSMEM (3 * STGB)            // 61440 (3 stages)

template<int MODE, bool RELU, bool HASRES>
__global__ __launch_bounds__(256, 2)
void gemm_h1(const __half* __restrict__ A, const __half* __restrict__ B,
             const float* __restrict__ bias, const float* __restrict__ res,
             float* __restrict__ Cf, __half* __restrict__ Ch, int K, int N)
{
    extern __shared__ __align__(128) char smem[];
    const int tid   = threadIdx.x;
    const int wid   = tid >> 5;
    const int lane  = tid & 31;
    const int warpM = wid & 1;
    const int warpN = wid >> 1;
    const int brow  = blockIdx.y * 128;
    const int bcol  = blockIdx.x * 128;
    const unsigned smu = s2u(smem);

    const char* src[2] = { (const char*)A, (const char*)B };

    float acc[4][4][4];
    #pragma unroll
    for (int mi = 0; mi < 4; mi++)
        #pragma unroll
        for (int ni = 0; ni < 4; ni++)
            #pragma unroll
            for (int r = 0; r < 4; r++) acc[mi][ni][r] = 0.f;

    const int nch = K / BKC;

    auto load_stage = [&](int s, int kc) {
        #pragma unroll
        for (int it = 0; it < 4; it++) {
            int idx = tid + it * 256;
            int arr = idx >> 9, rem = idx & 511;
            int row = rem >> 2, ch = rem & 3;
            int base_row = (arr == 0) ? (brow + row) : (bcol + row);
            cpa16(smu + s * STGB + arr * SEG + row * 80 + ch * 16,
                  src[arr] + ((long)base_row * K + kc) * 2 + ch * 16);
        }
    };

    load_stage(0, 0);
    cpa_commit();
    if (nch > 1) { load_stage(1, BKC); cpa_commit(); }

    int s = 0;
    for (int c = 0; c < nch; ++c) {
        cpa_wait<1>();
        __syncthreads();
        if (c + 2 < nch) {
            int s2 = s + 2; if (s2 >= 3) s2 -= 3;
            load_stage(s2, (c + 2) * BKC);
            cpa_commit();
        }

        const unsigned uA = smu + s * STGB;
        const unsigned uB = uA + SEG;

        #pragma unroll
        for (int kk = 0; kk < 2; kk++) {
            unsigned a[4][4];
            #pragma unroll
            for (int mi = 0; mi < 4; mi++) {
                unsigned rowoff =
                    (unsigned)(((warpM * 64 + mi * 16 + (lane & 15)) * ASTR
                                + (lane >> 4) * 8 + kk * 16) * 2);
                ldm_x4(a[mi], uA + rowoff);
            }
            #pragma unroll
            for (int ni = 0; ni < 4; ni += 2) {
                unsigned boff =
                    (unsigned)(((warpN * 32 + (ni + ((lane >> 4) & 1)) * 8 + (lane & 7)) * ASTR
                                + ((lane >> 3) & 1) * 8 + kk * 16) * 2);
                unsigned b[4];
                ldm_x4(b, uB + boff);
                #pragma unroll
                for (int mi = 0; mi < 4; mi++) {
                    mma_f16(acc[mi][ni + 0], a[mi], b);
                    mma_f16(acc[mi][ni + 1], a[mi], b + 2);
                }
            }
        }
        if (++s >= 3) s -= 3;
    }

    // epilogue
    #pragma unroll
    for (int mi = 0; mi < 4; mi++) {
        #pragma unroll
        for (int half = 0; half < 2; half++) {
            const int row = brow + warpM * 64 + mi * 16 + (lane >> 2) + half * 8;
            #pragma unroll
            for (int ni = 0; ni < 4; ni++) {
                const int col = bcol + warpN * 32 + ni * 8 + (lane & 3) * 2;
                float2 o;
                o.x = acc[mi][ni][half * 2 + 0] + bias[col + 0];
                o.y = acc[mi][ni][half * 2 + 1] + bias[col + 1];
                if (RELU) { o.x = fmaxf(o.x, 0.f); o.y = fmaxf(o.y, 0.f); }
                if (HASRES) {
                    float2 r = *(const float2*)(res + (long)row * N + col);
                    o.x += r.x; o.y += r.y;
                }
                if (MODE == 0) {
                    *(float2*)(Cf + (long)row * N + col) = o;
                } else if (MODE == 1) {
                    *(__half2*)(Ch + (long)row * N + col) = __floats2half2_rn(o.x, o.y);
                } else {
                    int kind = (col >= 2 * DM) ? 2 : ((col >= DM) ? 1 : 0);
                    int cm   = col - kind * DM;
                    if (kind == 0) { o.x *= 0.125f; o.y *= 0.125f; }
                    int hh = cm >> 6, dd = cm & 63;
                    long off = ((long)hh * TSEQ + row) * DKH + dd;
                    __half2 v = __floats2half2_rn(o.x, o.y);
                    if (kind == 0)      *(__half2*)(g_qs + off) = v;
                    else if (kind == 1) *(__half2*)(g_ks + off) = v;
                    else                *(__half2*)(g_vs + off) = v;
                }
            }
        }
    }
}

// ============================================================
// Tensor-core flash attention, causal, fp16, 2 CTAs/SM.
// ============================================================
#define SM_Q    (128 * 144)            // 18432
#define KV_ARR  (64 * 144)             // 9216
#define KV_STG  (2 * KV_ARR)           // 18432
#define AT_SMEM (SM_Q + 2 * KV_STG)    // 55296

__global__ __launch_bounds__(256, 2)
void attn_tc(const __half* __restrict__ Qs, const __half* __restrict__ Ks,
             const __half* __restrict__ Vs, __half* __restrict__ O)
{
    extern __shared__ __align__(16) char sm[];
    const unsigned smu = s2u(sm);
    const int tid  = threadIdx.x;
    const int lane = tid & 31;
    const int wq   = tid >> 5;
    const int qb   = (int)gridDim.x - 1 - (int)blockIdx.x;
    const int h    = blockIdx.y;
    const long hb  = (long)h * TSEQ * DKH;

    {
        const char* sq = (const char*)(Qs + hb + (long)qb * 128 * DKH);
        #pragma unroll
        for (int it = 0; it < 4; it++) {
            int idx = tid + it * 256;
            int row = idx >> 3, ch = idx & 7;
            cpa16ca(smu + row * 144 + ch * 16, sq + row * 128 + ch * 16);
        }
    }
    const char* kvsrc[2] = { (const char*)(Ks + hb), (const char*)(Vs + hb) };
    {
        #pragma unroll
        for (int it = 0; it < 4; it++) {
            int idx = tid + it * 256;
            int arr = idx >> 9, rem = idx & 511;
            int row = rem >> 3, ch = rem & 7;
            cpa16ca(smu + SM_Q + arr * KV_ARR + row * 144 + ch * 16,
                    kvsrc[arr] + (long)row * 128 + ch * 16);
        }
    }
    cpa_commit();
    cpa_wait<0>();
    __syncthreads();

    unsigned qf[4][4];
    #pragma unroll
    for (int kt = 0; kt < 4; kt++) {
        unsigned a = smu + (wq * 16 + (lane & 15)) * 144
                   + ((lane >> 4) * 8 + kt * 16) * 2;
        ldm_x4(qf[kt], a);
    }

    float o_[8][4];
    #pragma unroll
    for (int i = 0; i < 8; i++)
        #pragma unroll
        for (int j = 0; j < 4; j++) o_[i][j] = 0.f;
    float m0 = -1e30f, m1 = -1e30f, l0 = 0.f, l1 = 0.f;

    const int nkb    = (qb + 1) * 2;
    const int diagKb = (qb * 128 + wq * 16) >> 6;
    const int r0g    = qb * 128 + wq * 16 + (lane >> 2);

    for (int kb = 0; kb < nkb; kb++) {
        const int s = kb & 1;

        if (kb + 1 < nkb) {
            const long kb0 = (long)(kb + 1) * 64;
            #pragma unroll
            for (int it = 0; it < 4; it++) {
                int idx = tid + it * 256;
                int arr = idx >> 9, rem = idx & 511;
                int row = rem >> 3, ch = rem & 7;
                cpa16ca(smu + SM_Q + (s ^ 1) * KV_STG + arr * KV_ARR + row * 144 + ch * 16,
                        kvsrc[arr] + (kb0 + row) * 128 + ch * 16);
            }
        }
        cpa_commit();

        float sc[8][4];
        #pragma unroll
        for (int i = 0; i < 8; i++)
            #pragma unroll
            for (int j = 0; j < 4; j++) sc[i][j] = 0.f;

        const unsigned kbase = smu + SM_Q + s * KV_STG;
        #pragma unroll
        for (int kt = 0; kt < 4; kt++) {
            #pragma unroll
            for (int nt = 0; nt < 8; nt += 2) {
                unsigned ka = kbase
                    + ((nt + ((lane >> 4) & 1)) * 8 + (lane & 7)) * 144
                    + (((lane >> 3) & 1) * 8 + kt * 16) * 2;
                unsigned b[4];
                ldm_x4(b, ka);
                mma_f16(sc[nt + 0], qf[kt], b);
                mma_f16(sc[nt + 1], qf[kt], b + 2);
            }
        }

        if (kb >= diagKb) {
            #pragma unroll
            for (int nt = 0; nt < 8; nt++) {
                int keyb = kb * 64 + nt * 8 + (lane & 3) * 2;
                #pragma unroll
                for (int c = 0; c < 4; c++) {
                    int key = keyb + (c & 1);
                    int row = r0g + (c >> 1) * 8;
                    if (key > row) sc[nt][c] = -1e30f;
                }
            }
        }

        float pm0 = -1e30f, pm1 = -1e30f;
        #pragma unroll
        for (int nt = 0; nt < 8; nt++) {
            pm0 = fmaxf(pm0, fmaxf(sc[nt][0], sc[nt][1]));
            pm1 = fmaxf(pm1, fmaxf(sc[nt][2], sc[nt][3]));
        }
        pm0 = fmaxf(pm0, __shfl_xor_sync(0xffffffffu, pm0, 1));
        pm0 = fmaxf(pm0, __shfl_xor_sync(0xffffffffu, pm0, 2));
        pm1 = fmaxf(pm1, __shfl_xor_sync(0xffffffffu, pm1, 1));
        pm1 = fmaxf(pm1, __shfl_xor_sync(0xffffffffu, pm1, 2));

        float mn0 = fmaxf(m0, pm0), mn1 = fmaxf(m1, pm1);
        float a0 = __expf(m0 - mn0), a1 = __expf(m1 - mn1);
        m0 = mn0; m1 = mn1;

        float rs0 = 0.f, rs1 = 0.f;
        #pragma unroll
        for (int nt = 0; nt < 8; nt++) {
            sc[nt][0] = __expf(sc[nt][0] - mn0);
            sc[nt][1] = __expf(sc[nt][1] - mn0);
            sc[nt][2] = __expf(sc[nt][2] - mn1);
            sc[nt][3] = __expf(sc[nt][3] - mn1);
            rs0 += sc[nt][0] + sc[nt][1];
            rs1 += sc[nt][2] + sc[nt][3];
        }
        rs0 += __shfl_xor_sync(0xffffffffu, rs0, 1);
        rs0 += __shfl_xor_sync(0xffffffffu, rs0, 2);
        rs1 += __shfl_xor_sync(0xffffffffu, rs1, 1);
        rs1 += __shfl_xor_sync(0xffffffffu, rs1, 2);
        l0 = l0 * a0 + rs0;
        l1 = l1 * a1 + rs1;

        #pragma unroll
        for (int dt = 0; dt < 8; dt++) {
            o_[dt][0] *= a0; o_[dt][1] *= a0;
            o_[dt][2] *= a1; o_[dt][3] *= a1;
        }

        // pack P: acc layout == A-frag layout
        unsigned pf[4][4];
        #pragma unroll
        for (int kt = 0; kt < 4; kt++) {
            #pragma unroll
            for (int half = 0; half < 2; half++) {
                const float* v0 = sc[kt * 2 + half];
                __half2 p01 = __floats2half2_rn(v0[0], v0[1]);
                __half2 p23 = __floats2half2_rn(v0[2], v0[3]);
                pf[kt][half * 2 + 0] = *(unsigned*)&p01;
                pf[kt][half * 2 + 1] = *(unsigned*)&p23;
            }
        }

        const unsigned vbase = kbase + KV_ARR;
        #pragma unroll
        for (int kt = 0; kt < 4; kt++) {
            #pragma unroll
            for (int nt = 0; nt < 8; nt += 2) {
                unsigned va = vbase + (kt * 16 + (lane & 15)) * 144
                            + (nt + ((lane >> 4) & 1)) * 16;
                unsigned b[4];
                ldm_x4t(b, va);
                mma_f16(o_[nt + 0], pf[kt], b);
                mma_f16(o_[nt + 1], pf[kt], b + 2);
            }
        }

        cpa_wait<0>();
        __syncthreads();
    }

    const float i0 = 1.f / l0, i1 = 1.f / l1;
    #pragma unroll
    for (int nt = 0; nt < 8; nt++) {
        int col = h * DKH + nt * 8 + (lane & 3) * 2;
        *(__half2*)(O + (long)r0g * DM + col) =
            __floats2half2_rn(o_[nt][0] * i0, o_[nt][1] * i0);
        *(__half2*)(O + (long)(r0g + 8) * DM + col) =
            __floats2half2_rn(o_[nt][2] * i1, o_[nt][3] * i1);
    }
}

// ============================================================
// LayerNorm; optional fp16 side output
// ============================================================
__global__ __launch_bounds__(256) void ln_kernel(
    const float* __restrict__ X, const float* __restrict__ g,
    const float* __restrict__ b, float* __restrict__ Y,
    __half* __restrict__ Yh)
{
    const int r   = blockIdx.x;
    const int tid = threadIdx.x;
    const float* x = X + (long)r * DM;

    float v[3];
    float s = 0.f, ss = 0.f;
    #pragma unroll
    for (int i = 0; i < 3; i++) {
        v[i] = x[tid + i * 256];
        s  += v[i];
        ss += v[i] * v[i];
    }
    #pragma unroll
    for (int off = 16; off > 0; off >>= 1) {
        s  += __shfl_xor_sync(0xffffffffu, s,  off);
        ss += __shfl_xor_sync(0xffffffffu, ss, off);
    }
    __shared__ float rs_[8], rss_[8];
    const int lane = tid & 31, wid = tid >> 5;
    if (lane == 0) { rs_[wid] = s; rss_[wid] = ss; }
    __syncthreads();
    float ts = 0.f, tss = 0.f;
    #pragma unroll
    for (int w = 0; w < 8; w++) { ts += rs_[w]; tss += rss_[w]; }

    const float mean = ts * (1.f / 768.f);
    const float var  = tss * (1.f / 768.f) - mean * mean;
    const float rstd = rsqrtf(var + 1e-5f);

    #pragma unroll
    for (int i = 0; i < 3; i++) {
        int c = tid + i * 256;
        float yv = (v[i] - mean) * rstd * g[c] + b[c];
        Y[(long)r * DM + c] = yv;
        if (Yh) Yh[(long)r * DM + c] = __float2half_rn(yv);
    }
}

// ============================================================
extern "C" void kernel_launch(void* const* d_in, const int* in_sizes, int n_in,
                              void* d_out, int out_size)
{
    const float* x   = (const float*)d_in[0];
    const float* Wq  = (const float*)d_in[1];
    const float* bq  = (const float*)d_in[2];
    const float* Wk  = (const float*)d_in[3];
    const float* bk  = (const float*)d_in[4];
    const float* Wv  = (const float*)d_in[5];
    const float* bv  = (const float*)d_in[6];
    const float* Wo  = (const float*)d_in[7];
    const float* bo  = (const float*)d_in[8];
    const float* W1  = (const float*)d_in[9];
    const float* b1  = (const float*)d_in[10];
    const float* W2  = (const float*)d_in[11];
    const float* b2  = (const float*)d_in[12];
    const float* g1  = (const float*)d_in[13];
    const float* be1 = (const float*)d_in[14];
    const float* g2  = (const float*)d_in[15];
    const float* be2 = (const float*)d_in[16];
    float* out = (float*)d_out;

    float *y1, *hbuf, *y2, *bqkv;
    cudaGetSymbolAddress((void**)&y1,   g_y1);
    cudaGetSymbolAddress((void**)&hbuf, g_h);
    cudaGetSymbolAddress((void**)&y2,   g_y2);
    cudaGetSymbolAddress((void**)&bqkv, g_bqkv);

    __half *x16, *ab, *h16, *f1;
    cudaGetSymbolAddress((void**)&x16, g_x16);
    cudaGetSymbolAddress((void**)&ab,  g_ab);
    cudaGetSymbolAddress((void**)&h16, g_h16);
    cudaGetSymbolAddress((void**)&f1,  g_f1);

    __half *wqkv, *wo, *w1, *w2;
    cudaGetSymbolAddress((void**)&wqkv, g_wqkv);
    cudaGetSymbolAddress((void**)&wo, g_wo);
    cudaGetSymbolAddress((void**)&w1, g_w1);
    cudaGetSymbolAddress((void**)&w2, g_w2);

    __half *qs, *ks, *vs;
    cudaGetSymbolAddress((void**)&qs, g_qs);
    cudaGetSymbolAddress((void**)&ks, g_ks);
    cudaGetSymbolAddress((void**)&vs, g_vs);

    cudaFuncSetAttribute(gemm_h1<2, false, false>,
                         cudaFuncAttributeMaxDynamicSharedMemorySize, GSMEM);
    cudaFuncSetAttribute(gemm_h1<0, false, true>,
                         cudaFuncAttributeMaxDynamicSharedMemorySize, GSMEM);
    cudaFuncSetAttribute(gemm_h1<1, true, false>,
                         cudaFuncAttributeMaxDynamicSharedMemorySize, GSMEM);
    cudaFuncSetAttribute(attn_tc, cudaFuncAttributeMaxDynamicSharedMemorySize, AT_SMEM);

    dim3 tblk(32, 8);
    dim3 blk(256);

    // weight prep (fp16) + bias concat + x conversion
    wconv4<<<dim3(24, 24, 4), tblk>>>(Wq, Wk, Wv, Wo, wqkv, wo);
    wconv_t<<<dim3(DFF / 32, DM  / 32), tblk>>>(W1, w1, DM,  DFF);
    wconv_t<<<dim3(DM  / 32, DFF / 32), tblk>>>(W2, w2, DFF, DM);
    bcat<<<9, blk>>>(bq, bk, bv, bqkv);
    fconv<<<TSEQ * DM / 1024, blk>>>(x, x16);

    // fused QKV projection -> head-major fp16 (Q scaled)
    gemm_h1<2, false, false><<<dim3(18, 32), blk, GSMEM>>>(
        x16, wqkv, bqkv, nullptr, nullptr, nullptr, DM, 3 * DM);

    // attention -> fp16
    attn_tc<<<dim3(TSEQ / 128, NH), blk, AT_SMEM>>>(qs, ks, vs, ab);

    // output projection + residual(x)
    gemm_h1<0, false, true><<<dim3(6, 32), blk, GSMEM>>>(
        ab, wo, bo, x, y1, nullptr, DM, DM);

    ln_kernel<<<TSEQ, blk>>>(y1, g1, be1, hbuf, h16);

    // FFN
    gemm_h1<1, true, false><<<dim3(24, 32), blk, GSMEM>>>(
        h16, w1, b1, nullptr, nullptr, f1, DM, DFF);
    gemm_h1<0, false, true><<<dim3(6, 32), blk, GSMEM>>>(
        f1, w2, b2, hbuf, y2, nullptr, DFF, DM);

    ln_kernel<<<TSEQ, blk>>>(y2, g2, be2, out, nullptr);
}

// round 10
// speedup vs baseline: 7.1989x; 1.0540x over previous
#include <cuda_runtime.h>
#include <cuda_fp16.h>

#define TSEQ 4096
#define DM   768
#define NH   12
#define DKH  64
#define DFF  3072

// ---- fp32 scratch ----
__device__ float g_y1  [TSEQ * DM];
__device__ float g_y1b [TSEQ * DM];
__device__ float g_h   [TSEQ * DM];
__device__ float g_y2  [TSEQ * DM];
__device__ float g_y2b [TSEQ * DM];
__device__ float g_bqkv[3 * DM];

// ---- fp16 activations ----
__device__ __half g_x16[TSEQ * DM];
__device__ __half g_ab [TSEQ * DM];
__device__ __half g_h16[TSEQ * DM];
__device__ __half g_f1 [TSEQ * DFF];

// ---- fp16 transposed weights [N, K] ----
__device__ __half g_wqkv[3 * DM * DM];
__device__ __half g_wo  [DM * DM];
__device__ __half g_w1  [DM * DFF];
__device__ __half g_w2  [DM * DFF];

// ---- fp16 QKV, head-major [NH][TSEQ][64] ----
__device__ __half g_qs[NH * TSEQ * DKH];
__device__ __half g_ks[NH * TSEQ * DKH];
__device__ __half g_vs[NH * TSEQ * DKH];

// ============================================================
// helpers
// ============================================================
__device__ __forceinline__ unsigned s2u(const void* p) {
    unsigned a;
    asm("{ .reg .u64 t; cvta.to.shared.u64 t, %1; cvt.u32.u64 %0, t; }"
        : "=r"(a) : "l"(p));
    return a;
}
__device__ __forceinline__ void ldm_x4(unsigned* r, unsigned addr) {
    asm volatile("ldmatrix.sync.aligned.m8n8.x4.shared.b16 {%0,%1,%2,%3}, [%4];"
                 : "=r"(r[0]), "=r"(r[1]), "=r"(r[2]), "=r"(r[3]) : "r"(addr));
}
__device__ __forceinline__ void ldm_x4t(unsigned* r, unsigned addr) {
    asm volatile("ldmatrix.sync.aligned.m8n8.x4.trans.shared.b16 {%0,%1,%2,%3}, [%4];"
                 : "=r"(r[0]), "=r"(r[1]), "=r"(r[2]), "=r"(r[3]) : "r"(addr));
}
__device__ __forceinline__ void mma_f16(float* c, const unsigned* a, const unsigned* b) {
    asm volatile("mma.sync.aligned.m16n8k16.row.col.f32.f16.f16.f32 "
                 "{%0,%1,%2,%3}, {%4,%5,%6,%7}, {%8,%9}, {%0,%1,%2,%3};"
                 : "+f"(c[0]), "+f"(c[1]), "+f"(c[2]), "+f"(c[3])
                 : "r"(a[0]), "r"(a[1]), "r"(a[2]), "r"(a[3]), "r"(b[0]), "r"(b[1]));
}
__device__ __forceinline__ void cpa16(unsigned dst, const void* src) {
    asm volatile("cp.async.cg.shared.global [%0], [%1], 16;" :: "r"(dst), "l"(src));
}
__device__ __forceinline__ void cpa16ca(unsigned dst, const void* src) {
    asm volatile("cp.async.ca.shared.global [%0], [%1], 16;" :: "r"(dst), "l"(src));
}
__device__ __forceinline__ void cpa_commit() {
    asm volatile("cp.async.commit_group;" ::: "memory");
}
template<int N> __device__ __forceinline__ void cpa_wait() {
    asm volatile("cp.async.wait_group %0;" :: "n"(N) : "memory");
}

// ============================================================
// ALL weight transposes + fp16 convert in ONE launch.
// blocks [0,2304): Wq/Wk/Wv/Wo (576 each); [2304,4608): W1; [4608,6912): W2
// ============================================================
__device__ __forceinline__ void wconv_body(
    const float* __restrict__ W, __half* __restrict__ T,
    int K, int N, int n0, int k0, float t[32][33])
{
    const int tx = threadIdx.x, ty = threadIdx.y;
    #pragma unroll
    for (int i = 0; i < 4; i++)
        t[ty + i * 8][tx] = W[(long)(k0 + ty + i * 8) * N + n0 + tx];
    __syncthreads();
    #pragma unroll
    for (int i = 0; i < 4; i++) {
        int n = n0 + ty + i * 8;
        T[(long)n * K + k0 + tx] = __float2half_rn(t[tx][ty + i * 8]);
    }
}
__global__ __launch_bounds__(256) void wprep_all(
    const float* __restrict__ Wq, const float* __restrict__ Wk,
    const float* __restrict__ Wv, const float* __restrict__ Wo,
    const float* __restrict__ W1, const float* __restrict__ W2,
    __half* __restrict__ qkv, __half* __restrict__ wo,
    __half* __restrict__ w1, __half* __restrict__ w2)
{
    __shared__ float t[32][33];
    int bid = blockIdx.x;
    if (bid < 2304) {
        int z = bid / 576, r = bid % 576;
        const float* W = (z == 0) ? Wq : (z == 1) ? Wk : (z == 2) ? Wv : Wo;
        __half* T = (z < 3) ? (qkv + (long)z * DM * DM) : wo;
        wconv_body(W, T, DM, DM, (r % 24) * 32, (r / 24) * 32, t);
    } else if (bid < 4608) {
        int r = bid - 2304;
        wconv_body(W1, w1, DM, DFF, (r % 96) * 32, (r / 96) * 32, t);
    } else {
        int r = bid - 4608;
        wconv_body(W2, w2, DFF, DM, (r % 24) * 32, (r / 24) * 32, t);
    }
}

// ============================================================
// fconv (x -> fp16) + bias concat in ONE launch
// blocks [0,3072): fconv; [3072,3081): bcat
// ============================================================
__global__ __launch_bounds__(256) void prep_misc(
    const float* __restrict__ X, __half* __restrict__ H,
    const float* __restrict__ bq, const float* __restrict__ bk,
    const float* __restrict__ bv, float* __restrict__ dst)
{
    if (blockIdx.x < 3072) {
        long idx = ((long)blockIdx.x * 256 + threadIdx.x) * 4;
        float4 v = *(const float4*)(X + idx);
        *(__half2*)(H + idx)     = __floats2half2_rn(v.x, v.y);
        *(__half2*)(H + idx + 2) = __floats2half2_rn(v.z, v.w);
    } else {
        int i = (blockIdx.x - 3072) * 256 + threadIdx.x;
        if (i < 3 * DM) {
            float v = (i < DM) ? bq[i] : (i < 2 * DM) ? bk[i - DM] : bv[i - 2 * DM];
            dst[i] = v;
        }
    }
}

// ============================================================
// fp16 GEMM: C[M,N] = A[M,K] @ B^T[N,K] (+bias)
// 3-stage cp.async pipeline. Optional split-K x2 (blockIdx.z).
// MODE 0: fp32 out (+res; z=1 writes raw partial to Cf2).
// MODE 1: fp16 out (+relu). MODE 2: QKV head-major fp16 out.
// ============================================================
#define BKC   32
#define ASTR  40
#define SEG   10240                 // 128 rows * 80 B
#define STGB  (2 * SEG)             // 20480 per stage
#define GSMEM (3 * STGB)            // 61440 (3 stages)

template<int MODE, bool RELU, bool HASRES, bool SPLITK>
__global__ __launch_bounds__(256, 2)
void gemm_h1(const __half* __restrict__ A, const __half* __restrict__ B,
             const float* __restrict__ bias, const float* __restrict__ res,
             float* __restrict__ Cf, float* __restrict__ Cf2,
             __half* __restrict__ Ch, int K, int N)
{
    extern __shared__ __align__(128) char smem[];
    const int tid   = threadIdx.x;
    const int wid   = tid >> 5;
    const int lane  = tid & 31;
    const int warpM = wid & 1;
    const int warpN = wid >> 1;
    const int brow  = blockIdx.y * 128;
    const int bcol  = blockIdx.x * 128;
    const int kz    = SPLITK ? (int)blockIdx.z : 0;
    const int Keff  = SPLITK ? (K >> 1) : K;
    const int koff  = kz * Keff;
    const unsigned smu = s2u(smem);

    const char* src[2] = { (const char*)A, (const char*)B };

    float acc[4][4][4];
    #pragma unroll
    for (int mi = 0; mi < 4; mi++)
        #pragma unroll
        for (int ni = 0; ni < 4; ni++)
            #pragma unroll
            for (int r = 0; r < 4; r++) acc[mi][ni][r] = 0.f;

    const int nch = Keff / BKC;

    auto load_stage = [&](int s, int kc) {
        #pragma unroll
        for (int it = 0; it < 4; it++) {
            int idx = tid + it * 256;
            int arr = idx >> 9, rem = idx & 511;
            int row = rem >> 2, ch = rem & 3;
            int base_row = (arr == 0) ? (brow + row) : (bcol + row);
            cpa16(smu + s * STGB + arr * SEG + row * 80 + ch * 16,
                  src[arr] + ((long)base_row * K + koff + kc) * 2 + ch * 16);
        }
    };

    load_stage(0, 0);
    cpa_commit();
    if (nch > 1) { load_stage(1, BKC); cpa_commit(); }

    int s = 0;
    for (int c = 0; c < nch; ++c) {
        cpa_wait<1>();
        __syncthreads();
        if (c + 2 < nch) {
            int s2 = s + 2; if (s2 >= 3) s2 -= 3;
            load_stage(s2, (c + 2) * BKC);
            cpa_commit();
        }

        const unsigned uA = smu + s * STGB;
        const unsigned uB = uA + SEG;

        #pragma unroll
        for (int kk = 0; kk < 2; kk++) {
            unsigned a[4][4];
            #pragma unroll
            for (int mi = 0; mi < 4; mi++) {
                unsigned rowoff =
                    (unsigned)(((warpM * 64 + mi * 16 + (lane & 15)) * ASTR
                                + (lane >> 4) * 8 + kk * 16) * 2);
                ldm_x4(a[mi], uA + rowoff);
            }
            #pragma unroll
            for (int ni = 0; ni < 4; ni += 2) {
                unsigned boff =
                    (unsigned)(((warpN * 32 + (ni + ((lane >> 4) & 1)) * 8 + (lane & 7)) * ASTR
                                + ((lane >> 3) & 1) * 8 + kk * 16) * 2);
                unsigned b[4];
                ldm_x4(b, uB + boff);
                #pragma unroll
                for (int mi = 0; mi < 4; mi++) {
                    mma_f16(acc[mi][ni + 0], a[mi], b);
                    mma_f16(acc[mi][ni + 1], a[mi], b + 2);
                }
            }
        }
        if (++s >= 3) s -= 3;
    }

    // epilogue
    #pragma unroll
    for (int mi = 0; mi < 4; mi++) {
        #pragma unroll
        for (int half = 0; half < 2; half++) {
            const int row = brow + warpM * 64 + mi * 16 + (lane >> 2) + half * 8;
            #pragma unroll
            for (int ni = 0; ni < 4; ni++) {
                const int col = bcol + warpN * 32 + ni * 8 + (lane & 3) * 2;
                float2 o;
                o.x = acc[mi][ni][half * 2 + 0];
                o.y = acc[mi][ni][half * 2 + 1];
                if (SPLITK && kz == 1) {           // raw partial
                    *(float2*)(Cf2 + (long)row * N + col) = o;
                    continue;
                }
                o.x += bias[col + 0];
                o.y += bias[col + 1];
                if (RELU) { o.x = fmaxf(o.x, 0.f); o.y = fmaxf(o.y, 0.f); }
                if (HASRES) {
                    float2 r = *(const float2*)(res + (long)row * N + col);
                    o.x += r.x; o.y += r.y;
                }
                if (MODE == 0) {
                    *(float2*)(Cf + (long)row * N + col) = o;
                } else if (MODE == 1) {
                    *(__half2*)(Ch + (long)row * N + col) = __floats2half2_rn(o.x, o.y);
                } else {
                    int kind = (col >= 2 * DM) ? 2 : ((col >= DM) ? 1 : 0);
                    int cm   = col - kind * DM;
                    if (kind == 0) { o.x *= 0.125f; o.y *= 0.125f; }
                    int hh = cm >> 6, dd = cm & 63;
                    long off = ((long)hh * TSEQ + row) * DKH + dd;
                    __half2 v = __floats2half2_rn(o.x, o.y);
                    if (kind == 0)      *(__half2*)(g_qs + off) = v;
                    else if (kind == 1) *(__half2*)(g_ks + off) = v;
                    else                *(__half2*)(g_vs + off) = v;
                }
            }
        }
    }
}

// ============================================================
// Tensor-core flash attention, causal, fp16, 2 CTAs/SM.
// ============================================================
#define SM_Q    (128 * 144)
#define KV_ARR  (64 * 144)
#define KV_STG  (2 * KV_ARR)
#define AT_SMEM (SM_Q + 2 * KV_STG)

__global__ __launch_bounds__(256, 2)
void attn_tc(const __half* __restrict__ Qs, const __half* __restrict__ Ks,
             const __half* __restrict__ Vs, __half* __restrict__ O)
{
    extern __shared__ __align__(16) char sm[];
    const unsigned smu = s2u(sm);
    const int tid  = threadIdx.x;
    const int lane = tid & 31;
    const int wq   = tid >> 5;
    const int qb   = (int)gridDim.x - 1 - (int)blockIdx.x;
    const int h    = blockIdx.y;
    const long hb  = (long)h * TSEQ * DKH;

    {
        const char* sq = (const char*)(Qs + hb + (long)qb * 128 * DKH);
        #pragma unroll
        for (int it = 0; it < 4; it++) {
            int idx = tid + it * 256;
            int row = idx >> 3, ch = idx & 7;
            cpa16ca(smu + row * 144 + ch * 16, sq + row * 128 + ch * 16);
        }
    }
    const char* kvsrc[2] = { (const char*)(Ks + hb), (const char*)(Vs + hb) };
    {
        #pragma unroll
        for (int it = 0; it < 4; it++) {
            int idx = tid + it * 256;
            int arr = idx >> 9, rem = idx & 511;
            int row = rem >> 3, ch = rem & 7;
            cpa16ca(smu + SM_Q + arr * KV_ARR + row * 144 + ch * 16,
                    kvsrc[arr] + (long)row * 128 + ch * 16);
        }
    }
    cpa_commit();
    cpa_wait<0>();
    __syncthreads();

    unsigned qf[4][4];
    #pragma unroll
    for (int kt = 0; kt < 4; kt++) {
        unsigned a = smu + (wq * 16 + (lane & 15)) * 144
                   + ((lane >> 4) * 8 + kt * 16) * 2;
        ldm_x4(qf[kt], a);
    }

    float o_[8][4];
    #pragma unroll
    for (int i = 0; i < 8; i++)
        #pragma unroll
        for (int j = 0; j < 4; j++) o_[i][j] = 0.f;
    float m0 = -1e30f, m1 = -1e30f, l0 = 0.f, l1 = 0.f;

    const int nkb    = (qb + 1) * 2;
    const int diagKb = (qb * 128 + wq * 16) >> 6;
    const int r0g    = qb * 128 + wq * 16 + (lane >> 2);

    for (int kb = 0; kb < nkb; kb++) {
        const int s = kb & 1;

        if (kb + 1 < nkb) {
            const long kb0 = (long)(kb + 1) * 64;
            #pragma unroll
            for (int it = 0; it < 4; it++) {
                int idx = tid + it * 256;
                int arr = idx >> 9, rem = idx & 511;
                int row = rem >> 3, ch = rem & 7;
                cpa16ca(smu + SM_Q + (s ^ 1) * KV_STG + arr * KV_ARR + row * 144 + ch * 16,
                        kvsrc[arr] + (kb0 + row) * 128 + ch * 16);
            }
        }
        cpa_commit();

        float sc[8][4];
        #pragma unroll
        for (int i = 0; i < 8; i++)
            #pragma unroll
            for (int j = 0; j < 4; j++) sc[i][j] = 0.f;

        const unsigned kbase = smu + SM_Q + s * KV_STG;
        #pragma unroll
        for (int kt = 0; kt < 4; kt++) {
            #pragma unroll
            for (int nt = 0; nt < 8; nt += 2) {
                unsigned ka = kbase
                    + ((nt + ((lane >> 4) & 1)) * 8 + (lane & 7)) * 144
                    + (((lane >> 3) & 1) * 8 + kt * 16) * 2;
                unsigned b[4];
                ldm_x4(b, ka);
                mma_f16(sc[nt + 0], qf[kt], b);
                mma_f16(sc[nt + 1], qf[kt], b + 2);
            }
        }

        if (kb >= diagKb) {
            #pragma unroll
            for (int nt = 0; nt < 8; nt++) {
                int keyb = kb * 64 + nt * 8 + (lane & 3) * 2;
                #pragma unroll
                for (int c = 0; c < 4; c++) {
                    int key = keyb + (c & 1);
                    int row = r0g + (c >> 1) * 8;
                    if (key > row) sc[nt][c] = -1e30f;
                }
            }
        }

        float pm0 = -1e30f, pm1 = -1e30f;
        #pragma unroll
        for (int nt = 0; nt < 8; nt++) {
            pm0 = fmaxf(pm0, fmaxf(sc[nt][0], sc[nt][1]));
            pm1 = fmaxf(pm1, fmaxf(sc[nt][2], sc[nt][3]));
        }
        pm0 = fmaxf(pm0, __shfl_xor_sync(0xffffffffu, pm0, 1));
        pm0 = fmaxf(pm0, __shfl_xor_sync(0xffffffffu, pm0, 2));
        pm1 = fmaxf(pm1, __shfl_xor_sync(0xffffffffu, pm1, 1));
        pm1 = fmaxf(pm1, __shfl_xor_sync(0xffffffffu, pm1, 2));

        float mn0 = fmaxf(m0, pm0), mn1 = fmaxf(m1, pm1);
        float a0 = __expf(m0 - mn0), a1 = __expf(m1 - mn1);
        m0 = mn0; m1 = mn1;

        float rs0 = 0.f, rs1 = 0.f;
        #pragma unroll
        for (int nt = 0; nt < 8; nt++) {
            sc[nt][0] = __expf(sc[nt][0] - mn0);
            sc[nt][1] = __expf(sc[nt][1] - mn0);
            sc[nt][2] = __expf(sc[nt][2] - mn1);
            sc[nt][3] = __expf(sc[nt][3] - mn1);
            rs0 += sc[nt][0] + sc[nt][1];
            rs1 += sc[nt][2] + sc[nt][3];
        }
        rs0 += __shfl_xor_sync(0xffffffffu, rs0, 1);
        rs0 += __shfl_xor_sync(0xffffffffu, rs0, 2);
        rs1 += __shfl_xor_sync(0xffffffffu, rs1, 1);
        rs1 += __shfl_xor_sync(0xffffffffu, rs1, 2);
        l0 = l0 * a0 + rs0;
        l1 = l1 * a1 + rs1;

        #pragma unroll
        for (int dt = 0; dt < 8; dt++) {
            o_[dt][0] *= a0; o_[dt][1] *= a0;
            o_[dt][2] *= a1; o_[dt][3] *= a1;
        }

        unsigned pf[4][4];
        #pragma unroll
        for (int kt = 0; kt < 4; kt++) {
            #pragma unroll
            for (int half = 0; half < 2; half++) {
                const float* v0 = sc[kt * 2 + half];
                __half2 p01 = __floats2half2_rn(v0[0], v0[1]);
                __half2 p23 = __floats2half2_rn(v0[2], v0[3]);
                pf[kt][half * 2 + 0] = *(unsigned*)&p01;
                pf[kt][half * 2 + 1] = *(unsigned*)&p23;
            }
        }

        const unsigned vbase = kbase + KV_ARR;
        #pragma unroll
        for (int kt = 0; kt < 4; kt++) {
            #pragma unroll
            for (int nt = 0; nt < 8; nt += 2) {
                unsigned va = vbase + (kt * 16 + (lane & 15)) * 144
                            + (nt + ((lane >> 4) & 1)) * 16;
                unsigned b[4];
                ldm_x4t(b, va);
                mma_f16(o_[nt + 0], pf[kt], b);
                mma_f16(o_[nt + 1], pf[kt], b + 2);
            }
        }

        cpa_wait<0>();
        __syncthreads();
    }

    const float i0 = 1.f / l0, i1 = 1.f / l1;
    #pragma unroll
    for (int nt = 0; nt < 8; nt++) {
        int col = h * DKH + nt * 8 + (lane & 3) * 2;
        *(__half2*)(O + (long)r0g * DM + col) =
            __floats2half2_rn(o_[nt][0] * i0, o_[nt][1] * i0);
        *(__half2*)(O + (long)(r0g + 8) * DM + col) =
            __floats2half2_rn(o_[nt][2] * i1, o_[nt][3] * i1);
    }
}

// ============================================================
// LayerNorm over X (+ optional X2 partial); optional fp16 out
// ============================================================
__global__ __launch_bounds__(256) void ln_kernel(
    const float* __restrict__ X, const float* __restrict__ X2,
    const float* __restrict__ g, const float* __restrict__ b,
    float* __restrict__ Y, __half* __restrict__ Yh)
{
    const int r   = blockIdx.x;
    const int tid = threadIdx.x;
    const float* x  = X  + (long)r * DM;
    const float* x2 = X2 ? (X2 + (long)r * DM) : (const float*)0;

    float v[3];
    float s = 0.f, ss = 0.f;
    #pragma unroll
    for (int i = 0; i < 3; i++) {
        int c = tid + i * 256;
        v[i] = x[c] + (x2 ? x2[c] : 0.f);
        s  += v[i];
        ss += v[i] * v[i];
    }
    #pragma unroll
    for (int off = 16; off > 0; off >>= 1) {
        s  += __shfl_xor_sync(0xffffffffu, s,  off);
        ss += __shfl_xor_sync(0xffffffffu, ss, off);
    }
    __shared__ float rs_[8], rss_[8];
    const int lane = tid & 31, wid = tid >> 5;
    if (lane == 0) { rs_[wid] = s; rss_[wid] = ss; }
    __syncthreads();
    float ts = 0.f, tss = 0.f;
    #pragma unroll
    for (int w = 0; w < 8; w++) { ts += rs_[w]; tss += rss_[w]; }

    const float mean = ts * (1.f / 768.f);
    const float var  = tss * (1.f / 768.f) - mean * mean;
    const float rstd = rsqrtf(var + 1e-5f);

    #pragma unroll
    for (int i = 0; i < 3; i++) {
        int c = tid + i * 256;
        float yv = (v[i] - mean) * rstd * g[c] + b[c];
        Y[(long)r * DM + c] = yv;
        if (Yh) Yh[(long)r * DM + c] = __float2half_rn(yv);
    }
}

// ============================================================
extern "C" void kernel_launch(void* const* d_in, const int* in_sizes, int n_in,
                              void* d_out, int out_size)
{
    const float* x   = (const float*)d_in[0];
    const float* Wq  = (const float*)d_in[1];
    const float* bq  = (const float*)d_in[2];
    const float* Wk  = (const float*)d_in[3];
    const float* bk  = (const float*)d_in[4];
    const float* Wv  = (const float*)d_in[5];
    const float* bv  = (const float*)d_in[6];
    const float* Wo  = (const float*)d_in[7];
    const float* bo  = (const float*)d_in[8];
    const float* W1  = (const float*)d_in[9];
    const float* b1  = (const float*)d_in[10];
    const float* W2  = (const float*)d_in[11];
    const float* b2  = (const float*)d_in[12];
    const float* g1  = (const float*)d_in[13];
    const float* be1 = (const float*)d_in[14];
    const float* g2  = (const float*)d_in[15];
    const float* be2 = (const float*)d_in[16];
    float* out = (float*)d_out;

    float *y1, *y1b, *hbuf, *y2, *y2b, *bqkv;
    cudaGetSymbolAddress((void**)&y1,   g_y1);
    cudaGetSymbolAddress((void**)&y1b,  g_y1b);
    cudaGetSymbolAddress((void**)&hbuf, g_h);
    cudaGetSymbolAddress((void**)&y2,   g_y2);
    cudaGetSymbolAddress((void**)&y2b,  g_y2b);
    cudaGetSymbolAddress((void**)&bqkv, g_bqkv);

    __half *x16, *ab, *h16, *f1;
    cudaGetSymbolAddress((void**)&x16, g_x16);
    cudaGetSymbolAddress((void**)&ab,  g_ab);
    cudaGetSymbolAddress((void**)&h16, g_h16);
    cudaGetSymbolAddress((void**)&f1,  g_f1);

    __half *wqkv, *wo, *w1, *w2;
    cudaGetSymbolAddress((void**)&wqkv, g_wqkv);
    cudaGetSymbolAddress((void**)&wo, g_wo);
    cudaGetSymbolAddress((void**)&w1, g_w1);
    cudaGetSymbolAddress((void**)&w2, g_w2);

    __half *qs, *ks, *vs;
    cudaGetSymbolAddress((void**)&qs, g_qs);
    cudaGetSymbolAddress((void**)&ks, g_ks);
    cudaGetSymbolAddress((void**)&vs, g_vs);

    cudaFuncSetAttribute(gemm_h1<2, false, false, false>,
                         cudaFuncAttributeMaxDynamicSharedMemorySize, GSMEM);
    cudaFuncSetAttribute(gemm_h1<0, false, true, true>,
                         cudaFuncAttributeMaxDynamicSharedMemorySize, GSMEM);
    cudaFuncSetAttribute(gemm_h1<1, true, false, false>,
                         cudaFuncAttributeMaxDynamicSharedMemorySize, GSMEM);
    cudaFuncSetAttribute(attn_tc, cudaFuncAttributeMaxDynamicSharedMemorySize, AT_SMEM);

    dim3 tblk(32, 8);
    dim3 blk(256);

    // all weight conversions (one launch) + fconv/bcat (one launch)
    wprep_all<<<6912, tblk>>>(Wq, Wk, Wv, Wo, W1, W2, wqkv, wo, w1, w2);
    prep_misc<<<3081, blk>>>(x, x16, bq, bk, bv, bqkv);

    // fused QKV projection -> head-major fp16 (Q scaled)
    gemm_h1<2, false, false, false><<<dim3(18, 32), blk, GSMEM>>>(
        x16, wqkv, bqkv, nullptr, nullptr, nullptr, nullptr, DM, 3 * DM);

    // attention -> fp16
    attn_tc<<<dim3(TSEQ / 128, NH), blk, AT_SMEM>>>(qs, ks, vs, ab);

    // output projection + residual(x), split-K x2
    gemm_h1<0, false, true, true><<<dim3(6, 32, 2), blk, GSMEM>>>(
        ab, wo, bo, x, y1, y1b, nullptr, DM, DM);

    ln_kernel<<<TSEQ, blk>>>(y1, y1b, g1, be1, hbuf, h16);

    // FFN
    gemm_h1<1, true, false, false><<<dim3(24, 32), blk, GSMEM>>>(
        h16, w1, b1, nullptr, nullptr, nullptr, f1, DM, DFF);
    gemm_h1<0, false, true, true><<<dim3(6, 32, 2), blk, GSMEM>>>(
        f1, w2, b2, hbuf, y2, y2b, nullptr, DFF, DM);

    ln_kernel<<<TSEQ, blk>>>(y2, y2b, g2, be2, out, nullptr);
}

// round 11
// speedup vs baseline: 7.3246x; 1.0175x over previous
#include <cuda_runtime.h>
#include <cuda_fp16.h>

#define TSEQ 4096
#define DM   768
#define NH   12
#define DKH  64
#define DFF  3072
#define NSPLIT_TILES (NH * 16)       // 192 split q-tiles (qb 16..31)

// ---- fp32 scratch ----
__device__ float g_y1  [TSEQ * DM];
__device__ float g_y1b [TSEQ * DM];
__device__ float g_h   [TSEQ * DM];
__device__ float g_y2  [TSEQ * DM];
__device__ float g_y2b [TSEQ * DM];
__device__ float g_bqkv[3 * DM];

// ---- attention split-KV partials ----
__device__ float g_po[2 * NSPLIT_TILES * 128 * 64];
__device__ float g_pm[2 * NSPLIT_TILES * 128];
__device__ float g_pl[2 * NSPLIT_TILES * 128];

// ---- fp16 activations ----
__device__ __half g_x16[TSEQ * DM];
__device__ __half g_ab [TSEQ * DM];
__device__ __half g_h16[TSEQ * DM];
__device__ __half g_f1 [TSEQ * DFF];

// ---- fp16 transposed weights [N, K] ----
__device__ __half g_wqkv[3 * DM * DM];
__device__ __half g_wo  [DM * DM];
__device__ __half g_w1  [DM * DFF];
__device__ __half g_w2  [DM * DFF];

// ---- fp16 QKV, head-major [NH][TSEQ][64] ----
__device__ __half g_qs[NH * TSEQ * DKH];
__device__ __half g_ks[NH * TSEQ * DKH];
__device__ __half g_vs[NH * TSEQ * DKH];

// ============================================================
// helpers
// ============================================================
__device__ __forceinline__ unsigned s2u(const void* p) {
    unsigned a;
    asm("{ .reg .u64 t; cvta.to.shared.u64 t, %1; cvt.u32.u64 %0, t; }"
        : "=r"(a) : "l"(p));
    return a;
}
__device__ __forceinline__ float ex2(float x) {
    float r;
    asm("ex2.approx.f32 %0, %1;" : "=f"(r) : "f"(x));
    return r;
}
__device__ __forceinline__ void ldm_x4(unsigned* r, unsigned addr) {
    asm volatile("ldmatrix.sync.aligned.m8n8.x4.shared.b16 {%0,%1,%2,%3}, [%4];"
                 : "=r"(r[0]), "=r"(r[1]), "=r"(r[2]), "=r"(r[3]) : "r"(addr));
}
__device__ __forceinline__ void ldm_x4t(unsigned* r, unsigned addr) {
    asm volatile("ldmatrix.sync.aligned.m8n8.x4.trans.shared.b16 {%0,%1,%2,%3}, [%4];"
                 : "=r"(r[0]), "=r"(r[1]), "=r"(r[2]), "=r"(r[3]) : "r"(addr));
}
__device__ __forceinline__ void mma_f16(float* c, const unsigned* a, const unsigned* b) {
    asm volatile("mma.sync.aligned.m16n8k16.row.col.f32.f16.f16.f32 "
                 "{%0,%1,%2,%3}, {%4,%5,%6,%7}, {%8,%9}, {%0,%1,%2,%3};"
                 : "+f"(c[0]), "+f"(c[1]), "+f"(c[2]), "+f"(c[3])
                 : "r"(a[0]), "r"(a[1]), "r"(a[2]), "r"(a[3]), "r"(b[0]), "r"(b[1]));
}
__device__ __forceinline__ void cpa16(unsigned dst, const void* src) {
    asm volatile("cp.async.cg.shared.global [%0], [%1], 16;" :: "r"(dst), "l"(src));
}
__device__ __forceinline__ void cpa16ca(unsigned dst, const void* src) {
    asm volatile("cp.async.ca.shared.global [%0], [%1], 16;" :: "r"(dst), "l"(src));
}
__device__ __forceinline__ void cpa_commit() {
    asm volatile("cp.async.commit_group;" ::: "memory");
}
template<int N> __device__ __forceinline__ void cpa_wait() {
    asm volatile("cp.async.wait_group %0;" :: "n"(N) : "memory");
}

// ============================================================
// ONE prep kernel: all weight transposes + x conv + bias concat
// blocks [0,2304): Wq/Wk/Wv/Wo; [2304,4608): W1; [4608,6912): W2
// [6912,9984): fconv; [9984,9993): bcat
// ============================================================
__device__ __forceinline__ void wconv_body(
    const float* __restrict__ W, __half* __restrict__ T,
    int K, int N, int n0, int k0, float t[32][33])
{
    const int tx = threadIdx.x & 31, ty = threadIdx.x >> 5;
    #pragma unroll
    for (int i = 0; i < 4; i++)
        t[ty + i * 8][tx] = W[(long)(k0 + ty + i * 8) * N + n0 + tx];
    __syncthreads();
    #pragma unroll
    for (int i = 0; i < 4; i++) {
        int n = n0 + ty + i * 8;
        T[(long)n * K + k0 + tx] = __float2half_rn(t[tx][ty + i * 8]);
    }
}
__global__ __launch_bounds__(256) void prep_all(
    const float* __restrict__ Wq, const float* __restrict__ Wk,
    const float* __restrict__ Wv, const float* __restrict__ Wo,
    const float* __restrict__ W1, const float* __restrict__ W2,
    __half* __restrict__ qkv, __half* __restrict__ wo,
    __half* __restrict__ w1, __half* __restrict__ w2,
    const float* __restrict__ X, __half* __restrict__ H,
    const float* __restrict__ bq, const float* __restrict__ bk,
    const float* __restrict__ bv, float* __restrict__ bdst)
{
    __shared__ float t[32][33];
    int bid = blockIdx.x;
    if (bid < 2304) {
        int z = bid / 576, r = bid % 576;
        const float* W = (z == 0) ? Wq : (z == 1) ? Wk : (z == 2) ? Wv : Wo;
        __half* T = (z < 3) ? (qkv + (long)z * DM * DM) : wo;
        wconv_body(W, T, DM, DM, (r % 24) * 32, (r / 24) * 32, t);
    } else if (bid < 4608) {
        int r = bid - 2304;
        wconv_body(W1, w1, DM, DFF, (r % 96) * 32, (r / 96) * 32, t);
    } else if (bid < 6912) {
        int r = bid - 4608;
        wconv_body(W2, w2, DFF, DM, (r % 24) * 32, (r / 24) * 32, t);
    } else if (bid < 9984) {
        long idx = ((long)(bid - 6912) * 256 + threadIdx.x) * 4;
        float4 v = *(const float4*)(X + idx);
        *(__half2*)(H + idx)     = __floats2half2_rn(v.x, v.y);
        *(__half2*)(H + idx + 2) = __floats2half2_rn(v.z, v.w);
    } else {
        int i = (bid - 9984) * 256 + threadIdx.x;
        if (i < 3 * DM) {
            float v = (i < DM) ? bq[i] : (i < 2 * DM) ? bk[i - DM] : bv[i - 2 * DM];
            bdst[i] = v;
        }
    }
}

// ============================================================
// fp16 GEMM (unchanged from R10)
// ============================================================
#define BKC   32
#define ASTR  40
#define SEG   10240
#define STGB  (2 * SEG)
#define GSMEM (3 * STGB)

template<int MODE, bool RELU, bool HASRES, bool SPLITK>
__global__ __launch_bounds__(256, 2)
void gemm_h1(const __half* __restrict__ A, const __half* __restrict__ B,
             const float* __restrict__ bias, const float* __restrict__ res,
             float* __restrict__ Cf, float* __restrict__ Cf2,
             __half* __restrict__ Ch, int K, int N)
{
    extern __shared__ __align__(128) char smem[];
    const int tid   = threadIdx.x;
    const int wid   = tid >> 5;
    const int lane  = tid & 31;
    const int warpM = wid & 1;
    const int warpN = wid >> 1;
    const int brow  = blockIdx.y * 128;
    const int bcol  = blockIdx.x * 128;
    const int kz    = SPLITK ? (int)blockIdx.z : 0;
    const int Keff  = SPLITK ? (K >> 1) : K;
    const int koff  = kz * Keff;
    const unsigned smu = s2u(smem);

    const char* src[2] = { (const char*)A, (const char*)B };

    float acc[4][4][4];
    #pragma unroll
    for (int mi = 0; mi < 4; mi++)
        #pragma unroll
        for (int ni = 0; ni < 4; ni++)
            #pragma unroll
            for (int r = 0; r < 4; r++) acc[mi][ni][r] = 0.f;

    const int nch = Keff / BKC;

    auto load_stage = [&](int s, int kc) {
        #pragma unroll
        for (int it = 0; it < 4; it++) {
            int idx = tid + it * 256;
            int arr = idx >> 9, rem = idx & 511;
            int row = rem >> 2, ch = rem & 3;
            int base_row = (arr == 0) ? (brow + row) : (bcol + row);
            cpa16(smu + s * STGB + arr * SEG + row * 80 + ch * 16,
                  src[arr] + ((long)base_row * K + koff + kc) * 2 + ch * 16);
        }
    };

    load_stage(0, 0);
    cpa_commit();
    if (nch > 1) { load_stage(1, BKC); cpa_commit(); }

    int s = 0;
    for (int c = 0; c < nch; ++c) {
        cpa_wait<1>();
        __syncthreads();
        if (c + 2 < nch) {
            int s2 = s + 2; if (s2 >= 3) s2 -= 3;
            load_stage(s2, (c + 2) * BKC);
            cpa_commit();
        }

        const unsigned uA = smu + s * STGB;
        const unsigned uB = uA + SEG;

        #pragma unroll
        for (int kk = 0; kk < 2; kk++) {
            unsigned a[4][4];
            #pragma unroll
            for (int mi = 0; mi < 4; mi++) {
                unsigned rowoff =
                    (unsigned)(((warpM * 64 + mi * 16 + (lane & 15)) * ASTR
                                + (lane >> 4) * 8 + kk * 16) * 2);
                ldm_x4(a[mi], uA + rowoff);
            }
            #pragma unroll
            for (int ni = 0; ni < 4; ni += 2) {
                unsigned boff =
                    (unsigned)(((warpN * 32 + (ni + ((lane >> 4) & 1)) * 8 + (lane & 7)) * ASTR
                                + ((lane >> 3) & 1) * 8 + kk * 16) * 2);
                unsigned b[4];
                ldm_x4(b, uB + boff);
                #pragma unroll
                for (int mi = 0; mi < 4; mi++) {
                    mma_f16(acc[mi][ni + 0], a[mi], b);
                    mma_f16(acc[mi][ni + 1], a[mi], b + 2);
                }
            }
        }
        if (++s >= 3) s -= 3;
    }

    #pragma unroll
    for (int mi = 0; mi < 4; mi++) {
        #pragma unroll
        for (int half = 0; half < 2; half++) {
            const int row = brow + warpM * 64 + mi * 16 + (lane >> 2) + half * 8;
            #pragma unroll
            for (int ni = 0; ni < 4; ni++) {
                const int col = bcol + warpN * 32 + ni * 8 + (lane & 3) * 2;
                float2 o;
                o.x = acc[mi][ni][half * 2 + 0];
                o.y = acc[mi][ni][half * 2 + 1];
                if (SPLITK && kz == 1) {
                    *(float2*)(Cf2 + (long)row * N + col) = o;
                    continue;
                }
                o.x += bias[col + 0];
                o.y += bias[col + 1];
                if (RELU) { o.x = fmaxf(o.x, 0.f); o.y = fmaxf(o.y, 0.f); }
                if (HASRES) {
                    float2 r = *(const float2*)(res + (long)row * N + col);
                    o.x += r.x; o.y += r.y;
                }
                if (MODE == 0) {
                    *(float2*)(Cf + (long)row * N + col) = o;
                } else if (MODE == 1) {
                    *(__half2*)(Ch + (long)row * N + col) = __floats2half2_rn(o.x, o.y);
                } else {
                    int kind = (col >= 2 * DM) ? 2 : ((col >= DM) ? 1 : 0);
                    int cm   = col - kind * DM;
                    // Q scale folds 1/sqrt(64) * log2(e) for exp2-softmax
                    if (kind == 0) { o.x *= 0.180336880f; o.y *= 0.180336880f; }
                    int hh = cm >> 6, dd = cm & 63;
                    long off = ((long)hh * TSEQ + row) * DKH + dd;
                    __half2 v = __floats2half2_rn(o.x, o.y);
                    if (kind == 0)      *(__half2*)(g_qs + off) = v;
                    else if (kind == 1) *(__half2*)(g_ks + off) = v;
                    else                *(__half2*)(g_vs + off) = v;
                }
            }
        }
    }
}

// ============================================================
// Tensor-core flash attention, causal, fp16, split-KV.
// grid.x = 48: x<32 -> split pieces (qb=31-(x>>1), piece=x&1);
// x>=32 -> unsplit qb = 15-(x-32). All exp in exp2 domain.
// ============================================================
#define SM_Q    (128 * 144)
#define KV_ARR  (64 * 144)
#define KV_STG  (2 * KV_ARR)
#define AT_SMEM (SM_Q + 2 * KV_STG)

__global__ __launch_bounds__(256, 2)
void attn_tc(const __half* __restrict__ Qs, const __half* __restrict__ Ks,
             const __half* __restrict__ Vs, __half* __restrict__ O,
             float* __restrict__ po, float* __restrict__ pm,
             float* __restrict__ pl)
{
    extern __shared__ __align__(16) char sm[];
    const unsigned smu = s2u(sm);
    const int tid  = threadIdx.x;
    const int lane = tid & 31;
    const int wq   = tid >> 5;
    const int xi   = blockIdx.x;
    const int h    = blockIdx.y;
    const long hb  = (long)h * TSEQ * DKH;

    int qb, kb0, kb1, piece;
    bool split;
    if (xi < 32) {
        qb = 31 - (xi >> 1); piece = xi & 1; split = true;
        const int half = qb + 1;
        kb0 = piece * half; kb1 = kb0 + half;
    } else {
        qb = 15 - (xi - 32); piece = 0; split = false;
        kb0 = 0; kb1 = 2 * (qb + 1);
    }

    {
        const char* sq = (const char*)(Qs + hb + (long)qb * 128 * DKH);
        #pragma unroll
        for (int it = 0; it < 4; it++) {
            int idx = tid + it * 256;
            int row = idx >> 3, ch = idx & 7;
            cpa16ca(smu + row * 144 + ch * 16, sq + row * 128 + ch * 16);
        }
    }
    const char* kvsrc[2] = { (const char*)(Ks + hb), (const char*)(Vs + hb) };
    {
        const long kboff = (long)kb0 * 64;
        #pragma unroll
        for (int it = 0; it < 4; it++) {
            int idx = tid + it * 256;
            int arr = idx >> 9, rem = idx & 511;
            int row = rem >> 3, ch = rem & 7;
            cpa16ca(smu + SM_Q + arr * KV_ARR + row * 144 + ch * 16,
                    kvsrc[arr] + (kboff + row) * 128 + ch * 16);
        }
    }
    cpa_commit();
    cpa_wait<0>();
    __syncthreads();

    unsigned qf[4][4];
    #pragma unroll
    for (int kt = 0; kt < 4; kt++) {
        unsigned a = smu + (wq * 16 + (lane & 15)) * 144
                   + ((lane >> 4) * 8 + kt * 16) * 2;
        ldm_x4(qf[kt], a);
    }

    float o_[8][4];
    #pragma unroll
    for (int i = 0; i < 8; i++)
        #pragma unroll
        for (int j = 0; j < 4; j++) o_[i][j] = 0.f;
    float m0 = -1e30f, m1 = -1e30f, l0 = 0.f, l1 = 0.f;

    const int diagKb = (qb * 128 + wq * 16) >> 6;
    const int r0g    = qb * 128 + wq * 16 + (lane >> 2);

    for (int kb = kb0; kb < kb1; kb++) {
        const int s = (kb - kb0) & 1;

        if (kb + 1 < kb1) {
            const long kbn = (long)(kb + 1) * 64;
            #pragma unroll
            for (int it = 0; it < 4; it++) {
                int idx = tid + it * 256;
                int arr = idx >> 9, rem = idx & 511;
                int row = rem >> 3, ch = rem & 7;
                cpa16ca(smu + SM_Q + (s ^ 1) * KV_STG + arr * KV_ARR + row * 144 + ch * 16,
                        kvsrc[arr] + (kbn + row) * 128 + ch * 16);
            }
        }
        cpa_commit();

        float sc[8][4];
        #pragma unroll
        for (int i = 0; i < 8; i++)
            #pragma unroll
            for (int j = 0; j < 4; j++) sc[i][j] = 0.f;

        const unsigned kbase = smu + SM_Q + s * KV_STG;
        #pragma unroll
        for (int kt = 0; kt < 4; kt++) {
            #pragma unroll
            for (int nt = 0; nt < 8; nt += 2) {
                unsigned ka = kbase
                    + ((nt + ((lane >> 4) & 1)) * 8 + (lane & 7)) * 144
                    + (((lane >> 3) & 1) * 8 + kt * 16) * 2;
                unsigned b[4];
                ldm_x4(b, ka);
                mma_f16(sc[nt + 0], qf[kt], b);
                mma_f16(sc[nt + 1], qf[kt], b + 2);
            }
        }

        if (kb >= diagKb) {
            #pragma unroll
            for (int nt = 0; nt < 8; nt++) {
                int keyb = kb * 64 + nt * 8 + (lane & 3) * 2;
                #pragma unroll
                for (int c = 0; c < 4; c++) {
                    int key = keyb + (c & 1);
                    int row = r0g + (c >> 1) * 8;
                    if (key > row) sc[nt][c] = -1e30f;
                }
            }
        }

        float pm0 = -1e30f, pm1 = -1e30f;
        #pragma unroll
        for (int nt = 0; nt < 8; nt++) {
            pm0 = fmaxf(pm0, fmaxf(sc[nt][0], sc[nt][1]));
            pm1 = fmaxf(pm1, fmaxf(sc[nt][2], sc[nt][3]));
        }
        pm0 = fmaxf(pm0, __shfl_xor_sync(0xffffffffu, pm0, 1));
        pm0 = fmaxf(pm0, __shfl_xor_sync(0xffffffffu, pm0, 2));
        pm1 = fmaxf(pm1, __shfl_xor_sync(0xffffffffu, pm1, 1));
        pm1 = fmaxf(pm1, __shfl_xor_sync(0xffffffffu, pm1, 2));

        float mn0 = fmaxf(m0, pm0), mn1 = fmaxf(m1, pm1);
        float a0 = ex2(m0 - mn0), a1 = ex2(m1 - mn1);
        m0 = mn0; m1 = mn1;

        float rs0 = 0.f, rs1 = 0.f;
        #pragma unroll
        for (int nt = 0; nt < 8; nt++) {
            sc[nt][0] = ex2(sc[nt][0] - mn0);
            sc[nt][1] = ex2(sc[nt][1] - mn0);
            sc[nt][2] = ex2(sc[nt][2] - mn1);
            sc[nt][3] = ex2(sc[nt][3] - mn1);
            rs0 += sc[nt][0] + sc[nt][1];
            rs1 += sc[nt][2] + sc[nt][3];
        }
        rs0 += __shfl_xor_sync(0xffffffffu, rs0, 1);
        rs0 += __shfl_xor_sync(0xffffffffu, rs0, 2);
        rs1 += __shfl_xor_sync(0xffffffffu, rs1, 1);
        rs1 += __shfl_xor_sync(0xffffffffu, rs1, 2);
        l0 = l0 * a0 + rs0;
        l1 = l1 * a1 + rs1;

        #pragma unroll
        for (int dt = 0; dt < 8; dt++) {
            o_[dt][0] *= a0; o_[dt][1] *= a0;
            o_[dt][2] *= a1; o_[dt][3] *= a1;
        }

        unsigned pf[4][4];
        #pragma unroll
        for (int kt = 0; kt < 4; kt++) {
            #pragma unroll
            for (int half = 0; half < 2; half++) {
                const float* v0 = sc[kt * 2 + half];
                __half2 p01 = __floats2half2_rn(v0[0], v0[1]);
                __half2 p23 = __floats2half2_rn(v0[2], v0[3]);
                pf[kt][half * 2 + 0] = *(unsigned*)&p01;
                pf[kt][half * 2 + 1] = *(unsigned*)&p23;
            }
        }

        const unsigned vbase = kbase + KV_ARR;
        #pragma unroll
        for (int kt = 0; kt < 4; kt++) {
            #pragma unroll
            for (int nt = 0; nt < 8; nt += 2) {
                unsigned va = vbase + (kt * 16 + (lane & 15)) * 144
                            + (nt + ((lane >> 4) & 1)) * 16;
                unsigned b[4];
                ldm_x4t(b, va);
                mma_f16(o_[nt + 0], pf[kt], b);
                mma_f16(o_[nt + 1], pf[kt], b + 2);
            }
        }

        cpa_wait<0>();
        __syncthreads();
    }

    if (!split) {
        const float i0 = 1.f / l0, i1 = 1.f / l1;
        #pragma unroll
        for (int nt = 0; nt < 8; nt++) {
            int col = h * DKH + nt * 8 + (lane & 3) * 2;
            *(__half2*)(O + (long)r0g * DM + col) =
                __floats2half2_rn(o_[nt][0] * i0, o_[nt][1] * i0);
            *(__half2*)(O + (long)(r0g + 8) * DM + col) =
                __floats2half2_rn(o_[nt][2] * i1, o_[nt][3] * i1);
        }
    } else {
        const int tile = h * 16 + (qb - 16);
        const int lr   = wq * 16 + (lane >> 2);
        float* pob = po + ((long)(piece * NSPLIT_TILES + tile) * 128) * 64;
        #pragma unroll
        for (int nt = 0; nt < 8; nt++) {
            int col = nt * 8 + (lane & 3) * 2;
            *(float2*)(pob + (long)lr * 64 + col)       = make_float2(o_[nt][0], o_[nt][1]);
            *(float2*)(pob + (long)(lr + 8) * 64 + col) = make_float2(o_[nt][2], o_[nt][3]);
        }
        if ((lane & 3) == 0) {
            long mb = (long)(piece * NSPLIT_TILES + tile) * 128;
            pm[mb + lr]     = m0;  pl[mb + lr]     = l0;
            pm[mb + lr + 8] = m1;  pl[mb + lr + 8] = l1;
        }
    }
}

// ============================================================
// Combine split-KV partials -> fp16 O
// grid = 192 tiles; 256 threads: thread t -> row t>>1, col half t&1
// ============================================================
__global__ __launch_bounds__(256) void attn_combine(
    const float* __restrict__ po, const float* __restrict__ pm,
    const float* __restrict__ pl, __half* __restrict__ O)
{
    const int tile = blockIdx.x;
    const int tid  = threadIdx.x;
    const int row  = tid >> 1;
    const int ch   = tid & 1;               // 0 or 1 -> 32-col half
    const int h    = tile / 16;
    const int qb   = 16 + (tile % 16);

    const long mb0 = (long)tile * 128 + row;
    const long mb1 = (long)(NSPLIT_TILES + tile) * 128 + row;
    float m0 = pm[mb0], l0 = pl[mb0];
    float m1 = pm[mb1], l1 = pl[mb1];
    float mx = fmaxf(m0, m1);
    float w0 = ex2(m0 - mx), w1 = ex2(m1 - mx);
    float inv = 1.f / (w0 * l0 + w1 * l1);
    w0 *= inv; w1 *= inv;

    const float* a = po + ((long)tile * 128 + row) * 64 + ch * 32;
    const float* b = po + ((long)(NSPLIT_TILES + tile) * 128 + row) * 64 + ch * 32;
    __half* dst = O + (long)(qb * 128 + row) * DM + h * DKH + ch * 32;
    #pragma unroll
    for (int c = 0; c < 32; c += 4) {
        float4 av = *(const float4*)(a + c);
        float4 bv = *(const float4*)(b + c);
        *(__half2*)(dst + c)     = __floats2half2_rn(w0 * av.x + w1 * bv.x,
                                                     w0 * av.y + w1 * bv.y);
        *(__half2*)(dst + c + 2) = __floats2half2_rn(w0 * av.z + w1 * bv.z,
                                                     w0 * av.w + w1 * bv.w);
    }
}

// ============================================================
// LayerNorm over X (+ optional X2 partial); optional fp16 out
// ============================================================
__global__ __launch_bounds__(256) void ln_kernel(
    const float* __restrict__ X, const float* __restrict__ X2,
    const float* __restrict__ g, const float* __restrict__ b,
    float* __restrict__ Y, __half* __restrict__ Yh)
{
    const int r   = blockIdx.x;
    const int tid = threadIdx.x;
    const float* x  = X  + (long)r * DM;
    const float* x2 = X2 ? (X2 + (long)r * DM) : (const float*)0;

    float v[3];
    float s = 0.f, ss = 0.f;
    #pragma unroll
    for (int i = 0; i < 3; i++) {
        int c = tid + i * 256;
        v[i] = x[c] + (x2 ? x2[c] : 0.f);
        s  += v[i];
        ss += v[i] * v[i];
    }
    #pragma unroll
    for (int off = 16; off > 0; off >>= 1) {
        s  += __shfl_xor_sync(0xffffffffu, s,  off);
        ss += __shfl_xor_sync(0xffffffffu, ss, off);
    }
    __shared__ float rs_[8], rss_[8];
    const int lane = tid & 31, wid = tid >> 5;
    if (lane == 0) { rs_[wid] = s; rss_[wid] = ss; }
    __syncthreads();
    float ts = 0.f, tss = 0.f;
    #pragma unroll
    for (int w = 0; w < 8; w++) { ts += rs_[w]; tss += rss_[w]; }

    const float mean = ts * (1.f / 768.f);
    const float var  = tss * (1.f / 768.f) - mean * mean;
    const float rstd = rsqrtf(var + 1e-5f);

    #pragma unroll
    for (int i = 0; i < 3; i++) {
        int c = tid + i * 256;
        float yv = (v[i] - mean) * rstd * g[c] + b[c];
        Y[(long)r * DM + c] = yv;
        if (Yh) Yh[(long)r * DM + c] = __float2half_rn(yv);
    }
}

// ============================================================
extern "C" void kernel_launch(void* const* d_in, const int* in_sizes, int n_in,
                              void* d_out, int out_size)
{
    const float* x   = (const float*)d_in[0];
    const float* Wq  = (const float*)d_in[1];
    const float* bq  = (const float*)d_in[2];
    const float* Wk  = (const float*)d_in[3];
    const float* bk  = (const float*)d_in[4];
    const float* Wv  = (const float*)d_in[5];
    const float* bv  = (const float*)d_in[6];
    const float* Wo  = (const float*)d_in[7];
    const float* bo  = (const float*)d_in[8];
    const float* W1  = (const float*)d_in[9];
    const float* b1  = (const float*)d_in[10];
    const float* W2  = (const float*)d_in[11];
    const float* b2  = (const float*)d_in[12];
    const float* g1  = (const float*)d_in[13];
    const float* be1 = (const float*)d_in[14];
    const float* g2  = (const float*)d_in[15];
    const float* be2 = (const float*)d_in[16];
    float* out = (float*)d_out;

    float *y1, *y1b, *hbuf, *y2, *y2b, *bqkv, *po, *pmv, *plv;
    cudaGetSymbolAddress((void**)&y1,   g_y1);
    cudaGetSymbolAddress((void**)&y1b,  g_y1b);
    cudaGetSymbolAddress((void**)&hbuf, g_h);
    cudaGetSymbolAddress((void**)&y2,   g_y2);
    cudaGetSymbolAddress((void**)&y2b,  g_y2b);
    cudaGetSymbolAddress((void**)&bqkv, g_bqkv);
    cudaGetSymbolAddress((void**)&po,   g_po);
    cudaGetSymbolAddress((void**)&pmv,  g_pm);
    cudaGetSymbolAddress((void**)&plv,  g_pl);

    __half *x16, *ab, *h16, *f1;
    cudaGetSymbolAddress((void**)&x16, g_x16);
    cudaGetSymbolAddress((void**)&ab,  g_ab);
    cudaGetSymbolAddress((void**)&h16, g_h16);
    cudaGetSymbolAddress((void**)&f1,  g_f1);

    __half *wqkv, *wo, *w1, *w2;
    cudaGetSymbolAddress((void**)&wqkv, g_wqkv);
    cudaGetSymbolAddress((void**)&wo, g_wo);
    cudaGetSymbolAddress((void**)&w1, g_w1);
    cudaGetSymbolAddress((void**)&w2, g_w2);

    __half *qs, *ks, *vs;
    cudaGetSymbolAddress((void**)&qs, g_qs);
    cudaGetSymbolAddress((void**)&ks, g_ks);
    cudaGetSymbolAddress((void**)&vs, g_vs);

    cudaFuncSetAttribute(gemm_h1<2, false, false, false>,
                         cudaFuncAttributeMaxDynamicSharedMemorySize, GSMEM);
    cudaFuncSetAttribute(gemm_h1<0, false, true, true>,
                         cudaFuncAttributeMaxDynamicSharedMemorySize, GSMEM);
    cudaFuncSetAttribute(gemm_h1<1, true, false, false>,
                         cudaFuncAttributeMaxDynamicSharedMemorySize, GSMEM);
    cudaFuncSetAttribute(attn_tc, cudaFuncAttributeMaxDynamicSharedMemorySize, AT_SMEM);

    dim3 blk(256);

    // one prep launch: weights + x conv + bias concat
    prep_all<<<9993, blk>>>(Wq, Wk, Wv, Wo, W1, W2, wqkv, wo, w1, w2,
                            x, x16, bq, bk, bv, bqkv);

    // fused QKV projection -> head-major fp16 (Q scaled by 0.125*log2e)
    gemm_h1<2, false, false, false><<<dim3(18, 32), blk, GSMEM>>>(
        x16, wqkv, bqkv, nullptr, nullptr, nullptr, nullptr, DM, 3 * DM);

    // attention (split-KV) + combine
    attn_tc<<<dim3(48, NH), blk, AT_SMEM>>>(qs, ks, vs, ab, po, pmv, plv);
    attn_combine<<<NSPLIT_TILES, blk>>>(po, pmv, plv, ab);

    // output projection + residual(x), split-K x2
    gemm_h1<0, false, true, true><<<dim3(6, 32, 2), blk, GSMEM>>>(
        ab, wo, bo, x, y1, y1b, nullptr, DM, DM);

    ln_kernel<<<TSEQ, blk>>>(y1, y1b, g1, be1, hbuf, h16);

    // FFN
    gemm_h1<1, true, false, false><<<dim3(24, 32), blk, GSMEM>>>(
        h16, w1, b1, nullptr, nullptr, nullptr, f1, DM, DFF);
    gemm_h1<0, false, true, true><<<dim3(6, 32, 2), blk, GSMEM>>>(
        f1, w2, b2, hbuf, y2, y2b, nullptr, DFF, DM);

    ln_kernel<<<TSEQ, blk>>>(y2, y2b, g2, be2, out, nullptr);
}

// round 12
// speedup vs baseline: 8.0862x; 1.1040x over previous
#include <cuda_runtime.h>
#include <cuda_fp16.h>

#define TSEQ 4096
#define DM   768
#define NH   12
#define DKH  64
#define DFF  3072
#define NSPLIT_TILES (NH * 16)       // 192 split q-tiles (qb 16..31)

// ---- fp32 scratch ----
__device__ float g_y1  [TSEQ * DM];
__device__ float g_y1b [TSEQ * DM];
__device__ float g_h   [TSEQ * DM];
__device__ float g_y2  [TSEQ * DM];
__device__ float g_y2b [TSEQ * DM];
__device__ float g_bqkv[3 * DM];

// ---- attention split-KV partials ----
__device__ float g_po[2 * NSPLIT_TILES * 128 * 64];
__device__ float g_pm[2 * NSPLIT_TILES * 128];
__device__ float g_pl[2 * NSPLIT_TILES * 128];

// ---- fp16 activations ----
__device__ __half g_x16[TSEQ * DM];
__device__ __half g_ab [TSEQ * DM];
__device__ __half g_h16[TSEQ * DM];
__device__ __half g_f1 [TSEQ * DFF];

// ---- fp16 transposed weights [N, K] ----
__device__ __half g_wqkv[3 * DM * DM];
__device__ __half g_wo  [DM * DM];
__device__ __half g_w1  [DM * DFF];
__device__ __half g_w2  [DM * DFF];

// ---- fp16 QKV, head-major [NH][TSEQ][64] ----
__device__ __half g_qs[NH * TSEQ * DKH];
__device__ __half g_ks[NH * TSEQ * DKH];
__device__ __half g_vs[NH * TSEQ * DKH];

// ============================================================
// helpers
// ============================================================
__device__ __forceinline__ unsigned s2u(const void* p) {
    unsigned a;
    asm("{ .reg .u64 t; cvta.to.shared.u64 t, %1; cvt.u32.u64 %0, t; }"
        : "=r"(a) : "l"(p));
    return a;
}
__device__ __forceinline__ float ex2(float x) {
    float r;
    asm("ex2.approx.f32 %0, %1;" : "=f"(r) : "f"(x));
    return r;
}
__device__ __forceinline__ void ldm_x4(unsigned* r, unsigned addr) {
    asm volatile("ldmatrix.sync.aligned.m8n8.x4.shared.b16 {%0,%1,%2,%3}, [%4];"
                 : "=r"(r[0]), "=r"(r[1]), "=r"(r[2]), "=r"(r[3]) : "r"(addr));
}
__device__ __forceinline__ void ldm_x4t(unsigned* r, unsigned addr) {
    asm volatile("ldmatrix.sync.aligned.m8n8.x4.trans.shared.b16 {%0,%1,%2,%3}, [%4];"
                 : "=r"(r[0]), "=r"(r[1]), "=r"(r[2]), "=r"(r[3]) : "r"(addr));
}
__device__ __forceinline__ void mma_f16(float* c, const unsigned* a, const unsigned* b) {
    asm volatile("mma.sync.aligned.m16n8k16.row.col.f32.f16.f16.f32 "
                 "{%0,%1,%2,%3}, {%4,%5,%6,%7}, {%8,%9}, {%0,%1,%2,%3};"
                 : "+f"(c[0]), "+f"(c[1]), "+f"(c[2]), "+f"(c[3])
                 : "r"(a[0]), "r"(a[1]), "r"(a[2]), "r"(a[3]), "r"(b[0]), "r"(b[1]));
}
__device__ __forceinline__ void cpa16(unsigned dst, const void* src) {
    asm volatile("cp.async.cg.shared.global [%0], [%1], 16;" :: "r"(dst), "l"(src));
}
__device__ __forceinline__ void cpa16ca(unsigned dst, const void* src) {
    asm volatile("cp.async.ca.shared.global [%0], [%1], 16;" :: "r"(dst), "l"(src));
}
__device__ __forceinline__ void cpa_commit() {
    asm volatile("cp.async.commit_group;" ::: "memory");
}
template<int N> __device__ __forceinline__ void cpa_wait() {
    asm volatile("cp.async.wait_group %0;" :: "n"(N) : "memory");
}

// ============================================================
// ONE prep kernel (unchanged from R11)
// ============================================================
__device__ __forceinline__ void wconv_body(
    const float* __restrict__ W, __half* __restrict__ T,
    int K, int N, int n0, int k0, float t[32][33])
{
    const int tx = threadIdx.x & 31, ty = threadIdx.x >> 5;
    #pragma unroll
    for (int i = 0; i < 4; i++)
        t[ty + i * 8][tx] = W[(long)(k0 + ty + i * 8) * N + n0 + tx];
    __syncthreads();
    #pragma unroll
    for (int i = 0; i < 4; i++) {
        int n = n0 + ty + i * 8;
        T[(long)n * K + k0 + tx] = __float2half_rn(t[tx][ty + i * 8]);
    }
}
__global__ __launch_bounds__(256) void prep_all(
    const float* __restrict__ Wq, const float* __restrict__ Wk,
    const float* __restrict__ Wv, const float* __restrict__ Wo,
    const float* __restrict__ W1, const float* __restrict__ W2,
    __half* __restrict__ qkv, __half* __restrict__ wo,
    __half* __restrict__ w1, __half* __restrict__ w2,
    const float* __restrict__ X, __half* __restrict__ H,
    const float* __restrict__ bq, const float* __restrict__ bk,
    const float* __restrict__ bv, float* __restrict__ bdst)
{
    __shared__ float t[32][33];
    int bid = blockIdx.x;
    if (bid < 2304) {
        int z = bid / 576, r = bid % 576;
        const float* W = (z == 0) ? Wq : (z == 1) ? Wk : (z == 2) ? Wv : Wo;
        __half* T = (z < 3) ? (qkv + (long)z * DM * DM) : wo;
        wconv_body(W, T, DM, DM, (r % 24) * 32, (r / 24) * 32, t);
    } else if (bid < 4608) {
        int r = bid - 2304;
        wconv_body(W1, w1, DM, DFF, (r % 96) * 32, (r / 96) * 32, t);
    } else if (bid < 6912) {
        int r = bid - 4608;
        wconv_body(W2, w2, DFF, DM, (r % 24) * 32, (r / 24) * 32, t);
    } else if (bid < 9984) {
        long idx = ((long)(bid - 6912) * 256 + threadIdx.x) * 4;
        float4 v = *(const float4*)(X + idx);
        *(__half2*)(H + idx)     = __floats2half2_rn(v.x, v.y);
        *(__half2*)(H + idx + 2) = __floats2half2_rn(v.z, v.w);
    } else {
        int i = (bid - 9984) * 256 + threadIdx.x;
        if (i < 3 * DM) {
            float v = (i < DM) ? bq[i] : (i < 2 * DM) ? bk[i - DM] : bv[i - 2 * DM];
            bdst[i] = v;
        }
    }
}

// ============================================================
// fp16 GEMM: BKC=64, 3-stage cp.async pipeline (108KB smem)
// ============================================================
#define BKC   64
#define ASTR  72                    // halves; 144 B row stride
#define SEG   18432                 // 128 rows * 144 B
#define STGB  (2 * SEG)             // 36864 per stage
#define GSMEM (3 * STGB)            // 110592 (3 stages)

template<int MODE, bool RELU, bool HASRES, bool SPLITK>
__global__ __launch_bounds__(256, 2)
void gemm_h1(const __half* __restrict__ A, const __half* __restrict__ B,
             const float* __restrict__ bias, const float* __restrict__ res,
             float* __restrict__ Cf, float* __restrict__ Cf2,
             __half* __restrict__ Ch, int K, int N)
{
    extern __shared__ __align__(128) char smem[];
    const int tid   = threadIdx.x;
    const int wid   = tid >> 5;
    const int lane  = tid & 31;
    const int warpM = wid & 1;
    const int warpN = wid >> 1;
    const int brow  = blockIdx.y * 128;
    const int bcol  = blockIdx.x * 128;
    const int kz    = SPLITK ? (int)blockIdx.z : 0;
    const int Keff  = SPLITK ? (K >> 1) : K;
    const int koff  = kz * Keff;
    const unsigned smu = s2u(smem);

    const char* src[2] = { (const char*)A, (const char*)B };

    float acc[4][4][4];
    #pragma unroll
    for (int mi = 0; mi < 4; mi++)
        #pragma unroll
        for (int ni = 0; ni < 4; ni++)
            #pragma unroll
            for (int r = 0; r < 4; r++) acc[mi][ni][r] = 0.f;

    const int nch = Keff / BKC;

    // 2048 cp.async16 per stage / 256 threads = 8 each
    auto load_stage = [&](int s, int kc) {
        #pragma unroll
        for (int it = 0; it < 8; it++) {
            int idx = tid + it * 256;
            int arr = idx >> 10, rem = idx & 1023;
            int row = rem >> 3, ch = rem & 7;
            int base_row = (arr == 0) ? (brow + row) : (bcol + row);
            cpa16(smu + s * STGB + arr * SEG + row * 144 + ch * 16,
                  src[arr] + ((long)base_row * K + koff + kc) * 2 + ch * 16);
        }
    };

    load_stage(0, 0);
    cpa_commit();
    if (nch > 1) { load_stage(1, BKC); cpa_commit(); }

    int s = 0;
    for (int c = 0; c < nch; ++c) {
        cpa_wait<1>();
        __syncthreads();
        if (c + 2 < nch) {
            int s2 = s + 2; if (s2 >= 3) s2 -= 3;
            load_stage(s2, (c + 2) * BKC);
            cpa_commit();
        }

        const unsigned uA = smu + s * STGB;
        const unsigned uB = uA + SEG;

        #pragma unroll
        for (int kk = 0; kk < 4; kk++) {
            unsigned a[4][4];
            #pragma unroll
            for (int mi = 0; mi < 4; mi++) {
                unsigned rowoff =
                    (unsigned)(((warpM * 64 + mi * 16 + (lane & 15)) * ASTR
                                + (lane >> 4) * 8 + kk * 16) * 2);
                ldm_x4(a[mi], uA + rowoff);
            }
            #pragma unroll
            for (int ni = 0; ni < 4; ni += 2) {
                unsigned boff =
                    (unsigned)(((warpN * 32 + (ni + ((lane >> 4) & 1)) * 8 + (lane & 7)) * ASTR
                                + ((lane >> 3) & 1) * 8 + kk * 16) * 2);
                unsigned b[4];
                ldm_x4(b, uB + boff);
                #pragma unroll
                for (int mi = 0; mi < 4; mi++) {
                    mma_f16(acc[mi][ni + 0], a[mi], b);
                    mma_f16(acc[mi][ni + 1], a[mi], b + 2);
                }
            }
        }
        if (++s >= 3) s -= 3;
    }

    #pragma unroll
    for (int mi = 0; mi < 4; mi++) {
        #pragma unroll
        for (int half = 0; half < 2; half++) {
            const int row = brow + warpM * 64 + mi * 16 + (lane >> 2) + half * 8;
            #pragma unroll
            for (int ni = 0; ni < 4; ni++) {
                const int col = bcol + warpN * 32 + ni * 8 + (lane & 3) * 2;
                float2 o;
                o.x = acc[mi][ni][half * 2 + 0];
                o.y = acc[mi][ni][half * 2 + 1];
                if (SPLITK && kz == 1) {
                    *(float2*)(Cf2 + (long)row * N + col) = o;
                    continue;
                }
                o.x += bias[col + 0];
                o.y += bias[col + 1];
                if (RELU) { o.x = fmaxf(o.x, 0.f); o.y = fmaxf(o.y, 0.f); }
                if (HASRES) {
                    float2 r = *(const float2*)(res + (long)row * N + col);
                    o.x += r.x; o.y += r.y;
                }
                if (MODE == 0) {
                    *(float2*)(Cf + (long)row * N + col) = o;
                } else if (MODE == 1) {
                    *(__half2*)(Ch + (long)row * N + col) = __floats2half2_rn(o.x, o.y);
                } else {
                    int kind = (col >= 2 * DM) ? 2 : ((col >= DM) ? 1 : 0);
                    int cm   = col - kind * DM;
                    // Q scale folds 1/sqrt(64) * log2(e)
                    if (kind == 0) { o.x *= 0.180336880f; o.y *= 0.180336880f; }
                    int hh = cm >> 6, dd = cm & 63;
                    long off = ((long)hh * TSEQ + row) * DKH + dd;
                    __half2 v = __floats2half2_rn(o.x, o.y);
                    if (kind == 0)      *(__half2*)(g_qs + off) = v;
                    else if (kind == 1) *(__half2*)(g_ks + off) = v;
                    else                *(__half2*)(g_vs + off) = v;
                }
            }
        }
    }
}

// ============================================================
// Tensor-core flash attention (unchanged from R11)
// ============================================================
#define SM_Q    (128 * 144)
#define KV_ARR  (64 * 144)
#define KV_STG  (2 * KV_ARR)
#define AT_SMEM (SM_Q + 2 * KV_STG)

__global__ __launch_bounds__(256, 2)
void attn_tc(const __half* __restrict__ Qs, const __half* __restrict__ Ks,
             const __half* __restrict__ Vs, __half* __restrict__ O,
             float* __restrict__ po, float* __restrict__ pm,
             float* __restrict__ pl)
{
    extern __shared__ __align__(16) char sm[];
    const unsigned smu = s2u(sm);
    const int tid  = threadIdx.x;
    const int lane = tid & 31;
    const int wq   = tid >> 5;
    const int xi   = blockIdx.x;
    const int h    = blockIdx.y;
    const long hb  = (long)h * TSEQ * DKH;

    int qb, kb0, kb1, piece;
    bool split;
    if (xi < 32) {
        qb = 31 - (xi >> 1); piece = xi & 1; split = true;
        const int half = qb + 1;
        kb0 = piece * half; kb1 = kb0 + half;
    } else {
        qb = 15 - (xi - 32); piece = 0; split = false;
        kb0 = 0; kb1 = 2 * (qb + 1);
    }

    {
        const char* sq = (const char*)(Qs + hb + (long)qb * 128 * DKH);
        #pragma unroll
        for (int it = 0; it < 4; it++) {
            int idx = tid + it * 256;
            int row = idx >> 3, ch = idx & 7;
            cpa16ca(smu + row * 144 + ch * 16, sq + row * 128 + ch * 16);
        }
    }
    const char* kvsrc[2] = { (const char*)(Ks + hb), (const char*)(Vs + hb) };
    {
        const long kboff = (long)kb0 * 64;
        #pragma unroll
        for (int it = 0; it < 4; it++) {
            int idx = tid + it * 256;
            int arr = idx >> 9, rem = idx & 511;
            int row = rem >> 3, ch = rem & 7;
            cpa16ca(smu + SM_Q + arr * KV_ARR + row * 144 + ch * 16,
                    kvsrc[arr] + (kboff + row) * 128 + ch * 16);
        }
    }
    cpa_commit();
    cpa_wait<0>();
    __syncthreads();

    unsigned qf[4][4];
    #pragma unroll
    for (int kt = 0; kt < 4; kt++) {
        unsigned a = smu + (wq * 16 + (lane & 15)) * 144
                   + ((lane >> 4) * 8 + kt * 16) * 2;
        ldm_x4(qf[kt], a);
    }

    float o_[8][4];
    #pragma unroll
    for (int i = 0; i < 8; i++)
        #pragma unroll
        for (int j = 0; j < 4; j++) o_[i][j] = 0.f;
    float m0 = -1e30f, m1 = -1e30f, l0 = 0.f, l1 = 0.f;

    const int diagKb = (qb * 128 + wq * 16) >> 6;
    const int r0g    = qb * 128 + wq * 16 + (lane >> 2);

    for (int kb = kb0; kb < kb1; kb++) {
        const int s = (kb - kb0) & 1;

        if (kb + 1 < kb1) {
            const long kbn = (long)(kb + 1) * 64;
            #pragma unroll
            for (int it = 0; it < 4; it++) {
                int idx = tid + it * 256;
                int arr = idx >> 9, rem = idx & 511;
                int row = rem >> 3, ch = rem & 7;
                cpa16ca(smu + SM_Q + (s ^ 1) * KV_STG + arr * KV_ARR + row * 144 + ch * 16,
                        kvsrc[arr] + (kbn + row) * 128 + ch * 16);
            }
        }
        cpa_commit();

        float sc[8][4];
        #pragma unroll
        for (int i = 0; i < 8; i++)
            #pragma unroll
            for (int j = 0; j < 4; j++) sc[i][j] = 0.f;

        const unsigned kbase = smu + SM_Q + s * KV_STG;
        #pragma unroll
        for (int kt = 0; kt < 4; kt++) {
            #pragma unroll
            for (int nt = 0; nt < 8; nt += 2) {
                unsigned ka = kbase
                    + ((nt + ((lane >> 4) & 1)) * 8 + (lane & 7)) * 144
                    + (((lane >> 3) & 1) * 8 + kt * 16) * 2;
                unsigned b[4];
                ldm_x4(b, ka);
                mma_f16(sc[nt + 0], qf[kt], b);
                mma_f16(sc[nt + 1], qf[kt], b + 2);
            }
        }

        if (kb >= diagKb) {
            #pragma unroll
            for (int nt = 0; nt < 8; nt++) {
                int keyb = kb * 64 + nt * 8 + (lane & 3) * 2;
                #pragma unroll
                for (int c = 0; c < 4; c++) {
                    int key = keyb + (c & 1);
                    int row = r0g + (c >> 1) * 8;
                    if (key > row) sc[nt][c] = -1e30f;
                }
            }
        }

        float pm0 = -1e30f, pm1 = -1e30f;
        #pragma unroll
        for (int nt = 0; nt < 8; nt++) {
            pm0 = fmaxf(pm0, fmaxf(sc[nt][0], sc[nt][1]));
            pm1 = fmaxf(pm1, fmaxf(sc[nt][2], sc[nt][3]));
        }
        pm0 = fmaxf(pm0, __shfl_xor_sync(0xffffffffu, pm0, 1));
        pm0 = fmaxf(pm0, __shfl_xor_sync(0xffffffffu, pm0, 2));
        pm1 = fmaxf(pm1, __shfl_xor_sync(0xffffffffu, pm1, 1));
        pm1 = fmaxf(pm1, __shfl_xor_sync(0xffffffffu, pm1, 2));

        float mn0 = fmaxf(m0, pm0), mn1 = fmaxf(m1, pm1);
        float a0 = ex2(m0 - mn0), a1 = ex2(m1 - mn1);
        m0 = mn0; m1 = mn1;

        float rs0 = 0.f, rs1 = 0.f;
        #pragma unroll
        for (int nt = 0; nt < 8; nt++) {
            sc[nt][0] = ex2(sc[nt][0] - mn0);
            sc[nt][1] = ex2(sc[nt][1] - mn0);
            sc[nt][2] = ex2(sc[nt][2] - mn1);
            sc[nt][3] = ex2(sc[nt][3] - mn1);
            rs0 += sc[nt][0] + sc[nt][1];
            rs1 += sc[nt][2] + sc[nt][3];
        }
        rs0 += __shfl_xor_sync(0xffffffffu, rs0, 1);
        rs0 += __shfl_xor_sync(0xffffffffu, rs0, 2);
        rs1 += __shfl_xor_sync(0xffffffffu, rs1, 1);
        rs1 += __shfl_xor_sync(0xffffffffu, rs1, 2);
        l0 = l0 * a0 + rs0;
        l1 = l1 * a1 + rs1;

        #pragma unroll
        for (int dt = 0; dt < 8; dt++) {
            o_[dt][0] *= a0; o_[dt][1] *= a0;
            o_[dt][2] *= a1; o_[dt][3] *= a1;
        }

        unsigned pf[4][4];
        #pragma unroll
        for (int kt = 0; kt < 4; kt++) {
            #pragma unroll
            for (int half = 0; half < 2; half++) {
                const float* v0 = sc[kt * 2 + half];
                __half2 p01 = __floats2half2_rn(v0[0], v0[1]);
                __half2 p23 = __floats2half2_rn(v0[2], v0[3]);
                pf[kt][half * 2 + 0] = *(unsigned*)&p01;
                pf[kt][half * 2 + 1] = *(unsigned*)&p23;
            }
        }

        const unsigned vbase = kbase + KV_ARR;
        #pragma unroll
        for (int kt = 0; kt < 4; kt++) {
            #pragma unroll
            for (int nt = 0; nt < 8; nt += 2) {
                unsigned va = vbase + (kt * 16 + (lane & 15)) * 144
                            + (nt + ((lane >> 4) & 1)) * 16;
                unsigned b[4];
                ldm_x4t(b, va);
                mma_f16(o_[nt + 0], pf[kt], b);
                mma_f16(o_[nt + 1], pf[kt], b + 2);
            }
        }

        cpa_wait<0>();
        __syncthreads();
    }

    if (!split) {
        const float i0 = 1.f / l0, i1 = 1.f / l1;
        #pragma unroll
        for (int nt = 0; nt < 8; nt++) {
            int col = h * DKH + nt * 8 + (lane & 3) * 2;
            *(__half2*)(O + (long)r0g * DM + col) =
                __floats2half2_rn(o_[nt][0] * i0, o_[nt][1] * i0);
            *(__half2*)(O + (long)(r0g + 8) * DM + col) =
                __floats2half2_rn(o_[nt][2] * i1, o_[nt][3] * i1);
        }
    } else {
        const int tile = h * 16 + (qb - 16);
        const int lr   = wq * 16 + (lane >> 2);
        float* pob = po + ((long)(piece * NSPLIT_TILES + tile) * 128) * 64;
        #pragma unroll
        for (int nt = 0; nt < 8; nt++) {
            int col = nt * 8 + (lane & 3) * 2;
            *(float2*)(pob + (long)lr * 64 + col)       = make_float2(o_[nt][0], o_[nt][1]);
            *(float2*)(pob + (long)(lr + 8) * 64 + col) = make_float2(o_[nt][2], o_[nt][3]);
        }
        if ((lane & 3) == 0) {
            long mb = (long)(piece * NSPLIT_TILES + tile) * 128;
            pm[mb + lr]     = m0;  pl[mb + lr]     = l0;
            pm[mb + lr + 8] = m1;  pl[mb + lr + 8] = l1;
        }
    }
}

// ============================================================
// Combine split-KV partials -> fp16 O. 4 blocks per tile,
// thread -> (row, 8-col group): 4x parallelism vs R11.
// ============================================================
__global__ __launch_bounds__(256) void attn_combine(
    const float* __restrict__ po, const float* __restrict__ pm,
    const float* __restrict__ pl, __half* __restrict__ O)
{
    const int tile = blockIdx.x >> 2;
    const int t    = (blockIdx.x & 3) * 256 + threadIdx.x;   // 0..1023 in tile
    const int row  = t >> 3;                                 // 0..127
    const int cg   = (t & 7) * 8;                            // col group of 8
    const int h    = tile / 16;
    const int qb   = 16 + (tile % 16);

    const long mb0 = (long)tile * 128 + row;
    const long mb1 = (long)(NSPLIT_TILES + tile) * 128 + row;
    float m0 = pm[mb0], l0 = pl[mb0];
    float m1 = pm[mb1], l1 = pl[mb1];
    float mx = fmaxf(m0, m1);
    float w0 = ex2(m0 - mx), w1 = ex2(m1 - mx);
    float inv = 1.f / (w0 * l0 + w1 * l1);
    w0 *= inv; w1 *= inv;

    const float* a = po + ((long)tile * 128 + row) * 64 + cg;
    const float* b = po + ((long)(NSPLIT_TILES + tile) * 128 + row) * 64 + cg;
    __half* dst = O + (long)(qb * 128 + row) * DM + h * DKH + cg;
    #pragma unroll
    for (int c = 0; c < 8; c += 4) {
        float4 av = *(const float4*)(a + c);
        float4 bv = *(const float4*)(b + c);
        *(__half2*)(dst + c)     = __floats2half2_rn(w0 * av.x + w1 * bv.x,
                                                     w0 * av.y + w1 * bv.y);
        *(__half2*)(dst + c + 2) = __floats2half2_rn(w0 * av.z + w1 * bv.z,
                                                     w0 * av.w + w1 * bv.w);
    }
}

// ============================================================
// LayerNorm (unchanged from R11)
// ============================================================
__global__ __launch_bounds__(256) void ln_kernel(
    const float* __restrict__ X, const float* __restrict__ X2,
    const float* __restrict__ g, const float* __restrict__ b,
    float* __restrict__ Y, __half* __restrict__ Yh)
{
    const int r   = blockIdx.x;
    const int tid = threadIdx.x;
    const float* x  = X  + (long)r * DM;
    const float* x2 = X2 ? (X2 + (long)r * DM) : (const float*)0;

    float v[3];
    float s = 0.f, ss = 0.f;
    #pragma unroll
    for (int i = 0; i < 3; i++) {
        int c = tid + i * 256;
        v[i] = x[c] + (x2 ? x2[c] : 0.f);
        s  += v[i];
        ss += v[i] * v[i];
    }
    #pragma unroll
    for (int off = 16; off > 0; off >>= 1) {
        s  += __shfl_xor_sync(0xffffffffu, s,  off);
        ss += __shfl_xor_sync(0xffffffffu, ss, off);
    }
    __shared__ float rs_[8], rss_[8];
    const int lane = tid & 31, wid = tid >> 5;
    if (lane == 0) { rs_[wid] = s; rss_[wid] = ss; }
    __syncthreads();
    float ts = 0.f, tss = 0.f;
    #pragma unroll
    for (int w = 0; w < 8; w++) { ts += rs_[w]; tss += rss_[w]; }

    const float mean = ts * (1.f / 768.f);
    const float var  = tss * (1.f / 768.f) - mean * mean;
    const float rstd = rsqrtf(var + 1e-5f);

    #pragma unroll
    for (int i = 0; i < 3; i++) {
        int c = tid + i * 256;
        float yv = (v[i] - mean) * rstd * g[c] + b[c];
        Y[(long)r * DM + c] = yv;
        if (Yh) Yh[(long)r * DM + c] = __float2half_rn(yv);
    }
}

// ============================================================
extern "C" void kernel_launch(void* const* d_in, const int* in_sizes, int n_in,
                              void* d_out, int out_size)
{
    const float* x   = (const float*)d_in[0];
    const float* Wq  = (const float*)d_in[1];
    const float* bq  = (const float*)d_in[2];
    const float* Wk  = (const float*)d_in[3];
    const float* bk  = (const float*)d_in[4];
    const float* Wv  = (const float*)d_in[5];
    const float* bv  = (const float*)d_in[6];
    const float* Wo  = (const float*)d_in[7];
    const float* bo  = (const float*)d_in[8];
    const float* W1  = (const float*)d_in[9];
    const float* b1  = (const float*)d_in[10];
    const float* W2  = (const float*)d_in[11];
    const float* b2  = (const float*)d_in[12];
    const float* g1  = (const float*)d_in[13];
    const float* be1 = (const float*)d_in[14];
    const float* g2  = (const float*)d_in[15];
    const float* be2 = (const float*)d_in[16];
    float* out = (float*)d_out;

    float *y1, *y1b, *hbuf, *y2, *y2b, *bqkv, *po, *pmv, *plv;
    cudaGetSymbolAddress((void**)&y1,   g_y1);
    cudaGetSymbolAddress((void**)&y1b,  g_y1b);
    cudaGetSymbolAddress((void**)&hbuf, g_h);
    cudaGetSymbolAddress((void**)&y2,   g_y2);
    cudaGetSymbolAddress((void**)&y2b,  g_y2b);
    cudaGetSymbolAddress((void**)&bqkv, g_bqkv);
    cudaGetSymbolAddress((void**)&po,   g_po);
    cudaGetSymbolAddress((void**)&pmv,  g_pm);
    cudaGetSymbolAddress((void**)&plv,  g_pl);

    __half *x16, *ab, *h16, *f1;
    cudaGetSymbolAddress((void**)&x16, g_x16);
    cudaGetSymbolAddress((void**)&ab,  g_ab);
    cudaGetSymbolAddress((void**)&h16, g_h16);
    cudaGetSymbolAddress((void**)&f1,  g_f1);

    __half *wqkv, *wo, *w1, *w2;
    cudaGetSymbolAddress((void**)&wqkv, g_wqkv);
    cudaGetSymbolAddress((void**)&wo, g_wo);
    cudaGetSymbolAddress((void**)&w1, g_w1);
    cudaGetSymbolAddress((void**)&w2, g_w2);

    __half *qs, *ks, *vs;
    cudaGetSymbolAddress((void**)&qs, g_qs);
    cudaGetSymbolAddress((void**)&ks, g_ks);
    cudaGetSymbolAddress((void**)&vs, g_vs);

    cudaFuncSetAttribute(gemm_h1<2, false, false, false>,
                         cudaFuncAttributeMaxDynamicSharedMemorySize, GSMEM);
    cudaFuncSetAttribute(gemm_h1<0, false, true, true>,
                         cudaFuncAttributeMaxDynamicSharedMemorySize, GSMEM);
    cudaFuncSetAttribute(gemm_h1<1, true, false, false>,
                         cudaFuncAttributeMaxDynamicSharedMemorySize, GSMEM);
    cudaFuncSetAttribute(attn_tc, cudaFuncAttributeMaxDynamicSharedMemorySize, AT_SMEM);

    dim3 blk(256);

    prep_all<<<9993, blk>>>(Wq, Wk, Wv, Wo, W1, W2, wqkv, wo, w1, w2,
                            x, x16, bq, bk, bv, bqkv);

    gemm_h1<2, false, false, false><<<dim3(18, 32), blk, GSMEM>>>(
        x16, wqkv, bqkv, nullptr, nullptr, nullptr, nullptr, DM, 3 * DM);

    attn_tc<<<dim3(48, NH), blk, AT_SMEM>>>(qs, ks, vs, ab, po, pmv, plv);
    attn_combine<<<NSPLIT_TILES * 4, blk>>>(po, pmv, plv, ab);

    gemm_h1<0, false, true, true><<<dim3(6, 32, 2), blk, GSMEM>>>(
        ab, wo, bo, x, y1, y1b, nullptr, DM, DM);

    ln_kernel<<<TSEQ, blk>>>(y1, y1b, g1, be1, hbuf, h16);

    gemm_h1<1, true, false, false><<<dim3(24, 32), blk, GSMEM>>>(
        h16, w1, b1, nullptr, nullptr, nullptr, f1, DM, DFF);
    gemm_h1<0, false, true, true><<<dim3(6, 32, 2), blk, GSMEM>>>(
        f1, w2, b2, hbuf, y2, y2b, nullptr, DFF, DM);

    ln_kernel<<<TSEQ, blk>>>(y2, y2b, g2, be2, out, nullptr);
}

// round 13
// speedup vs baseline: 8.1920x; 1.0131x over previous
#include <cuda_runtime.h>
#include <cuda_fp16.h>

#define TSEQ 4096
#define DM   768
#define NH   12
#define DKH  64
#define DFF  3072
#define NSPLIT_TILES (NH * 16)

// ---- fp32 scratch ----
__device__ float g_y1  [TSEQ * DM];
__device__ float g_y1b [TSEQ * DM];
__device__ float g_y2  [TSEQ * DM];
__device__ float g_y2b [TSEQ * DM];
__device__ float g_bqkv[3 * DM];

// ---- attention split-KV partials ----
__device__ float g_po[2 * NSPLIT_TILES * 128 * 64];
__device__ float g_pm[2 * NSPLIT_TILES * 128];
__device__ float g_pl[2 * NSPLIT_TILES * 128];

// ---- fp16 activations ----
__device__ __half g_x16[TSEQ * DM];
__device__ __half g_ab [TSEQ * DM];
__device__ __half g_h16[TSEQ * DM];
__device__ __half g_f1 [TSEQ * DFF];

// ---- fp16 transposed weights [N, K] ----
__device__ __half g_wqkv[3 * DM * DM];
__device__ __half g_wo  [DM * DM];
__device__ __half g_w1  [DM * DFF];
__device__ __half g_w2  [DM * DFF];

// ---- fp16 QKV, head-major [NH][TSEQ][64] ----
__device__ __half g_qs[NH * TSEQ * DKH];
__device__ __half g_ks[NH * TSEQ * DKH];
__device__ __half g_vs[NH * TSEQ * DKH];

// ============================================================
// helpers
// ============================================================
__device__ __forceinline__ unsigned s2u(const void* p) {
    unsigned a;
    asm("{ .reg .u64 t; cvta.to.shared.u64 t, %1; cvt.u32.u64 %0, t; }"
        : "=r"(a) : "l"(p));
    return a;
}
__device__ __forceinline__ float ex2(float x) {
    float r;
    asm("ex2.approx.f32 %0, %1;" : "=f"(r) : "f"(x));
    return r;
}
__device__ __forceinline__ void ldm_x4(unsigned* r, unsigned addr) {
    asm volatile("ldmatrix.sync.aligned.m8n8.x4.shared.b16 {%0,%1,%2,%3}, [%4];"
                 : "=r"(r[0]), "=r"(r[1]), "=r"(r[2]), "=r"(r[3]) : "r"(addr));
}
__device__ __forceinline__ void ldm_x4t(unsigned* r, unsigned addr) {
    asm volatile("ldmatrix.sync.aligned.m8n8.x4.trans.shared.b16 {%0,%1,%2,%3}, [%4];"
                 : "=r"(r[0]), "=r"(r[1]), "=r"(r[2]), "=r"(r[3]) : "r"(addr));
}
__device__ __forceinline__ void mma_f16(float* c, const unsigned* a, const unsigned* b) {
    asm volatile("mma.sync.aligned.m16n8k16.row.col.f32.f16.f16.f32 "
                 "{%0,%1,%2,%3}, {%4,%5,%6,%7}, {%8,%9}, {%0,%1,%2,%3};"
                 : "+f"(c[0]), "+f"(c[1]), "+f"(c[2]), "+f"(c[3])
                 : "r"(a[0]), "r"(a[1]), "r"(a[2]), "r"(a[3]), "r"(b[0]), "r"(b[1]));
}
__device__ __forceinline__ void cpa16(unsigned dst, const void* src) {
    asm volatile("cp.async.cg.shared.global [%0], [%1], 16;" :: "r"(dst), "l"(src));
}
__device__ __forceinline__ void cpa16ca(unsigned dst, const void* src) {
    asm volatile("cp.async.ca.shared.global [%0], [%1], 16;" :: "r"(dst), "l"(src));
}
__device__ __forceinline__ void cpa_commit() {
    asm volatile("cp.async.commit_group;" ::: "memory");
}
template<int N> __device__ __forceinline__ void cpa_wait() {
    asm volatile("cp.async.wait_group %0;" :: "n"(N) : "memory");
}

// ============================================================
// ONE prep kernel (unchanged)
// ============================================================
__device__ __forceinline__ void wconv_body(
    const float* __restrict__ W, __half* __restrict__ T,
    int K, int N, int n0, int k0, float t[32][33])
{
    const int tx = threadIdx.x & 31, ty = threadIdx.x >> 5;
    #pragma unroll
    for (int i = 0; i < 4; i++)
        t[ty + i * 8][tx] = W[(long)(k0 + ty + i * 8) * N + n0 + tx];
    __syncthreads();
    #pragma unroll
    for (int i = 0; i < 4; i++) {
        int n = n0 + ty + i * 8;
        T[(long)n * K + k0 + tx] = __float2half_rn(t[tx][ty + i * 8]);
    }
}
__global__ __launch_bounds__(256) void prep_all(
    const float* __restrict__ Wq, const float* __restrict__ Wk,
    const float* __restrict__ Wv, const float* __restrict__ Wo,
    const float* __restrict__ W1, const float* __restrict__ W2,
    __half* __restrict__ qkv, __half* __restrict__ wo,
    __half* __restrict__ w1, __half* __restrict__ w2,
    const float* __restrict__ X, __half* __restrict__ H,
    const float* __restrict__ bq, const float* __restrict__ bk,
    const float* __restrict__ bv, float* __restrict__ bdst)
{
    __shared__ float t[32][33];
    int bid = blockIdx.x;
    if (bid < 2304) {
        int z = bid / 576, r = bid % 576;
        const float* W = (z == 0) ? Wq : (z == 1) ? Wk : (z == 2) ? Wv : Wo;
        __half* T = (z < 3) ? (qkv + (long)z * DM * DM) : wo;
        wconv_body(W, T, DM, DM, (r % 24) * 32, (r / 24) * 32, t);
    } else if (bid < 4608) {
        int r = bid - 2304;
        wconv_body(W1, w1, DM, DFF, (r % 96) * 32, (r / 96) * 32, t);
    } else if (bid < 6912) {
        int r = bid - 4608;
        wconv_body(W2, w2, DFF, DM, (r % 24) * 32, (r / 24) * 32, t);
    } else if (bid < 9984) {
        long idx = ((long)(bid - 6912) * 256 + threadIdx.x) * 4;
        float4 v = *(const float4*)(X + idx);
        *(__half2*)(H + idx)     = __floats2half2_rn(v.x, v.y);
        *(__half2*)(H + idx + 2) = __floats2half2_rn(v.z, v.w);
    } else {
        int i = (bid - 9984) * 256 + threadIdx.x;
        if (i < 3 * DM) {
            float v = (i < DM) ? bq[i] : (i < 2 * DM) ? bk[i - DM] : bv[i - 2 * DM];
            bdst[i] = v;
        }
    }
}

// ============================================================
// fp16 GEMM: BKC=64, 3-stage pipeline. RESH: fp16 residual.
// ============================================================
#define BKC   64
#define ASTR  72
#define SEG   18432
#define STGB  (2 * SEG)
#define GSMEM (3 * STGB)

template<int MODE, bool RELU, bool HASRES, bool RESH, bool SPLITK>
__global__ __launch_bounds__(256, 2)
void gemm_h1(const __half* __restrict__ A, const __half* __restrict__ B,
             const float* __restrict__ bias, const float* __restrict__ res,
             const __half* __restrict__ resh,
             float* __restrict__ Cf, float* __restrict__ Cf2,
             __half* __restrict__ Ch, int K, int N)
{
    extern __shared__ __align__(128) char smem[];
    const int tid   = threadIdx.x;
    const int wid   = tid >> 5;
    const int lane  = tid & 31;
    const int warpM = wid & 1;
    const int warpN = wid >> 1;
    const int brow  = blockIdx.y * 128;
    const int bcol  = blockIdx.x * 128;
    const int kz    = SPLITK ? (int)blockIdx.z : 0;
    const int Keff  = SPLITK ? (K >> 1) : K;
    const int koff  = kz * Keff;
    const unsigned smu = s2u(smem);

    const char* src[2] = { (const char*)A, (const char*)B };

    float acc[4][4][4];
    #pragma unroll
    for (int mi = 0; mi < 4; mi++)
        #pragma unroll
        for (int ni = 0; ni < 4; ni++)
            #pragma unroll
            for (int r = 0; r < 4; r++) acc[mi][ni][r] = 0.f;

    const int nch = Keff / BKC;

    auto load_stage = [&](int s, int kc) {
        #pragma unroll
        for (int it = 0; it < 8; it++) {
            int idx = tid + it * 256;
            int arr = idx >> 10, rem = idx & 1023;
            int row = rem >> 3, ch = rem & 7;
            int base_row = (arr == 0) ? (brow + row) : (bcol + row);
            cpa16(smu + s * STGB + arr * SEG + row * 144 + ch * 16,
                  src[arr] + ((long)base_row * K + koff + kc) * 2 + ch * 16);
        }
    };

    load_stage(0, 0);
    cpa_commit();
    if (nch > 1) { load_stage(1, BKC); cpa_commit(); }

    int s = 0;
    for (int c = 0; c < nch; ++c) {
        cpa_wait<1>();
        __syncthreads();
        if (c + 2 < nch) {
            int s2 = s + 2; if (s2 >= 3) s2 -= 3;
            load_stage(s2, (c + 2) * BKC);
            cpa_commit();
        }

        const unsigned uA = smu + s * STGB;
        const unsigned uB = uA + SEG;

        #pragma unroll
        for (int kk = 0; kk < 4; kk++) {
            unsigned a[4][4];
            #pragma unroll
            for (int mi = 0; mi < 4; mi++) {
                unsigned rowoff =
                    (unsigned)(((warpM * 64 + mi * 16 + (lane & 15)) * ASTR
                                + (lane >> 4) * 8 + kk * 16) * 2);
                ldm_x4(a[mi], uA + rowoff);
            }
            #pragma unroll
            for (int ni = 0; ni < 4; ni += 2) {
                unsigned boff =
                    (unsigned)(((warpN * 32 + (ni + ((lane >> 4) & 1)) * 8 + (lane & 7)) * ASTR
                                + ((lane >> 3) & 1) * 8 + kk * 16) * 2);
                unsigned b[4];
                ldm_x4(b, uB + boff);
                #pragma unroll
                for (int mi = 0; mi < 4; mi++) {
                    mma_f16(acc[mi][ni + 0], a[mi], b);
                    mma_f16(acc[mi][ni + 1], a[mi], b + 2);
                }
            }
        }
        if (++s >= 3) s -= 3;
    }

    #pragma unroll
    for (int mi = 0; mi < 4; mi++) {
        #pragma unroll
        for (int half = 0; half < 2; half++) {
            const int row = brow + warpM * 64 + mi * 16 + (lane >> 2) + half * 8;
            #pragma unroll
            for (int ni = 0; ni < 4; ni++) {
                const int col = bcol + warpN * 32 + ni * 8 + (lane & 3) * 2;
                float2 o;
                o.x = acc[mi][ni][half * 2 + 0];
                o.y = acc[mi][ni][half * 2 + 1];
                if (SPLITK && kz == 1) {
                    *(float2*)(Cf2 + (long)row * N + col) = o;
                    continue;
                }
                o.x += bias[col + 0];
                o.y += bias[col + 1];
                if (RELU) { o.x = fmaxf(o.x, 0.f); o.y = fmaxf(o.y, 0.f); }
                if (HASRES) {
                    if (RESH) {
                        __half2 r2 = *(const __half2*)(resh + (long)row * N + col);
                        float2 rf = __half22float2(r2);
                        o.x += rf.x; o.y += rf.y;
                    } else {
                        float2 r = *(const float2*)(res + (long)row * N + col);
                        o.x += r.x; o.y += r.y;
                    }
                }
                if (MODE == 0) {
                    *(float2*)(Cf + (long)row * N + col) = o;
                } else if (MODE == 1) {
                    *(__half2*)(Ch + (long)row * N + col) = __floats2half2_rn(o.x, o.y);
                } else {
                    int kind = (col >= 2 * DM) ? 2 : ((col >= DM) ? 1 : 0);
                    int cm   = col - kind * DM;
                    if (kind == 0) { o.x *= 0.180336880f; o.y *= 0.180336880f; }
                    int hh = cm >> 6, dd = cm & 63;
                    long off = ((long)hh * TSEQ + row) * DKH + dd;
                    __half2 v = __floats2half2_rn(o.x, o.y);
                    if (kind == 0)      *(__half2*)(g_qs + off) = v;
                    else if (kind == 1) *(__half2*)(g_ks + off) = v;
                    else                *(__half2*)(g_vs + off) = v;
                }
            }
        }
    }
}

// ============================================================
// Tensor-core flash attention (unchanged from R12)
// ============================================================
#define SM_Q    (128 * 144)
#define KV_ARR  (64 * 144)
#define KV_STG  (2 * KV_ARR)
#define AT_SMEM (SM_Q + 2 * KV_STG)

__global__ __launch_bounds__(256, 2)
void attn_tc(const __half* __restrict__ Qs, const __half* __restrict__ Ks,
             const __half* __restrict__ Vs, __half* __restrict__ O,
             float* __restrict__ po, float* __restrict__ pm,
             float* __restrict__ pl)
{
    extern __shared__ __align__(16) char sm[];
    const unsigned smu = s2u(sm);
    const int tid  = threadIdx.x;
    const int lane = tid & 31;
    const int wq   = tid >> 5;
    const int xi   = blockIdx.x;
    const int h    = blockIdx.y;
    const long hb  = (long)h * TSEQ * DKH;

    int qb, kb0, kb1, piece;
    bool split;
    if (xi < 32) {
        qb = 31 - (xi >> 1); piece = xi & 1; split = true;
        const int half = qb + 1;
        kb0 = piece * half; kb1 = kb0 + half;
    } else {
        qb = 15 - (xi - 32); piece = 0; split = false;
        kb0 = 0; kb1 = 2 * (qb + 1);
    }

    {
        const char* sq = (const char*)(Qs + hb + (long)qb * 128 * DKH);
        #pragma unroll
        for (int it = 0; it < 4; it++) {
            int idx = tid + it * 256;
            int row = idx >> 3, ch = idx & 7;
            cpa16ca(smu + row * 144 + ch * 16, sq + row * 128 + ch * 16);
        }
    }
    const char* kvsrc[2] = { (const char*)(Ks + hb), (const char*)(Vs + hb) };
    {
        const long kboff = (long)kb0 * 64;
        #pragma unroll
        for (int it = 0; it < 4; it++) {
            int idx = tid + it * 256;
            int arr = idx >> 9, rem = idx & 511;
            int row = rem >> 3, ch = rem & 7;
            cpa16ca(smu + SM_Q + arr * KV_ARR + row * 144 + ch * 16,
                    kvsrc[arr] + (kboff + row) * 128 + ch * 16);
        }
    }
    cpa_commit();
    cpa_wait<0>();
    __syncthreads();

    unsigned qf[4][4];
    #pragma unroll
    for (int kt = 0; kt < 4; kt++) {
        unsigned a = smu + (wq * 16 + (lane & 15)) * 144
                   + ((lane >> 4) * 8 + kt * 16) * 2;
        ldm_x4(qf[kt], a);
    }

    float o_[8][4];
    #pragma unroll
    for (int i = 0; i < 8; i++)
        #pragma unroll
        for (int j = 0; j < 4; j++) o_[i][j] = 0.f;
    float m0 = -1e30f, m1 = -1e30f, l0 = 0.f, l1 = 0.f;

    const int diagKb = (qb * 128 + wq * 16) >> 6;
    const int r0g    = qb * 128 + wq * 16 + (lane >> 2);

    for (int kb = kb0; kb < kb1; kb++) {
        const int s = (kb - kb0) & 1;

        if (kb + 1 < kb1) {
            const long kbn = (long)(kb + 1) * 64;
            #pragma unroll
            for (int it = 0; it < 4; it++) {
                int idx = tid + it * 256;
                int arr = idx >> 9, rem = idx & 511;
                int row = rem >> 3, ch = rem & 7;
                cpa16ca(smu + SM_Q + (s ^ 1) * KV_STG + arr * KV_ARR + row * 144 + ch * 16,
                        kvsrc[arr] + (kbn + row) * 128 + ch * 16);
            }
        }
        cpa_commit();

        float sc[8][4];
        #pragma unroll
        for (int i = 0; i < 8; i++)
            #pragma unroll
            for (int j = 0; j < 4; j++) sc[i][j] = 0.f;

        const unsigned kbase = smu + SM_Q + s * KV_STG;
        #pragma unroll
        for (int kt = 0; kt < 4; kt++) {
            #pragma unroll
            for (int nt = 0; nt < 8; nt += 2) {
                unsigned ka = kbase
                    + ((nt + ((lane >> 4) & 1)) * 8 + (lane & 7)) * 144
                    + (((lane >> 3) & 1) * 8 + kt * 16) * 2;
                unsigned b[4];
                ldm_x4(b, ka);
                mma_f16(sc[nt + 0], qf[kt], b);
                mma_f16(sc[nt + 1], qf[kt], b + 2);
            }
        }

        if (kb >= diagKb) {
            #pragma unroll
            for (int nt = 0; nt < 8; nt++) {
                int keyb = kb * 64 + nt * 8 + (lane & 3) * 2;
                #pragma unroll
                for (int c = 0; c < 4; c++) {
                    int key = keyb + (c & 1);
                    int row = r0g + (c >> 1) * 8;
                    if (key > row) sc[nt][c] = -1e30f;
                }
            }
        }

        float pm0 = -1e30f, pm1 = -1e30f;
        #pragma unroll
        for (int nt = 0; nt < 8; nt++) {
            pm0 = fmaxf(pm0, fmaxf(sc[nt][0], sc[nt][1]));
            pm1 = fmaxf(pm1, fmaxf(sc[nt][2], sc[nt][3]));
        }
        pm0 = fmaxf(pm0, __shfl_xor_sync(0xffffffffu, pm0, 1));
        pm0 = fmaxf(pm0, __shfl_xor_sync(0xffffffffu, pm0, 2));
        pm1 = fmaxf(pm1, __shfl_xor_sync(0xffffffffu, pm1, 1));
        pm1 = fmaxf(pm1, __shfl_xor_sync(0xffffffffu, pm1, 2));

        float mn0 = fmaxf(m0, pm0), mn1 = fmaxf(m1, pm1);
        float a0 = ex2(m0 - mn0), a1 = ex2(m1 - mn1);
        m0 = mn0; m1 = mn1;

        float rs0 = 0.f, rs1 = 0.f;
        #pragma unroll
        for (int nt = 0; nt < 8; nt++) {
            sc[nt][0] = ex2(sc[nt][0] - mn0);
            sc[nt][1] = ex2(sc[nt][1] - mn0);
            sc[nt][2] = ex2(sc[nt][2] - mn1);
            sc[nt][3] = ex2(sc[nt][3] - mn1);
            rs0 += sc[nt][0] + sc[nt][1];
            rs1 += sc[nt][2] + sc[nt][3];
        }
        rs0 += __shfl_xor_sync(0xffffffffu, rs0, 1);
        rs0 += __shfl_xor_sync(0xffffffffu, rs0, 2);
        rs1 += __shfl_xor_sync(0xffffffffu, rs1, 1);
        rs1 += __shfl_xor_sync(0xffffffffu, rs1, 2);
        l0 = l0 * a0 + rs0;
        l1 = l1 * a1 + rs1;

        #pragma unroll
        for (int dt = 0; dt < 8; dt++) {
            o_[dt][0] *= a0; o_[dt][1] *= a0;
            o_[dt][2] *= a1; o_[dt][3] *= a1;
        }

        unsigned pf[4][4];
        #pragma unroll
        for (int kt = 0; kt < 4; kt++) {
            #pragma unroll
            for (int half = 0; half < 2; half++) {
                const float* v0 = sc[kt * 2 + half];
                __half2 p01 = __floats2half2_rn(v0[0], v0[1]);
                __half2 p23 = __floats2half2_rn(v0[2], v0[3]);
                pf[kt][half * 2 + 0] = *(unsigned*)&p01;
                pf[kt][half * 2 + 1] = *(unsigned*)&p23;
            }
        }

        const unsigned vbase = kbase + KV_ARR;
        #pragma unroll
        for (int kt = 0; kt < 4; kt++) {
            #pragma unroll
            for (int nt = 0; nt < 8; nt += 2) {
                unsigned va = vbase + (kt * 16 + (lane & 15)) * 144
                            + (nt + ((lane >> 4) & 1)) * 16;
                unsigned b[4];
                ldm_x4t(b, va);
                mma_f16(o_[nt + 0], pf[kt], b);
                mma_f16(o_[nt + 1], pf[kt], b + 2);
            }
        }

        cpa_wait<0>();
        __syncthreads();
    }

    if (!split) {
        const float i0 = 1.f / l0, i1 = 1.f / l1;
        #pragma unroll
        for (int nt = 0; nt < 8; nt++) {
            int col = h * DKH + nt * 8 + (lane & 3) * 2;
            *(__half2*)(O + (long)r0g * DM + col) =
                __floats2half2_rn(o_[nt][0] * i0, o_[nt][1] * i0);
            *(__half2*)(O + (long)(r0g + 8) * DM + col) =
                __floats2half2_rn(o_[nt][2] * i1, o_[nt][3] * i1);
        }
    } else {
        const int tile = h * 16 + (qb - 16);
        const int lr   = wq * 16 + (lane >> 2);
        float* pob = po + ((long)(piece * NSPLIT_TILES + tile) * 128) * 64;
        #pragma unroll
        for (int nt = 0; nt < 8; nt++) {
            int col = nt * 8 + (lane & 3) * 2;
            *(float2*)(pob + (long)lr * 64 + col)       = make_float2(o_[nt][0], o_[nt][1]);
            *(float2*)(pob + (long)(lr + 8) * 64 + col) = make_float2(o_[nt][2], o_[nt][3]);
        }
        if ((lane & 3) == 0) {
            long mb = (long)(piece * NSPLIT_TILES + tile) * 128;
            pm[mb + lr]     = m0;  pl[mb + lr]     = l0;
            pm[mb + lr + 8] = m1;  pl[mb + lr + 8] = l1;
        }
    }
}

// ============================================================
// Combine split-KV partials (unchanged from R12)
// ============================================================
__global__ __launch_bounds__(256) void attn_combine(
    const float* __restrict__ po, const float* __restrict__ pm,
    const float* __restrict__ pl, __half* __restrict__ O)
{
    const int tile = blockIdx.x >> 2;
    const int t    = (blockIdx.x & 3) * 256 + threadIdx.x;
    const int row  = t >> 3;
    const int cg   = (t & 7) * 8;
    const int h    = tile / 16;
    const int qb   = 16 + (tile % 16);

    const long mb0 = (long)tile * 128 + row;
    const long mb1 = (long)(NSPLIT_TILES + tile) * 128 + row;
    float m0 = pm[mb0], l0 = pl[mb0];
    float m1 = pm[mb1], l1 = pl[mb1];
    float mx = fmaxf(m0, m1);
    float w0 = ex2(m0 - mx), w1 = ex2(m1 - mx);
    float inv = 1.f / (w0 * l0 + w1 * l1);
    w0 *= inv; w1 *= inv;

    const float* a = po + ((long)tile * 128 + row) * 64 + cg;
    const float* b = po + ((long)(NSPLIT_TILES + tile) * 128 + row) * 64 + cg;
    __half* dst = O + (long)(qb * 128 + row) * DM + h * DKH + cg;
    #pragma unroll
    for (int c = 0; c < 8; c += 4) {
        float4 av = *(const float4*)(a + c);
        float4 bv = *(const float4*)(b + c);
        *(__half2*)(dst + c)     = __floats2half2_rn(w0 * av.x + w1 * bv.x,
                                                     w0 * av.y + w1 * bv.y);
        *(__half2*)(dst + c + 2) = __floats2half2_rn(w0 * av.z + w1 * bv.z,
                                                     w0 * av.w + w1 * bv.w);
    }
}

// ============================================================
// LayerNorm: warp-per-row, float4 vectorized, 8 rows/block.
// WF32: write fp32 Y. WF16: write fp16 Yh.
// ============================================================
template<bool WF32, bool WF16>
__global__ __launch_bounds__(256) void ln_kernel(
    const float* __restrict__ X, const float* __restrict__ X2,
    const float* __restrict__ g, const float* __restrict__ b,
    float* __restrict__ Y, __half* __restrict__ Yh)
{
    const int lane = threadIdx.x & 31;
    const int r    = blockIdx.x * 8 + (threadIdx.x >> 5);
    const float* x  = X  + (long)r * DM;
    const float* x2 = X2 + (long)r * DM;

    float4 v[6];
    float s = 0.f, ss = 0.f;
    #pragma unroll
    for (int j = 0; j < 6; j++) {
        int c = (lane + 32 * j) * 4;
        v[j] = *(const float4*)(x + c);
        float4 w = *(const float4*)(x2 + c);
        v[j].x += w.x; v[j].y += w.y; v[j].z += w.z; v[j].w += w.w;
        s  += v[j].x + v[j].y + v[j].z + v[j].w;
        ss += v[j].x * v[j].x + v[j].y * v[j].y + v[j].z * v[j].z + v[j].w * v[j].w;
    }
    #pragma unroll
    for (int off = 16; off > 0; off >>= 1) {
        s  += __shfl_xor_sync(0xffffffffu, s,  off);
        ss += __shfl_xor_sync(0xffffffffu, ss, off);
    }
    const float mean = s * (1.f / 768.f);
    const float var  = ss * (1.f / 768.f) - mean * mean;
    const float rstd = rsqrtf(var + 1e-5f);

    #pragma unroll
    for (int j = 0; j < 6; j++) {
        int c = (lane + 32 * j) * 4;
        float4 gv = *(const float4*)(g + c);
        float4 bv = *(const float4*)(b + c);
        float4 y;
        y.x = (v[j].x - mean) * rstd * gv.x + bv.x;
        y.y = (v[j].y - mean) * rstd * gv.y + bv.y;
        y.z = (v[j].z - mean) * rstd * gv.z + bv.z;
        y.w = (v[j].w - mean) * rstd * gv.w + bv.w;
        if (WF32) *(float4*)(Y + (long)r * DM + c) = y;
        if (WF16) {
            __half2 h0 = __floats2half2_rn(y.x, y.y);
            __half2 h1 = __floats2half2_rn(y.z, y.w);
            uint2 u = { *(unsigned*)&h0, *(unsigned*)&h1 };
            *(uint2*)(Yh + (long)r * DM + c) = u;
        }
    }
}

// ============================================================
extern "C" void kernel_launch(void* const* d_in, const int* in_sizes, int n_in,
                              void* d_out, int out_size)
{
    const float* x   = (const float*)d_in[0];
    const float* Wq  = (const float*)d_in[1];
    const float* bq  = (const float*)d_in[2];
    const float* Wk  = (const float*)d_in[3];
    const float* bk  = (const float*)d_in[4];
    const float* Wv  = (const float*)d_in[5];
    const float* bv  = (const float*)d_in[6];
    const float* Wo  = (const float*)d_in[7];
    const float* bo  = (const float*)d_in[8];
    const float* W1  = (const float*)d_in[9];
    const float* b1  = (const float*)d_in[10];
    const float* W2  = (const float*)d_in[11];
    const float* b2  = (const float*)d_in[12];
    const float* g1  = (const float*)d_in[13];
    const float* be1 = (const float*)d_in[14];
    const float* g2  = (const float*)d_in[15];
    const float* be2 = (const float*)d_in[16];
    float* out = (float*)d_out;

    float *y1, *y1b, *y2, *y2b, *bqkv, *po, *pmv, *plv;
    cudaGetSymbolAddress((void**)&y1,   g_y1);
    cudaGetSymbolAddress((void**)&y1b,  g_y1b);
    cudaGetSymbolAddress((void**)&y2,   g_y2);
    cudaGetSymbolAddress((void**)&y2b,  g_y2b);
    cudaGetSymbolAddress((void**)&bqkv, g_bqkv);
    cudaGetSymbolAddress((void**)&po,   g_po);
    cudaGetSymbolAddress((void**)&pmv,  g_pm);
    cudaGetSymbolAddress((void**)&plv,  g_pl);

    __half *x16, *ab, *h16, *f1;
    cudaGetSymbolAddress((void**)&x16, g_x16);
    cudaGetSymbolAddress((void**)&ab,  g_ab);
    cudaGetSymbolAddress((void**)&h16, g_h16);
    cudaGetSymbolAddress((void**)&f1,  g_f1);

    __half *wqkv, *wo, *w1, *w2;
    cudaGetSymbolAddress((void**)&wqkv, g_wqkv);
    cudaGetSymbolAddress((void**)&wo, g_wo);
    cudaGetSymbolAddress((void**)&w1, g_w1);
    cudaGetSymbolAddress((void**)&w2, g_w2);

    __half *qs, *ks, *vs;
    cudaGetSymbolAddress((void**)&qs, g_qs);
    cudaGetSymbolAddress((void**)&ks, g_ks);
    cudaGetSymbolAddress((void**)&vs, g_vs);

    cudaFuncSetAttribute(gemm_h1<2, false, false, false, false>,
                         cudaFuncAttributeMaxDynamicSharedMemorySize, GSMEM);
    cudaFuncSetAttribute(gemm_h1<0, false, true, false, true>,
                         cudaFuncAttributeMaxDynamicSharedMemorySize, GSMEM);
    cudaFuncSetAttribute(gemm_h1<0, false, true, true, true>,
                         cudaFuncAttributeMaxDynamicSharedMemorySize, GSMEM);
    cudaFuncSetAttribute(gemm_h1<1, true, false, false, false>,
                         cudaFuncAttributeMaxDynamicSharedMemorySize, GSMEM);
    cudaFuncSetAttribute(attn_tc, cudaFuncAttributeMaxDynamicSharedMemorySize, AT_SMEM);

    dim3 blk(256);

    prep_all<<<9993, blk>>>(Wq, Wk, Wv, Wo, W1, W2, wqkv, wo, w1, w2,
                            x, x16, bq, bk, bv, bqkv);

    gemm_h1<2, false, false, false, false><<<dim3(18, 32), blk, GSMEM>>>(
        x16, wqkv, bqkv, nullptr, nullptr, nullptr, nullptr, nullptr, DM, 3 * DM);

    attn_tc<<<dim3(48, NH), blk, AT_SMEM>>>(qs, ks, vs, ab, po, pmv, plv);
    attn_combine<<<NSPLIT_TILES * 4, blk>>>(po, pmv, plv, ab);

    // output projection + residual(x fp32), split-K x2
    gemm_h1<0, false, true, false, true><<<dim3(6, 32, 2), blk, GSMEM>>>(
        ab, wo, bo, x, nullptr, y1, y1b, nullptr, DM, DM);

    // LN1: fp16 output only
    ln_kernel<false, true><<<TSEQ / 8, blk>>>(y1, y1b, g1, be1, nullptr, h16);

    // FFN
    gemm_h1<1, true, false, false, false><<<dim3(24, 32), blk, GSMEM>>>(
        h16, w1, b1, nullptr, nullptr, nullptr, nullptr, f1, DM, DFF);
    // FF2 + residual(h16 fp16), split-K x2
    gemm_h1<0, false, true, true, true><<<dim3(6, 32, 2), blk, GSMEM>>>(
        f1, w2, b2, nullptr, h16, y2, y2b, nullptr, DFF, DM);

    // LN2: fp32 output only
    ln_kernel<true, false><<<TSEQ / 8, blk>>>(y2, y2b, g2, be2, out, nullptr);
}